// round 5
// baseline (speedup 1.0000x reference)
#include <cuda_runtime.h>
#include <cuda_bf16.h>
#include <math.h>
#include <stdint.h>

#define B_ 8
#define T_ 512
#define J_ 26
#define D_ 256
#define H_ 8
#define DH_ 32
#define HID_ 1024
#define NTOK 106496            // B*T*J  (= 832 * 128 exactly)
#define EPSF 1e-6f

// ================= PTX helpers (base ISA only: sm_80+ features) =================
__device__ __forceinline__ uint32_t smem_u32(const void* p) {
    uint32_t a;
    asm("{ .reg .u64 t; cvta.to.shared.u64 t, %1; cvt.u32.u64 %0, t; }" : "=r"(a) : "l"(p));
    return a;
}
#define CP_ASYNC16(dst, src) \
    asm volatile("cp.async.cg.shared.global [%0], [%1], 16;" :: "r"(dst), "l"(src) : "memory")
#define CP_COMMIT() asm volatile("cp.async.commit_group;" ::: "memory")
#define CP_WAIT(n)  asm volatile("cp.async.wait_group %0;" :: "n"(n) : "memory")

#define LDSM4(r0, r1, r2, r3, addr) \
    asm volatile("ldmatrix.sync.aligned.m8n8.x4.shared.b16 {%0,%1,%2,%3}, [%4];" \
        : "=r"(r0), "=r"(r1), "=r"(r2), "=r"(r3) : "r"(addr))

__device__ __forceinline__ void mma16816(float* c, const uint32_t* a, const uint32_t* b) {
    asm volatile(
        "mma.sync.aligned.m16n8k16.row.col.f32.bf16.bf16.f32 "
        "{%0,%1,%2,%3}, {%4,%5,%6,%7}, {%8,%9}, {%0,%1,%2,%3};"
        : "+f"(c[0]), "+f"(c[1]), "+f"(c[2]), "+f"(c[3])
        : "r"(a[0]), "r"(a[1]), "r"(a[2]), "r"(a[3]), "r"(b[0]), "r"(b[1]));
}

// ================= scratch (static device .bss) =================
__device__ __nv_bfloat16 g_th [(size_t)NTOK * D_];    // t / y / u2  hi
__device__ __nv_bfloat16 g_tl [(size_t)NTOK * D_];    // t / y / u2  lo
__device__ float         g_q  [(size_t)NTOK * D_];    // pq / o / f
__device__ float         g_k  [(size_t)NTOK * D_];    // pk
__device__ float         g_v  [(size_t)NTOK * D_];    // v
__device__ __nv_bfloat16 g_hh [(size_t)NTOK * HID_];  // hid hi
__device__ __nv_bfloat16 g_hl [(size_t)NTOK * HID_];  // hid lo
__device__ float g_kv [(size_t)B_ * J_ * H_ * DH_ * DH_];
__device__ float g_ks [(size_t)B_ * J_ * H_ * DH_];
// transposed bf16 hi/lo weights: Bt[n,k]
__device__ __nv_bfloat16 g_wqh[D_ * D_],   g_wql[D_ * D_];
__device__ __nv_bfloat16 g_wkh[D_ * D_],   g_wkl[D_ * D_];
__device__ __nv_bfloat16 g_wvh[D_ * D_],   g_wvl[D_ * D_];
__device__ __nv_bfloat16 g_woh[D_ * D_],   g_wol[D_ * D_];
__device__ __nv_bfloat16 g_w1h[D_ * HID_], g_w1l[D_ * HID_];
__device__ __nv_bfloat16 g_w2h[HID_ * D_], g_w2l[HID_ * D_];

// ================= small helpers =================
__device__ __forceinline__ float block_reduce_sum(float v, float* sbuf) {
    int lane = threadIdx.x & 31, w = threadIdx.x >> 5;
    #pragma unroll
    for (int o = 16; o; o >>= 1) v += __shfl_down_sync(0xffffffffu, v, o);
    if (lane == 0) sbuf[w] = v;
    __syncthreads();
    float r = (threadIdx.x < 8) ? sbuf[threadIdx.x] : 0.f;
    if (w == 0) {
        r += __shfl_down_sync(0xffffffffu, r, 4);
        r += __shfl_down_sync(0xffffffffu, r, 2);
        r += __shfl_down_sync(0xffffffffu, r, 1);
        if (lane == 0) sbuf[0] = r;
    }
    __syncthreads();
    float res = sbuf[0];
    __syncthreads();
    return res;
}
__device__ __forceinline__ void split_store(__nv_bfloat16* hi, __nv_bfloat16* lo,
                                            size_t idx, float v) {
    __nv_bfloat16 h = __float2bfloat16(v);
    hi[idx] = h;
    lo[idx] = __float2bfloat16(v - __bfloat162float(h));
}

// ============ weight transpose+split: Bt[n,k] = W[k,n] as bf16 hi/lo ============
__global__ void wsplit_kernel(const float* __restrict__ W,
                              __nv_bfloat16* __restrict__ Bh,
                              __nv_bfloat16* __restrict__ Bl, int K, int N) {
    int idx = blockIdx.x * 256 + threadIdx.x;
    if (idx >= K * N) return;
    int k = idx / N, n = idx % N;
    float w = W[idx];
    __nv_bfloat16 h = __float2bfloat16(w);
    Bh[(size_t)n * K + k] = h;
    Bl[(size_t)n * K + k] = __float2bfloat16(w - __bfloat162float(h));
}

// ============ K1: t = layernorm(logmap0(x)) -> bf16 hi/lo ============
// (expmap0 -> logmap0 round-trip in the reference is the identity; skipped)
__global__ void pre_kernel(const float* __restrict__ x,
                           const float* __restrict__ g1,
                           const float* __restrict__ b1,
                           __nv_bfloat16* __restrict__ th,
                           __nv_bfloat16* __restrict__ tl) {
    __shared__ float sbuf[32];
    int row = blockIdx.x, i = threadIdx.x;
    const float* xr = x + (size_t)row * (D_ + 1);
    float xi = xr[1 + i];
    float ss = block_reduce_sum(xi * xi, sbuf);
    float n  = fmaxf(sqrtf(ss), EPSF);
    float x0 = fmaxf(xr[0], 1.0f + 1e-7f);
    float u  = acoshf(x0) * xi / n;
    float s1 = block_reduce_sum(u, sbuf);
    float s2 = block_reduce_sum(u * u, sbuf);
    float mean = s1 * (1.f / D_);
    float var  = s2 * (1.f / D_) - mean * mean;
    float tv = (u - mean) * rsqrtf(var + 1e-5f) * g1[i] + b1[i];
    split_store(th, tl, (size_t)row * D_ + i, tv);
}

// ============ HMMA split-bf16 GEMM (mma.sync.m16n8k16) =================
// C[m,n] = act( sum_k A[m,k] * Bt[n,k] + bias[n] ), 3-pass hi/lo split.
// ACT: 0 none, 1 elu+1, 2 gelu(tanh). OUT: 0 fp32, 1 bf16 hi/lo split.
// Block 128x128, K-tile 32, 8 warps (4 Mrows x 2 Ncols), warp tile 32x64.
// 4-stage cp.async pipeline.
#define STAGES 4
#define ROWB 80                       // padded SMEM row stride (bytes) for 64B data
#define TILEB (128 * ROWB)            // 10240 B per tile
#define STAGEB (4 * TILEB)            // Ah, Al, Bh, Bl = 40960 B
#define GEMM_SMEM (STAGES * STAGEB)   // 163840 B

template<int ACT, int OUT>
__global__ __launch_bounds__(256) void gemm_kernel(
    const __nv_bfloat16* __restrict__ Ah, const __nv_bfloat16* __restrict__ Al,
    const __nv_bfloat16* __restrict__ Bh, const __nv_bfloat16* __restrict__ Bl,
    const float* __restrict__ bias,
    float* __restrict__ Cf,
    __nv_bfloat16* __restrict__ Ch, __nv_bfloat16* __restrict__ Cl,
    int K, int NC)
{
    extern __shared__ char smem[];
    const uint32_t sb = smem_u32(smem);
    const int tid  = threadIdx.x;
    const int lane = tid & 31;
    const int w    = tid >> 5;
    const int mBase = blockIdx.y * 128;
    const int nBase = blockIdx.x * 128;
    const int wm = (w & 3) * 32;      // warp M offset in tile
    const int wn = (w >> 2) * 64;     // warp N offset in tile

    const __nv_bfloat16* srcs[4] = {Ah, Al, Bh, Bl};
    // per-thread cp.async coordinates: idx in [0,512): r = idx>>2, c = idx&3
    const int r0 = tid >> 2, c0 = (tid & 3);

    auto load_stage = [&](int kt, int s) {
        int k0 = kt * 32;
        uint32_t sOff = sb + s * STAGEB;
        #pragma unroll
        for (int t = 0; t < 4; t++) {
            int rowBase = (t < 2) ? mBase : nBase;
            const __nv_bfloat16* src = srcs[t];
            #pragma unroll
            for (int it = 0; it < 2; it++) {
                int r = r0 + it * 64;
                const __nv_bfloat16* g = src + (size_t)(rowBase + r) * K + k0 + c0 * 8;
                uint32_t d = sOff + t * TILEB + r * ROWB + c0 * 16;
                CP_ASYNC16(d, g);
            }
        }
    };

    float acc[2][8][4];
    #pragma unroll
    for (int mt = 0; mt < 2; mt++)
        #pragma unroll
        for (int nt = 0; nt < 8; nt++)
            #pragma unroll
            for (int i = 0; i < 4; i++) acc[mt][nt][i] = 0.f;

    const int nkt = K >> 5;
    // prologue: stages 0..2
    #pragma unroll
    for (int s = 0; s < STAGES - 1; s++) {
        load_stage(s, s);
        CP_COMMIT();
    }

    // ldmatrix per-thread address pieces
    const int aRow = lane & 15;             // row within 16
    const int aSel = lane >> 4;             // 16B half (k0-7 / k8-15)

    for (int kt = 0; kt < nkt; kt++) {
        // prefetch stage kt+3 (slot (kt+3)&3) — safe: its previous contents
        // (stage kt-1) were fully consumed before the sync that ended iter kt-1.
        if (kt + STAGES - 1 < nkt) load_stage(kt + STAGES - 1, (kt + STAGES - 1) & (STAGES - 1));
        CP_COMMIT();                       // empty group on tail — keeps counts uniform
        CP_WAIT(STAGES - 1);               // stage kt complete
        __syncthreads();

        uint32_t base = sb + (kt & (STAGES - 1)) * STAGEB;
        uint32_t aHb = base;                 // Ah tile
        uint32_t aLb = base + TILEB;         // Al tile
        uint32_t bHb = base + 2 * TILEB;     // Bh tile
        uint32_t bLb = base + 3 * TILEB;     // Bl tile

        #pragma unroll
        for (int kk = 0; kk < 2; kk++) {
            // B fragments: 8 n-tiles x (hi, lo); paired LDSM4 (two n8 tiles per op)
            uint32_t bH[8][2], bL[8][2];
            #pragma unroll
            for (int p = 0; p < 4; p++) {
                uint32_t off = (uint32_t)(wn + p * 16 + (lane & 15)) * ROWB
                             + (uint32_t)(2 * kk + (lane >> 4)) * 16;
                uint32_t q0, q1, q2, q3;
                LDSM4(q0, q1, q2, q3, bHb + off);
                bH[2*p][0] = q0; bH[2*p+1][0] = q1; bH[2*p][1] = q2; bH[2*p+1][1] = q3;
                LDSM4(q0, q1, q2, q3, bLb + off);
                bL[2*p][0] = q0; bL[2*p+1][0] = q1; bL[2*p][1] = q2; bL[2*p+1][1] = q3;
            }
            #pragma unroll
            for (int mt = 0; mt < 2; mt++) {
                uint32_t aH[4], aL[4];
                uint32_t off = (uint32_t)(wm + mt * 16 + aRow) * ROWB
                             + (uint32_t)(2 * kk + aSel) * 16;
                LDSM4(aH[0], aH[1], aH[2], aH[3], aHb + off);
                LDSM4(aL[0], aL[1], aL[2], aL[3], aLb + off);
                #pragma unroll
                for (int nt = 0; nt < 8; nt++) {
                    mma16816(acc[mt][nt], aH, bH[nt]);   // Ah * Bh
                    mma16816(acc[mt][nt], aL, bH[nt]);   // Al * Bh
                    mma16816(acc[mt][nt], aH, bL[nt]);   // Ah * Bl
                }
            }
        }
        __syncthreads();   // all warps done reading stage kt before it is refilled
    }

    // ---------------- epilogue ----------------
    const int gid = lane >> 2;               // 0..7 (row in 8-block)
    const int tig = lane & 3;                // 0..3 (col pair)
    #pragma unroll
    for (int mt = 0; mt < 2; mt++) {
        #pragma unroll
        for (int nt = 0; nt < 8; nt++) {
            int col = nBase + wn + nt * 8 + tig * 2;
            float b0 = bias[col], b1 = bias[col + 1];
            #pragma unroll
            for (int half = 0; half < 2; half++) {
                int row = mBase + wm + mt * 16 + gid + half * 8;
                float v0 = acc[mt][nt][half * 2 + 0] + b0;
                float v1 = acc[mt][nt][half * 2 + 1] + b1;
                if (ACT == 1) {
                    v0 = (v0 > 0.f) ? (v0 + 1.f) : __expf(v0);
                    v1 = (v1 > 0.f) ? (v1 + 1.f) : __expf(v1);
                } else if (ACT == 2) {
                    float c0 = v0 * v0 * v0;
                    v0 = 0.5f * v0 * (1.f + tanhf(0.7978845608028654f * (v0 + 0.044715f * c0)));
                    float c1 = v1 * v1 * v1;
                    v1 = 0.5f * v1 * (1.f + tanhf(0.7978845608028654f * (v1 + 0.044715f * c1)));
                }
                size_t base = (size_t)row * NC + col;
                if (OUT == 0) {
                    *reinterpret_cast<float2*>(Cf + base) = make_float2(v0, v1);
                } else {
                    __nv_bfloat16 h0 = __float2bfloat16(v0);
                    __nv_bfloat16 h1 = __float2bfloat16(v1);
                    __nv_bfloat16 l0 = __float2bfloat16(v0 - __bfloat162float(h0));
                    __nv_bfloat16 l1 = __float2bfloat16(v1 - __bfloat162float(h1));
                    uint32_t hp = ((uint32_t)__bfloat16_as_ushort(h1) << 16) | __bfloat16_as_ushort(h0);
                    uint32_t lp = ((uint32_t)__bfloat16_as_ushort(l1) << 16) | __bfloat16_as_ushort(l0);
                    *reinterpret_cast<uint32_t*>(Ch + base) = hp;
                    *reinterpret_cast<uint32_t*>(Cl + base) = lp;
                }
            }
        }
    }
}

// ============ K3: kv / ksum reduction over T ============
__global__ void kv_reduce_kernel(const float* __restrict__ pk,
                                 const float* __restrict__ v,
                                 float* __restrict__ kv,
                                 float* __restrict__ ksum) {
    int bh = blockIdx.x;
    int h  = bh % H_;
    int bj = bh / H_;
    int j  = bj % J_;
    int b  = bj / J_;
    int tid = threadIdx.x;
    int lane = tid & 31, w = tid >> 5;
    __shared__ float sp[4][32];
    __shared__ float sv[4][32];
    float acc[4] = {0.f, 0.f, 0.f, 0.f};
    float ks = 0.f;
    int tl = tid >> 6;
    int e  = tid & 63;
    for (int t0 = 0; t0 < T_; t0 += 4) {
        int t = t0 + tl;
        size_t base = (((size_t)(b * T_ + t) * J_) + j) * D_ + h * DH_;
        float val = (e < 32) ? pk[base + e] : v[base + e - 32];
        __syncthreads();
        if (e < 32) sp[tl][e] = val; else sv[tl][e - 32] = val;
        __syncthreads();
        #pragma unroll
        for (int tt = 0; tt < 4; tt++) {
            float vv = sv[tt][lane];
            #pragma unroll
            for (int c = 0; c < 4; c++)
                acc[c] += sp[tt][w + c * 8] * vv;
            if (w == 0) ks += sp[tt][lane];
        }
    }
    size_t ob = (size_t)bh * (DH_ * DH_);
    #pragma unroll
    for (int c = 0; c < 4; c++)
        kv[ob + (size_t)(w + c * 8) * 32 + lane] = acc[c];
    if (w == 0) ksum[(size_t)bh * 32 + lane] = ks;
}

// ============ K4: y = (pq @ kv) / (pq . ksum + EPS) -> bf16 hi/lo ============
__global__ void attn_apply_kernel(const float* __restrict__ pq,
                                  const float* __restrict__ kv,
                                  const float* __restrict__ ksum,
                                  __nv_bfloat16* __restrict__ yh,
                                  __nv_bfloat16* __restrict__ yl) {
    int bh = blockIdx.x;
    int h  = bh % H_;
    int bj = bh / H_;
    int j  = bj % J_;
    int b  = bj / J_;
    __shared__ float skv[DH_ * DH_];
    __shared__ float sks[DH_];
    int tid = threadIdx.x;
    for (int i = tid; i < DH_ * DH_; i += 256) skv[i] = kv[(size_t)bh * (DH_ * DH_) + i];
    if (tid < DH_) sks[tid] = ksum[(size_t)bh * DH_ + tid];
    __syncthreads();
    int lane = tid & 31, w = tid >> 5;
    for (int t = w; t < T_; t += 8) {
        size_t base = (((size_t)(b * T_ + t) * J_) + j) * D_ + h * DH_;
        float q = pq[base + lane];
        float den = q * sks[lane];
        #pragma unroll
        for (int o = 16; o; o >>= 1) den += __shfl_xor_sync(0xffffffffu, den, o);
        float num = 0.f;
        #pragma unroll
        for (int k = 0; k < 32; k++)
            num += __shfl_sync(0xffffffffu, q, k) * skv[k * 32 + lane];
        split_store(yh, yl, base + lane, num / (den + EPSF));
    }
}

// ============ K5: residual + LN2 -> bf16 hi/lo ============
__global__ void resid_kernel(const float* __restrict__ x,
                             const float* __restrict__ o_in,
                             const float* __restrict__ g2,
                             const float* __restrict__ b2,
                             __nv_bfloat16* __restrict__ uh,
                             __nv_bfloat16* __restrict__ ul) {
    __shared__ float sbuf[32];
    int row = blockIdx.x, i = threadIdx.x;
    const float* xr = x + (size_t)row * (D_ + 1);
    float o = o_in[(size_t)row * D_ + i];
    float so = block_reduce_sum(o * o, sbuf);
    float n  = fmaxf(sqrtf(so), EPSF);
    float z  = sinhf(n) * o / n;
    float m  = xr[1 + i] + z;
    float sm = block_reduce_sum(m * m, sbuf);
    float m0 = xr[0] + coshf(n);
    float mink = -m0 * m0 + sm;
    float inv  = rsqrtf(fmaxf(-mink, EPSF));
    float h0   = m0 * inv;
    float hs   = m * inv;
    float hn   = fmaxf(sqrtf(sm) * inv, EPSF);
    float u    = acoshf(fmaxf(h0, 1.0f + 1e-7f)) * hs / hn;
    float s1 = block_reduce_sum(u, sbuf);
    float s2 = block_reduce_sum(u * u, sbuf);
    float mean = s1 * (1.f / D_);
    float var  = s2 * (1.f / D_) - mean * mean;
    float uv = (u - mean) * rsqrtf(var + 1e-5f) * g2[i] + b2[i];
    split_store(uh, ul, (size_t)row * D_ + i, uv);
}

// ============ K6: out = expmap0(f) ============
__global__ void final_kernel(const float* __restrict__ f_in,
                             float* __restrict__ out) {
    __shared__ float sbuf[32];
    int row = blockIdx.x, i = threadIdx.x;
    float f = f_in[(size_t)row * D_ + i];
    float ss = block_reduce_sum(f * f, sbuf);
    float n  = fmaxf(sqrtf(ss), EPSF);
    float* orow = out + (size_t)row * (D_ + 1);
    orow[1 + i] = sinhf(n) * f / n;
    if (i == 0) orow[0] = coshf(n);
}

// ================= launch =================
extern "C" void kernel_launch(void* const* d_in, const int* /*in_sizes*/, int /*n_in*/,
                              void* d_out, int /*out_size*/) {
    const float* x     = (const float*)d_in[0];
    const float* g1    = (const float*)d_in[1];
    const float* beta1 = (const float*)d_in[2];
    const float* Wq    = (const float*)d_in[3];
    const float* Wk    = (const float*)d_in[4];
    const float* Wv    = (const float*)d_in[5];
    const float* Wo    = (const float*)d_in[6];
    const float* bq    = (const float*)d_in[7];
    const float* bk    = (const float*)d_in[8];
    const float* bv    = (const float*)d_in[9];
    const float* bo    = (const float*)d_in[10];
    const float* g2    = (const float*)d_in[11];
    const float* beta2 = (const float*)d_in[12];
    const float* W1    = (const float*)d_in[13];
    const float* bf1   = (const float*)d_in[14];
    const float* W2    = (const float*)d_in[15];
    const float* bf2   = (const float*)d_in[16];
    float* out = (float*)d_out;

    static bool attr_done = false;
    if (!attr_done) {
        cudaFuncSetAttribute(gemm_kernel<1,0>, cudaFuncAttributeMaxDynamicSharedMemorySize, GEMM_SMEM);
        cudaFuncSetAttribute(gemm_kernel<0,0>, cudaFuncAttributeMaxDynamicSharedMemorySize, GEMM_SMEM);
        cudaFuncSetAttribute(gemm_kernel<2,1>, cudaFuncAttributeMaxDynamicSharedMemorySize, GEMM_SMEM);
        attr_done = true;
    }

    __nv_bfloat16 *th, *tl, *hh, *hl;
    __nv_bfloat16 *wqh, *wql, *wkh, *wkl, *wvh, *wvl, *woh, *wol, *w1h, *w1l, *w2h, *w2l;
    float *q_, *k_, *v_, *kv_, *ks_;
    cudaGetSymbolAddress((void**)&th, g_th);   cudaGetSymbolAddress((void**)&tl, g_tl);
    cudaGetSymbolAddress((void**)&q_, g_q);    cudaGetSymbolAddress((void**)&k_, g_k);
    cudaGetSymbolAddress((void**)&v_, g_v);
    cudaGetSymbolAddress((void**)&hh, g_hh);   cudaGetSymbolAddress((void**)&hl, g_hl);
    cudaGetSymbolAddress((void**)&kv_, g_kv);  cudaGetSymbolAddress((void**)&ks_, g_ks);
    cudaGetSymbolAddress((void**)&wqh, g_wqh); cudaGetSymbolAddress((void**)&wql, g_wql);
    cudaGetSymbolAddress((void**)&wkh, g_wkh); cudaGetSymbolAddress((void**)&wkl, g_wkl);
    cudaGetSymbolAddress((void**)&wvh, g_wvh); cudaGetSymbolAddress((void**)&wvl, g_wvl);
    cudaGetSymbolAddress((void**)&woh, g_woh); cudaGetSymbolAddress((void**)&wol, g_wol);
    cudaGetSymbolAddress((void**)&w1h, g_w1h); cudaGetSymbolAddress((void**)&w1l, g_w1l);
    cudaGetSymbolAddress((void**)&w2h, g_w2h); cudaGetSymbolAddress((void**)&w2l, g_w2l);

    // 0. weight transpose+split (tiny)
    int nDD = D_ * D_, nDH = D_ * HID_;
    wsplit_kernel<<<(nDD + 255) / 256, 256>>>(Wq, wqh, wql, D_, D_);
    wsplit_kernel<<<(nDD + 255) / 256, 256>>>(Wk, wkh, wkl, D_, D_);
    wsplit_kernel<<<(nDD + 255) / 256, 256>>>(Wv, wvh, wvl, D_, D_);
    wsplit_kernel<<<(nDD + 255) / 256, 256>>>(Wo, woh, wol, D_, D_);
    wsplit_kernel<<<(nDH + 255) / 256, 256>>>(W1, w1h, w1l, D_, HID_);
    wsplit_kernel<<<(nDH + 255) / 256, 256>>>(W2, w2h, w2l, HID_, D_);

    // 1. pre: x -> t (bf16 split)
    pre_kernel<<<NTOK, 256>>>(x, g1, beta1, th, tl);

    // 2. QKV projections (HMMA)
    dim3 gD(D_ / 128, NTOK / 128);      // (2, 832)
    gemm_kernel<1,0><<<gD, 256, GEMM_SMEM>>>(th, tl, wqh, wql, bq, q_, nullptr, nullptr, D_, D_);
    gemm_kernel<1,0><<<gD, 256, GEMM_SMEM>>>(th, tl, wkh, wkl, bk, k_, nullptr, nullptr, D_, D_);
    gemm_kernel<0,0><<<gD, 256, GEMM_SMEM>>>(th, tl, wvh, wvl, bv, v_, nullptr, nullptr, D_, D_);

    // 3. linear attention
    kv_reduce_kernel<<<B_ * J_ * H_, 256>>>(k_, v_, kv_, ks_);
    attn_apply_kernel<<<B_ * J_ * H_, 256>>>(q_, kv_, ks_, th, tl);   // y -> th/tl

    // 4. output projection: o = y @ Wo + bo -> q_ (fp32)
    gemm_kernel<0,0><<<gD, 256, GEMM_SMEM>>>(th, tl, woh, wol, bo, q_, nullptr, nullptr, D_, D_);

    // 5. Lorentz residual + LN2 -> th/tl (u2)
    resid_kernel<<<NTOK, 256>>>(x, q_, g2, beta2, th, tl);

    // 6. FFN
    dim3 gH(HID_ / 128, NTOK / 128);    // (8, 832)
    gemm_kernel<2,1><<<gH, 256, GEMM_SMEM>>>(th, tl, w1h, w1l, bf1, nullptr, hh, hl, D_, HID_);
    gemm_kernel<0,0><<<gD, 256, GEMM_SMEM>>>(hh, hl, w2h, w2l, bf2, q_, nullptr, nullptr, HID_, D_);

    // 7. final expmap0 -> out
    final_kernel<<<NTOK, 256>>>(q_, out);
}

// round 6
// speedup vs baseline: 1.0748x; 1.0748x over previous
#include <cuda_runtime.h>
#include <cuda_bf16.h>
#include <math.h>
#include <stdint.h>

#define B_ 8
#define T_ 512
#define J_ 26
#define D_ 256
#define H_ 8
#define DH_ 32
#define HID_ 1024
#define NTOK 106496            // B*T*J  (= 832 * 128 exactly)
#define EPSF 1e-6f

// ================= PTX helpers (base ISA only: sm_80+ features) =================
__device__ __forceinline__ uint32_t smem_u32(const void* p) {
    uint32_t a;
    asm("{ .reg .u64 t; cvta.to.shared.u64 t, %1; cvt.u32.u64 %0, t; }" : "=r"(a) : "l"(p));
    return a;
}
#define CP_ASYNC16(dst, src) \
    asm volatile("cp.async.cg.shared.global [%0], [%1], 16;" :: "r"(dst), "l"(src) : "memory")
#define CP_COMMIT() asm volatile("cp.async.commit_group;" ::: "memory")
#define CP_WAIT(n)  asm volatile("cp.async.wait_group %0;" :: "n"(n) : "memory")

#define LDSM4(r0, r1, r2, r3, addr) \
    asm volatile("ldmatrix.sync.aligned.m8n8.x4.shared.b16 {%0,%1,%2,%3}, [%4];" \
        : "=r"(r0), "=r"(r1), "=r"(r2), "=r"(r3) : "r"(addr))

__device__ __forceinline__ void mma16816(float* c, const uint32_t* a, const uint32_t* b) {
    asm volatile(
        "mma.sync.aligned.m16n8k16.row.col.f32.bf16.bf16.f32 "
        "{%0,%1,%2,%3}, {%4,%5,%6,%7}, {%8,%9}, {%0,%1,%2,%3};"
        : "+f"(c[0]), "+f"(c[1]), "+f"(c[2]), "+f"(c[3])
        : "r"(a[0]), "r"(a[1]), "r"(a[2]), "r"(a[3]), "r"(b[0]), "r"(b[1]));
}

// ================= scratch (static device .bss) =================
__device__ __nv_bfloat16 g_th [(size_t)NTOK * D_];    // t / y / u2  hi
__device__ __nv_bfloat16 g_tl [(size_t)NTOK * D_];    // t / y / u2  lo
__device__ float         g_q  [(size_t)NTOK * D_];    // pq / o / f
__device__ float         g_k  [(size_t)NTOK * D_];    // pk
__device__ float         g_v  [(size_t)NTOK * D_];    // v
__device__ __nv_bfloat16 g_hh [(size_t)NTOK * HID_];  // hid hi
__device__ __nv_bfloat16 g_hl [(size_t)NTOK * HID_];  // hid lo
__device__ float g_kv [(size_t)B_ * J_ * H_ * DH_ * DH_];
__device__ float g_ks [(size_t)B_ * J_ * H_ * DH_];
// transposed bf16 hi/lo weights: Bt[n,k]
__device__ __nv_bfloat16 g_wqh[D_ * D_],   g_wql[D_ * D_];
__device__ __nv_bfloat16 g_wkh[D_ * D_],   g_wkl[D_ * D_];
__device__ __nv_bfloat16 g_wvh[D_ * D_],   g_wvl[D_ * D_];
__device__ __nv_bfloat16 g_woh[D_ * D_],   g_wol[D_ * D_];
__device__ __nv_bfloat16 g_w1h[D_ * HID_], g_w1l[D_ * HID_];
__device__ __nv_bfloat16 g_w2h[HID_ * D_], g_w2l[HID_ * D_];

// ================= small helpers =================
__device__ __forceinline__ float block_reduce_sum(float v, float* sbuf) {
    int lane = threadIdx.x & 31, w = threadIdx.x >> 5;
    #pragma unroll
    for (int o = 16; o; o >>= 1) v += __shfl_down_sync(0xffffffffu, v, o);
    if (lane == 0) sbuf[w] = v;
    __syncthreads();
    float r = (threadIdx.x < 8) ? sbuf[threadIdx.x] : 0.f;
    if (w == 0) {
        r += __shfl_down_sync(0xffffffffu, r, 4);
        r += __shfl_down_sync(0xffffffffu, r, 2);
        r += __shfl_down_sync(0xffffffffu, r, 1);
        if (lane == 0) sbuf[0] = r;
    }
    __syncthreads();
    float res = sbuf[0];
    __syncthreads();
    return res;
}
__device__ __forceinline__ void split_store(__nv_bfloat16* hi, __nv_bfloat16* lo,
                                            size_t idx, float v) {
    __nv_bfloat16 h = __float2bfloat16(v);
    hi[idx] = h;
    lo[idx] = __float2bfloat16(v - __bfloat162float(h));
}

// ============ weight transpose+split: Bt[n,k] = W[k,n] as bf16 hi/lo ============
__global__ void wsplit_kernel(const float* __restrict__ W,
                              __nv_bfloat16* __restrict__ Bh,
                              __nv_bfloat16* __restrict__ Bl, int K, int N) {
    int idx = blockIdx.x * 256 + threadIdx.x;
    if (idx >= K * N) return;
    int k = idx / N, n = idx % N;
    float w = W[idx];
    __nv_bfloat16 h = __float2bfloat16(w);
    Bh[(size_t)n * K + k] = h;
    Bl[(size_t)n * K + k] = __float2bfloat16(w - __bfloat162float(h));
}

// ============ K1: t = layernorm(logmap0(x)) -> bf16 hi/lo ============
// (expmap0 -> logmap0 round-trip in the reference is the identity; skipped)
__global__ void pre_kernel(const float* __restrict__ x,
                           const float* __restrict__ g1,
                           const float* __restrict__ b1,
                           __nv_bfloat16* __restrict__ th,
                           __nv_bfloat16* __restrict__ tl) {
    __shared__ float sbuf[32];
    int row = blockIdx.x, i = threadIdx.x;
    const float* xr = x + (size_t)row * (D_ + 1);
    float xi = xr[1 + i];
    float ss = block_reduce_sum(xi * xi, sbuf);
    float n  = fmaxf(sqrtf(ss), EPSF);
    float x0 = fmaxf(xr[0], 1.0f + 1e-7f);
    float u  = acoshf(x0) * xi / n;
    float s1 = block_reduce_sum(u, sbuf);
    float s2 = block_reduce_sum(u * u, sbuf);
    float mean = s1 * (1.f / D_);
    float var  = s2 * (1.f / D_) - mean * mean;
    float tv = (u - mean) * rsqrtf(var + 1e-5f) * g1[i] + b1[i];
    split_store(th, tl, (size_t)row * D_ + i, tv);
}

// ============ HMMA split-bf16 GEMM (mma.sync.m16n8k16) =================
// C[m,n] = act( sum_k A[m,k] * Bt[n,k] + bias[n] ), 3-pass hi/lo split.
// ACT: 0 none, 1 elu+1, 2 gelu(tanh). OUT: 0 fp32, 1 bf16 hi/lo split.
// Block 128x128, K-tile 32, 8 warps (4 Mrows x 2 Ncols), warp tile 32x64.
// 2-stage cp.async double buffer (2 CTAs/SM), ONE __syncthreads per K-iter.
#define STAGES 2
#define ROWB 80                       // padded SMEM row stride (bytes) for 64B data
#define TILEB (128 * ROWB)            // 10240 B per tile
#define STAGEB (4 * TILEB)            // Ah, Al, Bh, Bl = 40960 B
#define GEMM_SMEM (STAGES * STAGEB)   // 81920 B -> 2 CTAs/SM

template<int ACT, int OUT>
__global__ __launch_bounds__(256) void gemm_kernel(
    const __nv_bfloat16* __restrict__ Ah, const __nv_bfloat16* __restrict__ Al,
    const __nv_bfloat16* __restrict__ Bh, const __nv_bfloat16* __restrict__ Bl,
    const float* __restrict__ bias,
    float* __restrict__ Cf,
    __nv_bfloat16* __restrict__ Ch, __nv_bfloat16* __restrict__ Cl,
    int K, int NC)
{
    extern __shared__ char smem[];
    const uint32_t sb = smem_u32(smem);
    const int tid  = threadIdx.x;
    const int lane = tid & 31;
    const int w    = tid >> 5;
    const int mBase = blockIdx.y * 128;
    const int nBase = blockIdx.x * 128;
    const int wm = (w & 3) * 32;      // warp M offset in tile
    const int wn = (w >> 2) * 64;     // warp N offset in tile

    const __nv_bfloat16* srcs[4] = {Ah, Al, Bh, Bl};
    const int r0 = tid >> 2, c0 = (tid & 3);

    auto load_stage = [&](int kt, int s) {
        int k0 = kt * 32;
        uint32_t sOff = sb + s * STAGEB;
        #pragma unroll
        for (int t = 0; t < 4; t++) {
            int rowBase = (t < 2) ? mBase : nBase;
            const __nv_bfloat16* src = srcs[t];
            #pragma unroll
            for (int it = 0; it < 2; it++) {
                int r = r0 + it * 64;
                const __nv_bfloat16* g = src + (size_t)(rowBase + r) * K + k0 + c0 * 8;
                uint32_t d = sOff + t * TILEB + r * ROWB + c0 * 16;
                CP_ASYNC16(d, g);
            }
        }
    };

    float acc[2][8][4];
    #pragma unroll
    for (int mt = 0; mt < 2; mt++)
        #pragma unroll
        for (int nt = 0; nt < 8; nt++)
            #pragma unroll
            for (int i = 0; i < 4; i++) acc[mt][nt][i] = 0.f;

    const int nkt = K >> 5;
    load_stage(0, 0);
    CP_COMMIT();

    const int aRow = lane & 15;
    const int aSel = lane >> 4;

    for (int kt = 0; kt < nkt; kt++) {
        CP_WAIT(0);               // stage kt data arrived (this thread's copies)
        __syncthreads();          // all threads' copies visible; all warps done with slot kt^1
        if (kt + 1 < nkt) {       // prefetch overlaps compute of stage kt
            load_stage(kt + 1, (kt + 1) & 1);
            CP_COMMIT();
        }

        uint32_t base = sb + (kt & 1) * STAGEB;
        uint32_t aHb = base;
        uint32_t aLb = base + TILEB;
        uint32_t bHb = base + 2 * TILEB;
        uint32_t bLb = base + 3 * TILEB;

        #pragma unroll
        for (int kk = 0; kk < 2; kk++) {
            uint32_t bH[8][2], bL[8][2];
            #pragma unroll
            for (int p = 0; p < 4; p++) {
                uint32_t off = (uint32_t)(wn + p * 16 + (lane & 15)) * ROWB
                             + (uint32_t)(2 * kk + (lane >> 4)) * 16;
                uint32_t q0, q1, q2, q3;
                LDSM4(q0, q1, q2, q3, bHb + off);
                bH[2*p][0] = q0; bH[2*p+1][0] = q1; bH[2*p][1] = q2; bH[2*p+1][1] = q3;
                LDSM4(q0, q1, q2, q3, bLb + off);
                bL[2*p][0] = q0; bL[2*p+1][0] = q1; bL[2*p][1] = q2; bL[2*p+1][1] = q3;
            }
            #pragma unroll
            for (int mt = 0; mt < 2; mt++) {
                uint32_t aH[4], aL[4];
                uint32_t off = (uint32_t)(wm + mt * 16 + aRow) * ROWB
                             + (uint32_t)(2 * kk + aSel) * 16;
                LDSM4(aH[0], aH[1], aH[2], aH[3], aHb + off);
                LDSM4(aL[0], aL[1], aL[2], aL[3], aLb + off);
                #pragma unroll
                for (int nt = 0; nt < 8; nt++) {
                    mma16816(acc[mt][nt], aH, bH[nt]);   // Ah * Bh
                    mma16816(acc[mt][nt], aL, bH[nt]);   // Al * Bh
                    mma16816(acc[mt][nt], aH, bL[nt]);   // Ah * Bl
                }
            }
        }
    }

    // ---------------- epilogue ----------------
    const int gid = lane >> 2;
    const int tig = lane & 3;
    #pragma unroll
    for (int mt = 0; mt < 2; mt++) {
        #pragma unroll
        for (int nt = 0; nt < 8; nt++) {
            int col = nBase + wn + nt * 8 + tig * 2;
            float b0 = bias[col], b1 = bias[col + 1];
            #pragma unroll
            for (int half = 0; half < 2; half++) {
                int row = mBase + wm + mt * 16 + gid + half * 8;
                float v0 = acc[mt][nt][half * 2 + 0] + b0;
                float v1 = acc[mt][nt][half * 2 + 1] + b1;
                if (ACT == 1) {
                    v0 = (v0 > 0.f) ? (v0 + 1.f) : __expf(v0);
                    v1 = (v1 > 0.f) ? (v1 + 1.f) : __expf(v1);
                } else if (ACT == 2) {
                    float c0 = v0 * v0 * v0;
                    v0 = 0.5f * v0 * (1.f + tanhf(0.7978845608028654f * (v0 + 0.044715f * c0)));
                    float c1 = v1 * v1 * v1;
                    v1 = 0.5f * v1 * (1.f + tanhf(0.7978845608028654f * (v1 + 0.044715f * c1)));
                }
                size_t base = (size_t)row * NC + col;
                if (OUT == 0) {
                    *reinterpret_cast<float2*>(Cf + base) = make_float2(v0, v1);
                } else {
                    __nv_bfloat16 h0 = __float2bfloat16(v0);
                    __nv_bfloat16 h1 = __float2bfloat16(v1);
                    __nv_bfloat16 l0 = __float2bfloat16(v0 - __bfloat162float(h0));
                    __nv_bfloat16 l1 = __float2bfloat16(v1 - __bfloat162float(h1));
                    uint32_t hp = ((uint32_t)__bfloat16_as_ushort(h1) << 16) | __bfloat16_as_ushort(h0);
                    uint32_t lp = ((uint32_t)__bfloat16_as_ushort(l1) << 16) | __bfloat16_as_ushort(l0);
                    *reinterpret_cast<uint32_t*>(Ch + base) = hp;
                    *reinterpret_cast<uint32_t*>(Cl + base) = lp;
                }
            }
        }
    }
}

// ============ K3: kv / ksum reduction over T ============
__global__ void kv_reduce_kernel(const float* __restrict__ pk,
                                 const float* __restrict__ v,
                                 float* __restrict__ kv,
                                 float* __restrict__ ksum) {
    int bh = blockIdx.x;
    int h  = bh % H_;
    int bj = bh / H_;
    int j  = bj % J_;
    int b  = bj / J_;
    int tid = threadIdx.x;
    int lane = tid & 31, w = tid >> 5;
    __shared__ float sp[4][32];
    __shared__ float sv[4][32];
    float acc[4] = {0.f, 0.f, 0.f, 0.f};
    float ks = 0.f;
    int tl = tid >> 6;
    int e  = tid & 63;
    for (int t0 = 0; t0 < T_; t0 += 4) {
        int t = t0 + tl;
        size_t base = (((size_t)(b * T_ + t) * J_) + j) * D_ + h * DH_;
        float val = (e < 32) ? pk[base + e] : v[base + e - 32];
        __syncthreads();
        if (e < 32) sp[tl][e] = val; else sv[tl][e - 32] = val;
        __syncthreads();
        #pragma unroll
        for (int tt = 0; tt < 4; tt++) {
            float vv = sv[tt][lane];
            #pragma unroll
            for (int c = 0; c < 4; c++)
                acc[c] += sp[tt][w + c * 8] * vv;
            if (w == 0) ks += sp[tt][lane];
        }
    }
    size_t ob = (size_t)bh * (DH_ * DH_);
    #pragma unroll
    for (int c = 0; c < 4; c++)
        kv[ob + (size_t)(w + c * 8) * 32 + lane] = acc[c];
    if (w == 0) ksum[(size_t)bh * 32 + lane] = ks;
}

// ============ K4: y = (pq @ kv) / (pq . ksum + EPS) -> bf16 hi/lo ============
__global__ void attn_apply_kernel(const float* __restrict__ pq,
                                  const float* __restrict__ kv,
                                  const float* __restrict__ ksum,
                                  __nv_bfloat16* __restrict__ yh,
                                  __nv_bfloat16* __restrict__ yl) {
    int bh = blockIdx.x;
    int h  = bh % H_;
    int bj = bh / H_;
    int j  = bj % J_;
    int b  = bj / J_;
    __shared__ float skv[DH_ * DH_];
    __shared__ float sks[DH_];
    int tid = threadIdx.x;
    for (int i = tid; i < DH_ * DH_; i += 256) skv[i] = kv[(size_t)bh * (DH_ * DH_) + i];
    if (tid < DH_) sks[tid] = ksum[(size_t)bh * DH_ + tid];
    __syncthreads();
    int lane = tid & 31, w = tid >> 5;
    for (int t = w; t < T_; t += 8) {
        size_t base = (((size_t)(b * T_ + t) * J_) + j) * D_ + h * DH_;
        float q = pq[base + lane];
        float den = q * sks[lane];
        #pragma unroll
        for (int o = 16; o; o >>= 1) den += __shfl_xor_sync(0xffffffffu, den, o);
        float num = 0.f;
        #pragma unroll
        for (int k = 0; k < 32; k++)
            num += __shfl_sync(0xffffffffu, q, k) * skv[k * 32 + lane];
        split_store(yh, yl, base + lane, num / (den + EPSF));
    }
}

// ============ K5: residual + LN2 -> bf16 hi/lo ============
__global__ void resid_kernel(const float* __restrict__ x,
                             const float* __restrict__ o_in,
                             const float* __restrict__ g2,
                             const float* __restrict__ b2,
                             __nv_bfloat16* __restrict__ uh,
                             __nv_bfloat16* __restrict__ ul) {
    __shared__ float sbuf[32];
    int row = blockIdx.x, i = threadIdx.x;
    const float* xr = x + (size_t)row * (D_ + 1);
    float o = o_in[(size_t)row * D_ + i];
    float so = block_reduce_sum(o * o, sbuf);
    float n  = fmaxf(sqrtf(so), EPSF);
    float z  = sinhf(n) * o / n;
    float m  = xr[1 + i] + z;
    float sm = block_reduce_sum(m * m, sbuf);
    float m0 = xr[0] + coshf(n);
    float mink = -m0 * m0 + sm;
    float inv  = rsqrtf(fmaxf(-mink, EPSF));
    float h0   = m0 * inv;
    float hs   = m * inv;
    float hn   = fmaxf(sqrtf(sm) * inv, EPSF);
    float u    = acoshf(fmaxf(h0, 1.0f + 1e-7f)) * hs / hn;
    float s1 = block_reduce_sum(u, sbuf);
    float s2 = block_reduce_sum(u * u, sbuf);
    float mean = s1 * (1.f / D_);
    float var  = s2 * (1.f / D_) - mean * mean;
    float uv = (u - mean) * rsqrtf(var + 1e-5f) * g2[i] + b2[i];
    split_store(uh, ul, (size_t)row * D_ + i, uv);
}

// ============ K6: out = expmap0(f) ============
__global__ void final_kernel(const float* __restrict__ f_in,
                             float* __restrict__ out) {
    __shared__ float sbuf[32];
    int row = blockIdx.x, i = threadIdx.x;
    float f = f_in[(size_t)row * D_ + i];
    float ss = block_reduce_sum(f * f, sbuf);
    float n  = fmaxf(sqrtf(ss), EPSF);
    float* orow = out + (size_t)row * (D_ + 1);
    orow[1 + i] = sinhf(n) * f / n;
    if (i == 0) orow[0] = coshf(n);
}

// ================= launch =================
extern "C" void kernel_launch(void* const* d_in, const int* /*in_sizes*/, int /*n_in*/,
                              void* d_out, int /*out_size*/) {
    const float* x     = (const float*)d_in[0];
    const float* g1    = (const float*)d_in[1];
    const float* beta1 = (const float*)d_in[2];
    const float* Wq    = (const float*)d_in[3];
    const float* Wk    = (const float*)d_in[4];
    const float* Wv    = (const float*)d_in[5];
    const float* Wo    = (const float*)d_in[6];
    const float* bq    = (const float*)d_in[7];
    const float* bk    = (const float*)d_in[8];
    const float* bv    = (const float*)d_in[9];
    const float* bo    = (const float*)d_in[10];
    const float* g2    = (const float*)d_in[11];
    const float* beta2 = (const float*)d_in[12];
    const float* W1    = (const float*)d_in[13];
    const float* bf1   = (const float*)d_in[14];
    const float* W2    = (const float*)d_in[15];
    const float* bf2   = (const float*)d_in[16];
    float* out = (float*)d_out;

    static bool attr_done = false;
    if (!attr_done) {
        cudaFuncSetAttribute(gemm_kernel<1,0>, cudaFuncAttributeMaxDynamicSharedMemorySize, GEMM_SMEM);
        cudaFuncSetAttribute(gemm_kernel<0,0>, cudaFuncAttributeMaxDynamicSharedMemorySize, GEMM_SMEM);
        cudaFuncSetAttribute(gemm_kernel<2,1>, cudaFuncAttributeMaxDynamicSharedMemorySize, GEMM_SMEM);
        attr_done = true;
    }

    __nv_bfloat16 *th, *tl, *hh, *hl;
    __nv_bfloat16 *wqh, *wql, *wkh, *wkl, *wvh, *wvl, *woh, *wol, *w1h, *w1l, *w2h, *w2l;
    float *q_, *k_, *v_, *kv_, *ks_;
    cudaGetSymbolAddress((void**)&th, g_th);   cudaGetSymbolAddress((void**)&tl, g_tl);
    cudaGetSymbolAddress((void**)&q_, g_q);    cudaGetSymbolAddress((void**)&k_, g_k);
    cudaGetSymbolAddress((void**)&v_, g_v);
    cudaGetSymbolAddress((void**)&hh, g_hh);   cudaGetSymbolAddress((void**)&hl, g_hl);
    cudaGetSymbolAddress((void**)&kv_, g_kv);  cudaGetSymbolAddress((void**)&ks_, g_ks);
    cudaGetSymbolAddress((void**)&wqh, g_wqh); cudaGetSymbolAddress((void**)&wql, g_wql);
    cudaGetSymbolAddress((void**)&wkh, g_wkh); cudaGetSymbolAddress((void**)&wkl, g_wkl);
    cudaGetSymbolAddress((void**)&wvh, g_wvh); cudaGetSymbolAddress((void**)&wvl, g_wvl);
    cudaGetSymbolAddress((void**)&woh, g_woh); cudaGetSymbolAddress((void**)&wol, g_wol);
    cudaGetSymbolAddress((void**)&w1h, g_w1h); cudaGetSymbolAddress((void**)&w1l, g_w1l);
    cudaGetSymbolAddress((void**)&w2h, g_w2h); cudaGetSymbolAddress((void**)&w2l, g_w2l);

    // 0. weight transpose+split (tiny)
    int nDD = D_ * D_, nDH = D_ * HID_;
    wsplit_kernel<<<(nDD + 255) / 256, 256>>>(Wq, wqh, wql, D_, D_);
    wsplit_kernel<<<(nDD + 255) / 256, 256>>>(Wk, wkh, wkl, D_, D_);
    wsplit_kernel<<<(nDD + 255) / 256, 256>>>(Wv, wvh, wvl, D_, D_);
    wsplit_kernel<<<(nDD + 255) / 256, 256>>>(Wo, woh, wol, D_, D_);
    wsplit_kernel<<<(nDH + 255) / 256, 256>>>(W1, w1h, w1l, D_, HID_);
    wsplit_kernel<<<(nDH + 255) / 256, 256>>>(W2, w2h, w2l, HID_, D_);

    // 1. pre: x -> t (bf16 split)
    pre_kernel<<<NTOK, 256>>>(x, g1, beta1, th, tl);

    // 2. QKV projections (HMMA)
    dim3 gD(D_ / 128, NTOK / 128);      // (2, 832)
    gemm_kernel<1,0><<<gD, 256, GEMM_SMEM>>>(th, tl, wqh, wql, bq, q_, nullptr, nullptr, D_, D_);
    gemm_kernel<1,0><<<gD, 256, GEMM_SMEM>>>(th, tl, wkh, wkl, bk, k_, nullptr, nullptr, D_, D_);
    gemm_kernel<0,0><<<gD, 256, GEMM_SMEM>>>(th, tl, wvh, wvl, bv, v_, nullptr, nullptr, D_, D_);

    // 3. linear attention
    kv_reduce_kernel<<<B_ * J_ * H_, 256>>>(k_, v_, kv_, ks_);
    attn_apply_kernel<<<B_ * J_ * H_, 256>>>(q_, kv_, ks_, th, tl);   // y -> th/tl

    // 4. output projection: o = y @ Wo + bo -> q_ (fp32)
    gemm_kernel<0,0><<<gD, 256, GEMM_SMEM>>>(th, tl, woh, wol, bo, q_, nullptr, nullptr, D_, D_);

    // 5. Lorentz residual + LN2 -> th/tl (u2)
    resid_kernel<<<NTOK, 256>>>(x, q_, g2, beta2, th, tl);

    // 6. FFN
    dim3 gH(HID_ / 128, NTOK / 128);    // (8, 832)
    gemm_kernel<2,1><<<gH, 256, GEMM_SMEM>>>(th, tl, w1h, w1l, bf1, nullptr, hh, hl, D_, HID_);
    gemm_kernel<0,0><<<gD, 256, GEMM_SMEM>>>(hh, hl, w2h, w2l, bf2, q_, nullptr, nullptr, HID_, D_);

    // 7. final expmap0 -> out
    final_kernel<<<NTOK, 256>>>(q_, out);
}

// round 7
// speedup vs baseline: 1.1378x; 1.0586x over previous
#include <cuda_runtime.h>
#include <cuda_bf16.h>
#include <math.h>
#include <stdint.h>

#define B_ 8
#define T_ 512
#define J_ 26
#define D_ 256
#define H_ 8
#define DH_ 32
#define HID_ 1024
#define NTOK 106496            // B*T*J  (= 832 * 128 exactly)
#define EPSF 1e-6f

// ================= PTX helpers (base ISA only: sm_80+ features) =================
__device__ __forceinline__ uint32_t smem_u32(const void* p) {
    uint32_t a;
    asm("{ .reg .u64 t; cvta.to.shared.u64 t, %1; cvt.u32.u64 %0, t; }" : "=r"(a) : "l"(p));
    return a;
}
#define CP_ASYNC16(dst, src) \
    asm volatile("cp.async.cg.shared.global [%0], [%1], 16;" :: "r"(dst), "l"(src) : "memory")
#define CP_COMMIT() asm volatile("cp.async.commit_group;" ::: "memory")
#define CP_WAIT(n)  asm volatile("cp.async.wait_group %0;" :: "n"(n) : "memory")

#define LDSM4(r0, r1, r2, r3, addr) \
    asm volatile("ldmatrix.sync.aligned.m8n8.x4.shared.b16 {%0,%1,%2,%3}, [%4];" \
        : "=r"(r0), "=r"(r1), "=r"(r2), "=r"(r3) : "r"(addr))

__device__ __forceinline__ void mma16816(float* c, const uint32_t* a, const uint32_t* b) {
    asm volatile(
        "mma.sync.aligned.m16n8k16.row.col.f32.bf16.bf16.f32 "
        "{%0,%1,%2,%3}, {%4,%5,%6,%7}, {%8,%9}, {%0,%1,%2,%3};"
        : "+f"(c[0]), "+f"(c[1]), "+f"(c[2]), "+f"(c[3])
        : "r"(a[0]), "r"(a[1]), "r"(a[2]), "r"(a[3]), "r"(b[0]), "r"(b[1]));
}

// ================= scratch (static device .bss) =================
__device__ __nv_bfloat16 g_th [(size_t)NTOK * D_];    // t / y / u2  hi
__device__ __nv_bfloat16 g_tl [(size_t)NTOK * D_];    // t / y / u2  lo
__device__ float         g_q  [(size_t)NTOK * D_];    // pq / o / f
__device__ float         g_k  [(size_t)NTOK * D_];    // pk
__device__ float         g_v  [(size_t)NTOK * D_];    // v
__device__ __nv_bfloat16 g_hh [(size_t)NTOK * HID_];  // hid hi
__device__ __nv_bfloat16 g_hl [(size_t)NTOK * HID_];  // hid lo
__device__ float g_kv [(size_t)B_ * J_ * H_ * DH_ * DH_];
__device__ float g_ks [(size_t)B_ * J_ * H_ * DH_];
// transposed bf16 hi/lo weights: Bt[n,k]
__device__ __nv_bfloat16 g_wqkvh[768 * D_],  g_wqkvl[768 * D_];   // rows: 0-255 Q, 256-511 K, 512-767 V
__device__ __nv_bfloat16 g_woh[D_ * D_],     g_wol[D_ * D_];
__device__ __nv_bfloat16 g_w1h[D_ * HID_],   g_w1l[D_ * HID_];
__device__ __nv_bfloat16 g_w2h[HID_ * D_],   g_w2l[HID_ * D_];
__device__ float g_bqkv[768];

// ================= small helpers =================
__device__ __forceinline__ float block_reduce_sum(float v, float* sbuf) {
    int lane = threadIdx.x & 31, w = threadIdx.x >> 5;
    #pragma unroll
    for (int o = 16; o; o >>= 1) v += __shfl_down_sync(0xffffffffu, v, o);
    if (lane == 0) sbuf[w] = v;
    __syncthreads();
    float r = (threadIdx.x < 8) ? sbuf[threadIdx.x] : 0.f;
    if (w == 0) {
        r += __shfl_down_sync(0xffffffffu, r, 4);
        r += __shfl_down_sync(0xffffffffu, r, 2);
        r += __shfl_down_sync(0xffffffffu, r, 1);
        if (lane == 0) sbuf[0] = r;
    }
    __syncthreads();
    float res = sbuf[0];
    __syncthreads();
    return res;
}
__device__ __forceinline__ void split_store(__nv_bfloat16* hi, __nv_bfloat16* lo,
                                            size_t idx, float v) {
    __nv_bfloat16 h = __float2bfloat16(v);
    hi[idx] = h;
    lo[idx] = __float2bfloat16(v - __bfloat162float(h));
}
__device__ __forceinline__ void wsplit_one(float w, __nv_bfloat16* Bh, __nv_bfloat16* Bl,
                                           size_t off) {
    __nv_bfloat16 h = __float2bfloat16(w);
    Bh[off] = h;
    Bl[off] = __float2bfloat16(w - __bfloat162float(h));
}

// ============ single kernel: all weight transposes/splits + bias concat ============
__global__ void wsplit_all_kernel(const float* __restrict__ Wq, const float* __restrict__ Wk,
                                  const float* __restrict__ Wv, const float* __restrict__ Wo,
                                  const float* __restrict__ W1, const float* __restrict__ W2,
                                  const float* __restrict__ bq, const float* __restrict__ bk,
                                  const float* __restrict__ bv) {
    int idx = blockIdx.x * 256 + threadIdx.x;
    if (idx < 196608) {                       // Wq, Wk, Wv -> fused qkv rows
        int wsel = idx >> 16;                 // 0,1,2
        int local = idx & 65535;
        const float* W = (wsel == 0) ? Wq : (wsel == 1) ? Wk : Wv;
        int k = local >> 8, n = local & 255;
        wsplit_one(W[local], g_wqkvh, g_wqkvl, (size_t)(wsel * 256 + n) * D_ + k);
    } else if (idx < 262144) {                // Wo
        int local = idx - 196608;
        int k = local >> 8, n = local & 255;
        wsplit_one(Wo[local], g_woh, g_wol, (size_t)n * D_ + k);
    } else if (idx < 524288) {                // W1 [D, HID]
        int local = idx - 262144;
        int k = local >> 10, n = local & 1023;
        wsplit_one(W1[local], g_w1h, g_w1l, (size_t)n * D_ + k);
    } else if (idx < 786432) {                // W2 [HID, D]
        int local = idx - 524288;
        int k = local >> 8, n = local & 255;
        wsplit_one(W2[local], g_w2h, g_w2l, (size_t)n * HID_ + k);
    } else if (idx < 787200) {                // bias concat
        int bi = idx - 786432;
        g_bqkv[bi] = (bi < 256) ? bq[bi] : (bi < 512) ? bk[bi - 256] : bv[bi - 512];
    }
}

// ============ K1: t = layernorm(logmap0(x)) -> bf16 hi/lo ============
// (expmap0 -> logmap0 round-trip in the reference is the identity; skipped)
__global__ void pre_kernel(const float* __restrict__ x,
                           const float* __restrict__ g1,
                           const float* __restrict__ b1,
                           __nv_bfloat16* __restrict__ th,
                           __nv_bfloat16* __restrict__ tl) {
    __shared__ float sbuf[32];
    int row = blockIdx.x, i = threadIdx.x;
    const float* xr = x + (size_t)row * (D_ + 1);
    float xi = xr[1 + i];
    float ss = block_reduce_sum(xi * xi, sbuf);
    float n  = fmaxf(sqrtf(ss), EPSF);
    float x0 = fmaxf(xr[0], 1.0f + 1e-7f);
    float u  = acoshf(x0) * xi / n;
    float s1 = block_reduce_sum(u, sbuf);
    float s2 = block_reduce_sum(u * u, sbuf);
    float mean = s1 * (1.f / D_);
    float var  = s2 * (1.f / D_) - mean * mean;
    float tv = (u - mean) * rsqrtf(var + 1e-5f) * g1[i] + b1[i];
    split_store(th, tl, (size_t)row * D_ + i, tv);
}

// ============ HMMA split-bf16 GEMM (mma.sync.m16n8k16) =================
// MODE 0: fp32 out, no act.  MODE 1: fp32 out, elu+1.
// MODE 2: bf16 hi/lo out, gelu.  MODE 3: fused QKV (route by nBase, elu for Q/K).
#define STAGES 2
#define ROWB 80                       // padded SMEM row stride (bytes) for 64B data
#define TILEB (128 * ROWB)            // 10240 B per tile
#define STAGEB (4 * TILEB)            // Ah, Al, Bh, Bl = 40960 B
#define GEMM_SMEM (STAGES * STAGEB)   // 81920 B -> 2 CTAs/SM

template<int MODE>
__global__ __launch_bounds__(256, 2) void gemm_kernel(
    const __nv_bfloat16* __restrict__ Ah, const __nv_bfloat16* __restrict__ Al,
    const __nv_bfloat16* __restrict__ Bh, const __nv_bfloat16* __restrict__ Bl,
    const float* __restrict__ bias,
    float* __restrict__ Cf, float* __restrict__ Cf2, float* __restrict__ Cf3,
    __nv_bfloat16* __restrict__ Ch, __nv_bfloat16* __restrict__ Cl,
    int K, int NC)
{
    extern __shared__ char smem[];
    const uint32_t sb = smem_u32(smem);
    const int tid  = threadIdx.x;
    const int lane = tid & 31;
    const int w    = tid >> 5;
    const int mBase = blockIdx.y * 128;
    const int nBase = blockIdx.x * 128;
    const int wm = (w & 3) * 32;      // warp M offset in tile
    const int wn = (w >> 2) * 64;     // warp N offset in tile

    const __nv_bfloat16* srcs[4] = {Ah, Al, Bh, Bl};
    const int r0 = tid >> 2, c0 = (tid & 3);

    auto load_stage = [&](int kt, int s) {
        int k0 = kt * 32;
        uint32_t sOff = sb + s * STAGEB;
        #pragma unroll
        for (int t = 0; t < 4; t++) {
            int rowBase = (t < 2) ? mBase : nBase;
            const __nv_bfloat16* src = srcs[t];
            #pragma unroll
            for (int it = 0; it < 2; it++) {
                int r = r0 + it * 64;
                const __nv_bfloat16* g = src + (size_t)(rowBase + r) * K + k0 + c0 * 8;
                uint32_t d = sOff + t * TILEB + r * ROWB + c0 * 16;
                CP_ASYNC16(d, g);
            }
        }
    };

    float acc[2][8][4];
    #pragma unroll
    for (int mt = 0; mt < 2; mt++)
        #pragma unroll
        for (int nt = 0; nt < 8; nt++)
            #pragma unroll
            for (int i = 0; i < 4; i++) acc[mt][nt][i] = 0.f;

    const int nkt = K >> 5;
    load_stage(0, 0);
    CP_COMMIT();

    const int aRow = lane & 15;
    const int aSel = lane >> 4;

    for (int kt = 0; kt < nkt; kt++) {
        if (kt + 1 < nkt) { load_stage(kt + 1, (kt + 1) & 1); CP_COMMIT(); CP_WAIT(1); }
        else              { CP_WAIT(0); }
        __syncthreads();

        uint32_t base = sb + (kt & 1) * STAGEB;
        uint32_t aHb = base;
        uint32_t aLb = base + TILEB;
        uint32_t bHb = base + 2 * TILEB;
        uint32_t bLb = base + 3 * TILEB;

        #pragma unroll
        for (int kk = 0; kk < 2; kk++) {
            uint32_t bH[8][2], bL[8][2];
            #pragma unroll
            for (int p = 0; p < 4; p++) {
                uint32_t off = (uint32_t)(wn + p * 16 + (lane & 15)) * ROWB
                             + (uint32_t)(2 * kk + (lane >> 4)) * 16;
                uint32_t q0, q1, q2, q3;
                LDSM4(q0, q1, q2, q3, bHb + off);
                bH[2*p][0] = q0; bH[2*p+1][0] = q1; bH[2*p][1] = q2; bH[2*p+1][1] = q3;
                LDSM4(q0, q1, q2, q3, bLb + off);
                bL[2*p][0] = q0; bL[2*p+1][0] = q1; bL[2*p][1] = q2; bL[2*p+1][1] = q3;
            }
            #pragma unroll
            for (int mt = 0; mt < 2; mt++) {
                uint32_t aH[4], aL[4];
                uint32_t off = (uint32_t)(wm + mt * 16 + aRow) * ROWB
                             + (uint32_t)(2 * kk + aSel) * 16;
                LDSM4(aH[0], aH[1], aH[2], aH[3], aHb + off);
                LDSM4(aL[0], aL[1], aL[2], aL[3], aLb + off);
                // pass-major ordering: 8-apart accumulator reuse distance
                #pragma unroll
                for (int nt = 0; nt < 8; nt++) mma16816(acc[mt][nt], aH, bH[nt]);
                #pragma unroll
                for (int nt = 0; nt < 8; nt++) mma16816(acc[mt][nt], aL, bH[nt]);
                #pragma unroll
                for (int nt = 0; nt < 8; nt++) mma16816(acc[mt][nt], aH, bL[nt]);
            }
        }
        __syncthreads();
    }

    // ---------------- epilogue ----------------
    const int gid = lane >> 2;
    const int tig = lane & 3;
    // QKV routing (uniform per CTA)
    int which = 0; float* dstQKV = Cf; bool eluAct = false; int nLoc = nBase;
    if (MODE == 3) {
        which = nBase >> 8;
        dstQKV = (which == 0) ? Cf : (which == 1) ? Cf2 : Cf3;
        eluAct = (which < 2);
        nLoc = nBase - which * 256;
    }
    #pragma unroll
    for (int mt = 0; mt < 2; mt++) {
        #pragma unroll
        for (int nt = 0; nt < 8; nt++) {
            int colT = wn + nt * 8 + tig * 2;            // col within 128-tile
            float b0 = bias[nBase + colT], b1 = bias[nBase + colT + 1];
            #pragma unroll
            for (int half = 0; half < 2; half++) {
                int row = mBase + wm + mt * 16 + gid + half * 8;
                float v0 = acc[mt][nt][half * 2 + 0] + b0;
                float v1 = acc[mt][nt][half * 2 + 1] + b1;
                if (MODE == 1 || (MODE == 3 && eluAct)) {
                    v0 = (v0 > 0.f) ? (v0 + 1.f) : __expf(v0);
                    v1 = (v1 > 0.f) ? (v1 + 1.f) : __expf(v1);
                } else if (MODE == 2) {
                    float c0 = v0 * v0 * v0;
                    v0 = 0.5f * v0 * (1.f + tanhf(0.7978845608028654f * (v0 + 0.044715f * c0)));
                    float c1 = v1 * v1 * v1;
                    v1 = 0.5f * v1 * (1.f + tanhf(0.7978845608028654f * (v1 + 0.044715f * c1)));
                }
                if (MODE == 2) {
                    size_t base = (size_t)row * NC + nBase + colT;
                    __nv_bfloat16 h0 = __float2bfloat16(v0);
                    __nv_bfloat16 h1 = __float2bfloat16(v1);
                    __nv_bfloat16 l0 = __float2bfloat16(v0 - __bfloat162float(h0));
                    __nv_bfloat16 l1 = __float2bfloat16(v1 - __bfloat162float(h1));
                    uint32_t hp = ((uint32_t)__bfloat16_as_ushort(h1) << 16) | __bfloat16_as_ushort(h0);
                    uint32_t lp = ((uint32_t)__bfloat16_as_ushort(l1) << 16) | __bfloat16_as_ushort(l0);
                    *reinterpret_cast<uint32_t*>(Ch + base) = hp;
                    *reinterpret_cast<uint32_t*>(Cl + base) = lp;
                } else if (MODE == 3) {
                    size_t base = (size_t)row * 256 + nLoc + colT;
                    *reinterpret_cast<float2*>(dstQKV + base) = make_float2(v0, v1);
                } else {
                    size_t base = (size_t)row * NC + nBase + colT;
                    *reinterpret_cast<float2*>(Cf + base) = make_float2(v0, v1);
                }
            }
        }
    }
}

// ============ K3: kv / ksum reduction over T ============
__global__ void kv_reduce_kernel(const float* __restrict__ pk,
                                 const float* __restrict__ v,
                                 float* __restrict__ kv,
                                 float* __restrict__ ksum) {
    int bh = blockIdx.x;
    int h  = bh % H_;
    int bj = bh / H_;
    int j  = bj % J_;
    int b  = bj / J_;
    int tid = threadIdx.x;
    int lane = tid & 31, w = tid >> 5;
    __shared__ float sp[4][32];
    __shared__ float sv[4][32];
    float acc[4] = {0.f, 0.f, 0.f, 0.f};
    float ks = 0.f;
    int tl = tid >> 6;
    int e  = tid & 63;
    for (int t0 = 0; t0 < T_; t0 += 4) {
        int t = t0 + tl;
        size_t base = (((size_t)(b * T_ + t) * J_) + j) * D_ + h * DH_;
        float val = (e < 32) ? pk[base + e] : v[base + e - 32];
        __syncthreads();
        if (e < 32) sp[tl][e] = val; else sv[tl][e - 32] = val;
        __syncthreads();
        #pragma unroll
        for (int tt = 0; tt < 4; tt++) {
            float vv = sv[tt][lane];
            #pragma unroll
            for (int c = 0; c < 4; c++)
                acc[c] += sp[tt][w + c * 8] * vv;
            if (w == 0) ks += sp[tt][lane];
        }
    }
    size_t ob = (size_t)bh * (DH_ * DH_);
    #pragma unroll
    for (int c = 0; c < 4; c++)
        kv[ob + (size_t)(w + c * 8) * 32 + lane] = acc[c];
    if (w == 0) ksum[(size_t)bh * 32 + lane] = ks;
}

// ============ K4: y = (pq @ kv) / (pq . ksum + EPS) -> bf16 hi/lo ============
__global__ void attn_apply_kernel(const float* __restrict__ pq,
                                  const float* __restrict__ kv,
                                  const float* __restrict__ ksum,
                                  __nv_bfloat16* __restrict__ yh,
                                  __nv_bfloat16* __restrict__ yl) {
    int bh = blockIdx.x;
    int h  = bh % H_;
    int bj = bh / H_;
    int j  = bj % J_;
    int b  = bj / J_;
    __shared__ float skv[DH_ * DH_];
    __shared__ float sks[DH_];
    int tid = threadIdx.x;
    for (int i = tid; i < DH_ * DH_; i += 256) skv[i] = kv[(size_t)bh * (DH_ * DH_) + i];
    if (tid < DH_) sks[tid] = ksum[(size_t)bh * DH_ + tid];
    __syncthreads();
    int lane = tid & 31, w = tid >> 5;
    for (int t = w; t < T_; t += 8) {
        size_t baseQ = (((size_t)(b * T_ + t) * J_) + j) * D_ + h * DH_;
        float q = pq[baseQ + lane];
        float den = q * sks[lane];
        #pragma unroll
        for (int o = 16; o; o >>= 1) den += __shfl_xor_sync(0xffffffffu, den, o);
        float num = 0.f;
        #pragma unroll
        for (int k = 0; k < 32; k++)
            num += __shfl_sync(0xffffffffu, q, k) * skv[k * 32 + lane];
        split_store(yh, yl, baseQ + lane, num / (den + EPSF));
    }
}

// ============ K5: residual + LN2 -> bf16 hi/lo ============
__global__ void resid_kernel(const float* __restrict__ x,
                             const float* __restrict__ o_in,
                             const float* __restrict__ g2,
                             const float* __restrict__ b2,
                             __nv_bfloat16* __restrict__ uh,
                             __nv_bfloat16* __restrict__ ul) {
    __shared__ float sbuf[32];
    int row = blockIdx.x, i = threadIdx.x;
    const float* xr = x + (size_t)row * (D_ + 1);
    float o = o_in[(size_t)row * D_ + i];
    float so = block_reduce_sum(o * o, sbuf);
    float n  = fmaxf(sqrtf(so), EPSF);
    float z  = sinhf(n) * o / n;
    float m  = xr[1 + i] + z;
    float sm = block_reduce_sum(m * m, sbuf);
    float m0 = xr[0] + coshf(n);
    float mink = -m0 * m0 + sm;
    float inv  = rsqrtf(fmaxf(-mink, EPSF));
    float h0   = m0 * inv;
    float hs   = m * inv;
    float hn   = fmaxf(sqrtf(sm) * inv, EPSF);
    float u    = acoshf(fmaxf(h0, 1.0f + 1e-7f)) * hs / hn;
    float s1 = block_reduce_sum(u, sbuf);
    float s2 = block_reduce_sum(u * u, sbuf);
    float mean = s1 * (1.f / D_);
    float var  = s2 * (1.f / D_) - mean * mean;
    float uv = (u - mean) * rsqrtf(var + 1e-5f) * g2[i] + b2[i];
    split_store(uh, ul, (size_t)row * D_ + i, uv);
}

// ============ K6: out = expmap0(f) ============
__global__ void final_kernel(const float* __restrict__ f_in,
                             float* __restrict__ out) {
    __shared__ float sbuf[32];
    int row = blockIdx.x, i = threadIdx.x;
    float f = f_in[(size_t)row * D_ + i];
    float ss = block_reduce_sum(f * f, sbuf);
    float n  = fmaxf(sqrtf(ss), EPSF);
    float* orow = out + (size_t)row * (D_ + 1);
    orow[1 + i] = sinhf(n) * f / n;
    if (i == 0) orow[0] = coshf(n);
}

// ================= launch =================
extern "C" void kernel_launch(void* const* d_in, const int* /*in_sizes*/, int /*n_in*/,
                              void* d_out, int /*out_size*/) {
    const float* x     = (const float*)d_in[0];
    const float* g1    = (const float*)d_in[1];
    const float* beta1 = (const float*)d_in[2];
    const float* Wq    = (const float*)d_in[3];
    const float* Wk    = (const float*)d_in[4];
    const float* Wv    = (const float*)d_in[5];
    const float* Wo    = (const float*)d_in[6];
    const float* bq    = (const float*)d_in[7];
    const float* bk    = (const float*)d_in[8];
    const float* bv    = (const float*)d_in[9];
    const float* bo    = (const float*)d_in[10];
    const float* g2    = (const float*)d_in[11];
    const float* beta2 = (const float*)d_in[12];
    const float* W1    = (const float*)d_in[13];
    const float* bf1   = (const float*)d_in[14];
    const float* W2    = (const float*)d_in[15];
    const float* bf2   = (const float*)d_in[16];
    float* out = (float*)d_out;

    static bool attr_done = false;
    if (!attr_done) {
        cudaFuncSetAttribute(gemm_kernel<0>, cudaFuncAttributeMaxDynamicSharedMemorySize, GEMM_SMEM);
        cudaFuncSetAttribute(gemm_kernel<2>, cudaFuncAttributeMaxDynamicSharedMemorySize, GEMM_SMEM);
        cudaFuncSetAttribute(gemm_kernel<3>, cudaFuncAttributeMaxDynamicSharedMemorySize, GEMM_SMEM);
        attr_done = true;
    }

    __nv_bfloat16 *th, *tl, *hh, *hl;
    __nv_bfloat16 *wqkvh, *wqkvl, *woh, *wol, *w1h, *w1l, *w2h, *w2l;
    float *q_, *k_, *v_, *kv_, *ks_, *bqkv_;
    cudaGetSymbolAddress((void**)&th, g_th);     cudaGetSymbolAddress((void**)&tl, g_tl);
    cudaGetSymbolAddress((void**)&q_, g_q);      cudaGetSymbolAddress((void**)&k_, g_k);
    cudaGetSymbolAddress((void**)&v_, g_v);
    cudaGetSymbolAddress((void**)&hh, g_hh);     cudaGetSymbolAddress((void**)&hl, g_hl);
    cudaGetSymbolAddress((void**)&kv_, g_kv);    cudaGetSymbolAddress((void**)&ks_, g_ks);
    cudaGetSymbolAddress((void**)&wqkvh, g_wqkvh); cudaGetSymbolAddress((void**)&wqkvl, g_wqkvl);
    cudaGetSymbolAddress((void**)&woh, g_woh);   cudaGetSymbolAddress((void**)&wol, g_wol);
    cudaGetSymbolAddress((void**)&w1h, g_w1h);   cudaGetSymbolAddress((void**)&w1l, g_w1l);
    cudaGetSymbolAddress((void**)&w2h, g_w2h);   cudaGetSymbolAddress((void**)&w2l, g_w2l);
    cudaGetSymbolAddress((void**)&bqkv_, g_bqkv);

    // 0. all weight prep in ONE launch
    wsplit_all_kernel<<<3075, 256>>>(Wq, Wk, Wv, Wo, W1, W2, bq, bk, bv);

    // 1. pre: x -> t (bf16 split)
    pre_kernel<<<NTOK, 256>>>(x, g1, beta1, th, tl);

    // 2. fused QKV projection (launch index 2)
    dim3 gQKV(768 / 128, NTOK / 128);   // (6, 832)
    gemm_kernel<3><<<gQKV, 256, GEMM_SMEM>>>(th, tl, wqkvh, wqkvl, bqkv_,
                                             q_, k_, v_, nullptr, nullptr, D_, 256);

    // 3. linear attention (launches 3, 4)
    kv_reduce_kernel<<<B_ * J_ * H_, 256>>>(k_, v_, kv_, ks_);
    attn_apply_kernel<<<B_ * J_ * H_, 256>>>(q_, kv_, ks_, th, tl);   // y -> th/tl

    // 4. output projection (launch index 5 — ncu captures this one)
    dim3 gD(D_ / 128, NTOK / 128);      // (2, 832)
    gemm_kernel<0><<<gD, 256, GEMM_SMEM>>>(th, tl, woh, wol, bo,
                                           q_, nullptr, nullptr, nullptr, nullptr, D_, D_);

    // 5. Lorentz residual + LN2 -> th/tl (u2)
    resid_kernel<<<NTOK, 256>>>(x, q_, g2, beta2, th, tl);

    // 6. FFN
    dim3 gH(HID_ / 128, NTOK / 128);    // (8, 832)
    gemm_kernel<2><<<gH, 256, GEMM_SMEM>>>(th, tl, w1h, w1l, bf1,
                                           nullptr, nullptr, nullptr, hh, hl, D_, HID_);
    gemm_kernel<0><<<gD, 256, GEMM_SMEM>>>(hh, hl, w2h, w2l, bf2,
                                           q_, nullptr, nullptr, nullptr, nullptr, HID_, D_);

    // 7. final expmap0 -> out
    final_kernel<<<NTOK, 256>>>(q_, out);
}

// round 8
// speedup vs baseline: 1.3255x; 1.1650x over previous
#include <cuda_runtime.h>
#include <cuda_bf16.h>
#include <math.h>
#include <stdint.h>

#define B_ 8
#define T_ 512
#define J_ 26
#define D_ 256
#define H_ 8
#define DH_ 32
#define HID_ 1024
#define NTOK 106496            // B*T*J  (= 832 * 128 exactly)
#define EPSF 1e-6f

// ================= PTX helpers (base ISA: sm_90 bulk-async, sm_80 mma) =================
__device__ __forceinline__ uint32_t smem_u32(const void* p) {
    uint32_t a;
    asm("{ .reg .u64 t; cvta.to.shared.u64 t, %1; cvt.u32.u64 %0, t; }" : "=r"(a) : "l"(p));
    return a;
}
#define MBAR_INIT(addr, cnt) \
    asm volatile("mbarrier.init.shared.b64 [%0], %1;" :: "r"(addr), "r"(cnt) : "memory")
#define MBAR_EXPECT_TX(addr, bytes) \
    asm volatile("mbarrier.arrive.expect_tx.shared.b64 _, [%0], %1;" :: "r"(addr), "r"(bytes) : "memory")
#define MBAR_WAIT(addr, phase) do { \
    uint32_t _m = (addr), _p = (phase); \
    asm volatile("{\n\t.reg .pred P;\n\tWL_%=:\n\t" \
        "mbarrier.try_wait.parity.acquire.cta.shared::cta.b64 P, [%0], %1, 0x989680;\n\t" \
        "@P bra.uni WD_%=;\n\tbra.uni WL_%=;\n\tWD_%=:\n\t}" :: "r"(_m), "r"(_p) : "memory"); \
} while (0)
#define CP_BULK(dst, src, bytes, mbar) \
    asm volatile("cp.async.bulk.shared::cluster.global.mbarrier::complete_tx::bytes [%0], [%1], %2, [%3];" \
        :: "r"(dst), "l"(src), "r"(bytes), "r"(mbar) : "memory")

#define LDSM4(r0, r1, r2, r3, addr) \
    asm volatile("ldmatrix.sync.aligned.m8n8.x4.shared.b16 {%0,%1,%2,%3}, [%4];" \
        : "=r"(r0), "=r"(r1), "=r"(r2), "=r"(r3) : "r"(addr))

__device__ __forceinline__ void mma16816(float* c, const uint32_t* a, const uint32_t* b) {
    asm volatile(
        "mma.sync.aligned.m16n8k16.row.col.f32.bf16.bf16.f32 "
        "{%0,%1,%2,%3}, {%4,%5,%6,%7}, {%8,%9}, {%0,%1,%2,%3};"
        : "+f"(c[0]), "+f"(c[1]), "+f"(c[2]), "+f"(c[3])
        : "r"(a[0]), "r"(a[1]), "r"(a[2]), "r"(a[3]), "r"(b[0]), "r"(b[1]));
}

// ============ tiled layout: [mtile][ktile][hi|lo][128x32 swizzled] ============
// tile = 128 rows x 32 cols bf16 = 4096 elems = 8192 B; hi+lo pair = 16384 B.
// within tile: elem(r, c) = r*32 + ((cc ^ ((r>>1)&3))<<3) + (c&7), cc = (c>>3)&3
// -> 64B rows; ldmatrix 8-row phases hit all 32 banks exactly once (conflict-free).
__device__ __forceinline__ size_t tiled_idx(int row, int col, int wKt) {
    int mt = row >> 7, r = row & 127, kt = col >> 5, c = col & 31;
    return ((size_t)(mt * wKt + kt) * 2) * 4096 + (size_t)(r * 32)
         + (size_t)(((((c >> 3) & 3) ^ ((r >> 1) & 3)) << 3) + (c & 7));
}

// ================= scratch (static device .bss) =================
__device__ __nv_bfloat16 g_ta [(size_t)NTOK * D_ * 2];    // t / y / u2, tiled hi|lo, wKt=8
__device__ __nv_bfloat16 g_ha [(size_t)NTOK * HID_ * 2];  // FFN hidden, tiled hi|lo, wKt=32
__device__ float         g_q  [(size_t)NTOK * D_];        // pq / o / f
__device__ float         g_k  [(size_t)NTOK * D_];        // pk
__device__ float         g_v  [(size_t)NTOK * D_];        // v
__device__ float g_kv [(size_t)B_ * J_ * H_ * DH_ * DH_];
__device__ float g_ks [(size_t)B_ * J_ * H_ * DH_];
// weights, tiled hi|lo (B operand: rows = output col n, cols = k)
__device__ __nv_bfloat16 g_wqkv[768 * D_ * 2];      // 6 ntiles, wKt=8
__device__ __nv_bfloat16 g_wo  [D_ * D_ * 2];       // 2 ntiles, wKt=8
__device__ __nv_bfloat16 g_w1  [HID_ * D_ * 2];     // 8 ntiles, wKt=8
__device__ __nv_bfloat16 g_w2  [D_ * HID_ * 2];     // 2 ntiles, wKt=32
__device__ float g_bqkv[768];

// ================= small helpers =================
__device__ __forceinline__ float block_reduce_sum(float v, float* sbuf) {
    int lane = threadIdx.x & 31, w = threadIdx.x >> 5;
    #pragma unroll
    for (int o = 16; o; o >>= 1) v += __shfl_down_sync(0xffffffffu, v, o);
    if (lane == 0) sbuf[w] = v;
    __syncthreads();
    float r = (threadIdx.x < 8) ? sbuf[threadIdx.x] : 0.f;
    if (w == 0) {
        r += __shfl_down_sync(0xffffffffu, r, 4);
        r += __shfl_down_sync(0xffffffffu, r, 2);
        r += __shfl_down_sync(0xffffffffu, r, 1);
        if (lane == 0) sbuf[0] = r;
    }
    __syncthreads();
    float res = sbuf[0];
    __syncthreads();
    return res;
}
// split fp32 -> bf16 hi/lo and store into tiled array (hi at idx, lo at idx+4096)
__device__ __forceinline__ void split_store_tiled(__nv_bfloat16* base, int row, int col,
                                                  int wKt, float v) {
    size_t idx = tiled_idx(row, col, wKt);
    __nv_bfloat16 h = __float2bfloat16(v);
    base[idx] = h;
    base[idx + 4096] = __float2bfloat16(v - __bfloat162float(h));
}

// ============ weight prep: transpose + split + tile, one launch ============
__global__ void wsplit_all_kernel(const float* __restrict__ Wq, const float* __restrict__ Wk,
                                  const float* __restrict__ Wv, const float* __restrict__ Wo,
                                  const float* __restrict__ W1, const float* __restrict__ W2,
                                  const float* __restrict__ bq, const float* __restrict__ bk,
                                  const float* __restrict__ bv) {
    int idx = blockIdx.x * 256 + threadIdx.x;
    if (idx < 196608) {                       // Wq, Wk, Wv [k,n] -> fused rows n' = wsel*256+n
        int wsel = idx >> 16;
        int local = idx & 65535;
        const float* W = (wsel == 0) ? Wq : (wsel == 1) ? Wk : Wv;
        int k = local >> 8, n = local & 255;
        split_store_tiled(g_wqkv, wsel * 256 + n, k, 8, W[local]);
    } else if (idx < 262144) {                // Wo [k,n]
        int local = idx - 196608;
        int k = local >> 8, n = local & 255;
        split_store_tiled(g_wo, n, k, 8, Wo[local]);
    } else if (idx < 524288) {                // W1 [k (256), n (1024)]
        int local = idx - 262144;
        int k = local >> 10, n = local & 1023;
        split_store_tiled(g_w1, n, k, 8, W1[local]);
    } else if (idx < 786432) {                // W2 [k (1024), n (256)]
        int local = idx - 524288;
        int k = local >> 8, n = local & 255;
        split_store_tiled(g_w2, n, k, 32, W2[local]);
    } else if (idx < 787200) {
        int bi = idx - 786432;
        g_bqkv[bi] = (bi < 256) ? bq[bi] : (bi < 512) ? bk[bi - 256] : bv[bi - 512];
    }
}

// ============ K1: t = layernorm(logmap0(x)) -> tiled bf16 hi/lo ============
// (expmap0 -> logmap0 round-trip in the reference is the identity; skipped)
__global__ void pre_kernel(const float* __restrict__ x,
                           const float* __restrict__ g1,
                           const float* __restrict__ b1,
                           __nv_bfloat16* __restrict__ ta) {
    __shared__ float sbuf[32];
    int row = blockIdx.x, i = threadIdx.x;
    const float* xr = x + (size_t)row * (D_ + 1);
    float xi = xr[1 + i];
    float ss = block_reduce_sum(xi * xi, sbuf);
    float n  = fmaxf(sqrtf(ss), EPSF);
    float x0 = fmaxf(xr[0], 1.0f + 1e-7f);
    float u  = acoshf(x0) * xi / n;
    float s1 = block_reduce_sum(u, sbuf);
    float s2 = block_reduce_sum(u * u, sbuf);
    float mean = s1 * (1.f / D_);
    float var  = s2 * (1.f / D_) - mean * mean;
    float tv = (u - mean) * rsqrtf(var + 1e-5f) * g1[i] + b1[i];
    split_store_tiled(ta, row, i, 8, tv);
}

// ============ HMMA split-bf16 GEMM, bulk-async staged =================
// MODE 0: fp32 out, no act.  MODE 2: tiled bf16 hi/lo out, gelu.
// MODE 3: fused QKV (route by nBase, elu for Q/K), fp32 out.
// Stage smem: A pair 16KB | B pair 16KB; double buffered. mbars at sb+0, sb+8.
#define STAGE_DATA 32768
#define GEMM_SMEM (64 + 2 * STAGE_DATA)   // 65600 B -> 2 CTAs/SM

template<int MODE>
__global__ __launch_bounds__(256) void gemm_kernel(
    const __nv_bfloat16* __restrict__ A,     // tiled, wKt = nkt
    const __nv_bfloat16* __restrict__ Bw,    // tiled, wKt = nkt
    const float* __restrict__ bias,
    float* __restrict__ Cf, float* __restrict__ Cf2, float* __restrict__ Cf3,
    __nv_bfloat16* __restrict__ Ct,          // tiled out (MODE 2)
    int nkt, int NC)
{
    extern __shared__ char smem[];
    const uint32_t sb = smem_u32(smem);
    const int tid  = threadIdx.x;
    const int lane = tid & 31;
    const int w    = tid >> 5;
    const int mTile = blockIdx.y;
    const int nTile = blockIdx.x;
    const int mBase = mTile * 128;
    const int nBase = nTile * 128;
    const int wm = (w & 3) * 32;
    const int wn = (w >> 2) * 64;

    if (tid == 0) { MBAR_INIT(sb, 1); MBAR_INIT(sb + 8, 1); }
    __syncthreads();

    const char* Ab = (const char*)A + (size_t)mTile * nkt * 16384;
    const char* Bb = (const char*)Bw + (size_t)nTile * nkt * 16384;

    if (tid == 0) {
        MBAR_EXPECT_TX(sb, 32768);
        CP_BULK(sb + 64,          Ab, 16384u, sb);
        CP_BULK(sb + 64 + 16384,  Bb, 16384u, sb);
    }

    float acc[2][8][4];
    #pragma unroll
    for (int mt = 0; mt < 2; mt++)
        #pragma unroll
        for (int nt = 0; nt < 8; nt++)
            #pragma unroll
            for (int i = 0; i < 4; i++) acc[mt][nt][i] = 0.f;

    const int aRow = lane & 15;
    const int aSel = lane >> 4;

    for (int kt = 0; kt < nkt; kt++) {
        int s = kt & 1;
        if (tid == 0 && kt + 1 < nkt) {        // prefetch next stage into other slot
            uint32_t mb2 = sb + (uint32_t)(s ^ 1) * 8;
            uint32_t d2  = sb + 64 + (uint32_t)(s ^ 1) * STAGE_DATA;
            MBAR_EXPECT_TX(mb2, 32768);
            CP_BULK(d2,         Ab + (size_t)(kt + 1) * 16384, 16384u, mb2);
            CP_BULK(d2 + 16384, Bb + (size_t)(kt + 1) * 16384, 16384u, mb2);
        }
        MBAR_WAIT(sb + (uint32_t)s * 8, (kt >> 1) & 1);

        uint32_t sbase = sb + 64 + (uint32_t)s * STAGE_DATA;
        uint32_t aHb = sbase;
        uint32_t aLb = sbase + 8192;
        uint32_t bHb = sbase + 16384;
        uint32_t bLb = sbase + 24576;

        #pragma unroll
        for (int kk = 0; kk < 2; kk++) {
            uint32_t bH[8][2], bL[8][2];
            #pragma unroll
            for (int p = 0; p < 4; p++) {
                int row = wn + p * 16 + (lane & 15);
                int cc  = 2 * kk + (lane >> 4);
                uint32_t off = (uint32_t)(row * 64 + ((cc ^ ((row >> 1) & 3)) << 4));
                uint32_t q0, q1, q2, q3;
                LDSM4(q0, q1, q2, q3, bHb + off);
                bH[2*p][0] = q0; bH[2*p+1][0] = q1; bH[2*p][1] = q2; bH[2*p+1][1] = q3;
                LDSM4(q0, q1, q2, q3, bLb + off);
                bL[2*p][0] = q0; bL[2*p+1][0] = q1; bL[2*p][1] = q2; bL[2*p+1][1] = q3;
            }
            #pragma unroll
            for (int mt = 0; mt < 2; mt++) {
                int row = wm + mt * 16 + aRow;
                int cc  = 2 * kk + aSel;
                uint32_t off = (uint32_t)(row * 64 + ((cc ^ ((row >> 1) & 3)) << 4));
                uint32_t aH[4], aL[4];
                LDSM4(aH[0], aH[1], aH[2], aH[3], aHb + off);
                LDSM4(aL[0], aL[1], aL[2], aL[3], aLb + off);
                #pragma unroll
                for (int nt = 0; nt < 8; nt++) {
                    mma16816(acc[mt][nt], aH, bH[nt]);   // Ah * Bh
                    mma16816(acc[mt][nt], aL, bH[nt]);   // Al * Bh
                    mma16816(acc[mt][nt], aH, bL[nt]);   // Ah * Bl
                }
            }
        }
        __syncthreads();   // all warps done with slot s -> safe to refill at iter kt+2
    }

    // ---------------- epilogue ----------------
    const int gid = lane >> 2;
    const int tig = lane & 3;
    int which = 0; float* dstQKV = Cf; bool eluAct = false; int nLoc = nBase;
    if (MODE == 3) {
        which = nBase >> 8;
        dstQKV = (which == 0) ? Cf : (which == 1) ? Cf2 : Cf3;
        eluAct = (which < 2);
        nLoc = nBase - which * 256;
    }
    #pragma unroll
    for (int mt = 0; mt < 2; mt++) {
        #pragma unroll
        for (int nt = 0; nt < 8; nt++) {
            int colT = wn + nt * 8 + tig * 2;
            float b0 = bias[nBase + colT], b1 = bias[nBase + colT + 1];
            #pragma unroll
            for (int half = 0; half < 2; half++) {
                int row = mBase + wm + mt * 16 + gid + half * 8;
                float v0 = acc[mt][nt][half * 2 + 0] + b0;
                float v1 = acc[mt][nt][half * 2 + 1] + b1;
                if (MODE == 3 && eluAct) {
                    v0 = (v0 > 0.f) ? (v0 + 1.f) : __expf(v0);
                    v1 = (v1 > 0.f) ? (v1 + 1.f) : __expf(v1);
                } else if (MODE == 2) {
                    float c0 = v0 * v0 * v0;
                    v0 = 0.5f * v0 * (1.f + tanhf(0.7978845608028654f * (v0 + 0.044715f * c0)));
                    float c1 = v1 * v1 * v1;
                    v1 = 0.5f * v1 * (1.f + tanhf(0.7978845608028654f * (v1 + 0.044715f * c1)));
                }
                if (MODE == 2) {
                    // tiled bf16 hi/lo out; col pair lies in one 16B chunk
                    size_t idx = tiled_idx(row, nBase + colT, NC >> 5);
                    __nv_bfloat16 h0 = __float2bfloat16(v0);
                    __nv_bfloat16 h1 = __float2bfloat16(v1);
                    __nv_bfloat16 l0 = __float2bfloat16(v0 - __bfloat162float(h0));
                    __nv_bfloat16 l1 = __float2bfloat16(v1 - __bfloat162float(h1));
                    uint32_t hp = ((uint32_t)__bfloat16_as_ushort(h1) << 16) | __bfloat16_as_ushort(h0);
                    uint32_t lp = ((uint32_t)__bfloat16_as_ushort(l1) << 16) | __bfloat16_as_ushort(l0);
                    *reinterpret_cast<uint32_t*>(Ct + idx) = hp;
                    *reinterpret_cast<uint32_t*>(Ct + idx + 4096) = lp;
                } else if (MODE == 3) {
                    size_t base = (size_t)row * 256 + nLoc + colT;
                    *reinterpret_cast<float2*>(dstQKV + base) = make_float2(v0, v1);
                } else {
                    size_t base = (size_t)row * NC + nBase + colT;
                    *reinterpret_cast<float2*>(Cf + base) = make_float2(v0, v1);
                }
            }
        }
    }
}

// ============ K3: kv / ksum reduction over T ============
__global__ void kv_reduce_kernel(const float* __restrict__ pk,
                                 const float* __restrict__ v,
                                 float* __restrict__ kv,
                                 float* __restrict__ ksum) {
    int bh = blockIdx.x;
    int h  = bh % H_;
    int bj = bh / H_;
    int j  = bj % J_;
    int b  = bj / J_;
    int tid = threadIdx.x;
    int lane = tid & 31, w = tid >> 5;
    __shared__ float sp[4][32];
    __shared__ float sv[4][32];
    float acc[4] = {0.f, 0.f, 0.f, 0.f};
    float ks = 0.f;
    int tl = tid >> 6;
    int e  = tid & 63;
    for (int t0 = 0; t0 < T_; t0 += 4) {
        int t = t0 + tl;
        size_t base = (((size_t)(b * T_ + t) * J_) + j) * D_ + h * DH_;
        float val = (e < 32) ? pk[base + e] : v[base + e - 32];
        __syncthreads();
        if (e < 32) sp[tl][e] = val; else sv[tl][e - 32] = val;
        __syncthreads();
        #pragma unroll
        for (int tt = 0; tt < 4; tt++) {
            float vv = sv[tt][lane];
            #pragma unroll
            for (int c = 0; c < 4; c++)
                acc[c] += sp[tt][w + c * 8] * vv;
            if (w == 0) ks += sp[tt][lane];
        }
    }
    size_t ob = (size_t)bh * (DH_ * DH_);
    #pragma unroll
    for (int c = 0; c < 4; c++)
        kv[ob + (size_t)(w + c * 8) * 32 + lane] = acc[c];
    if (w == 0) ksum[(size_t)bh * 32 + lane] = ks;
}

// ============ K4: y = (pq @ kv) / (pq . ksum + EPS) -> tiled bf16 hi/lo ============
__global__ void attn_apply_kernel(const float* __restrict__ pq,
                                  const float* __restrict__ kv,
                                  const float* __restrict__ ksum,
                                  __nv_bfloat16* __restrict__ ya) {
    int bh = blockIdx.x;
    int h  = bh % H_;
    int bj = bh / H_;
    int j  = bj % J_;
    int b  = bj / J_;
    __shared__ float skv[DH_ * DH_];
    __shared__ float sks[DH_];
    int tid = threadIdx.x;
    for (int i = tid; i < DH_ * DH_; i += 256) skv[i] = kv[(size_t)bh * (DH_ * DH_) + i];
    if (tid < DH_) sks[tid] = ksum[(size_t)bh * DH_ + tid];
    __syncthreads();
    int lane = tid & 31, w = tid >> 5;
    for (int t = w; t < T_; t += 8) {
        int token = (b * T_ + t) * J_ + j;
        size_t baseQ = (size_t)token * D_ + h * DH_;
        float q = pq[baseQ + lane];
        float den = q * sks[lane];
        #pragma unroll
        for (int o = 16; o; o >>= 1) den += __shfl_xor_sync(0xffffffffu, den, o);
        float num = 0.f;
        #pragma unroll
        for (int k = 0; k < 32; k++)
            num += __shfl_sync(0xffffffffu, q, k) * skv[k * 32 + lane];
        split_store_tiled(ya, token, h * DH_ + lane, 8, num / (den + EPSF));
    }
}

// ============ K5: residual + LN2 -> tiled bf16 hi/lo ============
__global__ void resid_kernel(const float* __restrict__ x,
                             const float* __restrict__ o_in,
                             const float* __restrict__ g2,
                             const float* __restrict__ b2,
                             __nv_bfloat16* __restrict__ ua) {
    __shared__ float sbuf[32];
    int row = blockIdx.x, i = threadIdx.x;
    const float* xr = x + (size_t)row * (D_ + 1);
    float o = o_in[(size_t)row * D_ + i];
    float so = block_reduce_sum(o * o, sbuf);
    float n  = fmaxf(sqrtf(so), EPSF);
    float z  = sinhf(n) * o / n;
    float m  = xr[1 + i] + z;
    float sm = block_reduce_sum(m * m, sbuf);
    float m0 = xr[0] + coshf(n);
    float mink = -m0 * m0 + sm;
    float inv  = rsqrtf(fmaxf(-mink, EPSF));
    float h0   = m0 * inv;
    float hs   = m * inv;
    float hn   = fmaxf(sqrtf(sm) * inv, EPSF);
    float u    = acoshf(fmaxf(h0, 1.0f + 1e-7f)) * hs / hn;
    float s1 = block_reduce_sum(u, sbuf);
    float s2 = block_reduce_sum(u * u, sbuf);
    float mean = s1 * (1.f / D_);
    float var  = s2 * (1.f / D_) - mean * mean;
    float uv = (u - mean) * rsqrtf(var + 1e-5f) * g2[i] + b2[i];
    split_store_tiled(ua, row, i, 8, uv);
}

// ============ K6: out = expmap0(f) ============
__global__ void final_kernel(const float* __restrict__ f_in,
                             float* __restrict__ out) {
    __shared__ float sbuf[32];
    int row = blockIdx.x, i = threadIdx.x;
    float f = f_in[(size_t)row * D_ + i];
    float ss = block_reduce_sum(f * f, sbuf);
    float n  = fmaxf(sqrtf(ss), EPSF);
    float* orow = out + (size_t)row * (D_ + 1);
    orow[1 + i] = sinhf(n) * f / n;
    if (i == 0) orow[0] = coshf(n);
}

// ================= launch =================
extern "C" void kernel_launch(void* const* d_in, const int* /*in_sizes*/, int /*n_in*/,
                              void* d_out, int /*out_size*/) {
    const float* x     = (const float*)d_in[0];
    const float* g1    = (const float*)d_in[1];
    const float* beta1 = (const float*)d_in[2];
    const float* Wq    = (const float*)d_in[3];
    const float* Wk    = (const float*)d_in[4];
    const float* Wv    = (const float*)d_in[5];
    const float* Wo    = (const float*)d_in[6];
    const float* bq    = (const float*)d_in[7];
    const float* bk    = (const float*)d_in[8];
    const float* bv    = (const float*)d_in[9];
    const float* bo    = (const float*)d_in[10];
    const float* g2    = (const float*)d_in[11];
    const float* beta2 = (const float*)d_in[12];
    const float* W1    = (const float*)d_in[13];
    const float* bf1   = (const float*)d_in[14];
    const float* W2    = (const float*)d_in[15];
    const float* bf2   = (const float*)d_in[16];
    float* out = (float*)d_out;

    static bool attr_done = false;
    if (!attr_done) {
        cudaFuncSetAttribute(gemm_kernel<0>, cudaFuncAttributeMaxDynamicSharedMemorySize, GEMM_SMEM);
        cudaFuncSetAttribute(gemm_kernel<2>, cudaFuncAttributeMaxDynamicSharedMemorySize, GEMM_SMEM);
        cudaFuncSetAttribute(gemm_kernel<3>, cudaFuncAttributeMaxDynamicSharedMemorySize, GEMM_SMEM);
        attr_done = true;
    }

    __nv_bfloat16 *ta, *ha, *wqkv, *wo, *w1, *w2;
    float *q_, *k_, *v_, *kv_, *ks_, *bqkv_;
    cudaGetSymbolAddress((void**)&ta, g_ta);     cudaGetSymbolAddress((void**)&ha, g_ha);
    cudaGetSymbolAddress((void**)&q_, g_q);      cudaGetSymbolAddress((void**)&k_, g_k);
    cudaGetSymbolAddress((void**)&v_, g_v);
    cudaGetSymbolAddress((void**)&kv_, g_kv);    cudaGetSymbolAddress((void**)&ks_, g_ks);
    cudaGetSymbolAddress((void**)&wqkv, g_wqkv); cudaGetSymbolAddress((void**)&wo, g_wo);
    cudaGetSymbolAddress((void**)&w1, g_w1);     cudaGetSymbolAddress((void**)&w2, g_w2);
    cudaGetSymbolAddress((void**)&bqkv_, g_bqkv);

    // 0. all weight prep in ONE launch
    wsplit_all_kernel<<<3075, 256>>>(Wq, Wk, Wv, Wo, W1, W2, bq, bk, bv);

    // 1. pre: x -> t (tiled bf16 split)
    pre_kernel<<<NTOK, 256>>>(x, g1, beta1, ta);

    // 2. fused QKV projection
    dim3 gQKV(6, NTOK / 128);
    gemm_kernel<3><<<gQKV, 256, GEMM_SMEM>>>(ta, wqkv, bqkv_, q_, k_, v_, nullptr, 8, 768);

    // 3. linear attention
    kv_reduce_kernel<<<B_ * J_ * H_, 256>>>(k_, v_, kv_, ks_);
    attn_apply_kernel<<<B_ * J_ * H_, 256>>>(q_, kv_, ks_, ta);   // y -> ta (tiled)

    // 4. output projection: o = y @ Wo + bo -> q_ (fp32)  [launch 5: ncu target]
    dim3 gD(2, NTOK / 128);
    gemm_kernel<0><<<gD, 256, GEMM_SMEM>>>(ta, wo, bo, q_, nullptr, nullptr, nullptr, 8, D_);

    // 5. Lorentz residual + LN2 -> ta (tiled u2)
    resid_kernel<<<NTOK, 256>>>(x, q_, g2, beta2, ta);

    // 6. FFN
    dim3 gH(8, NTOK / 128);
    gemm_kernel<2><<<gH, 256, GEMM_SMEM>>>(ta, w1, bf1, nullptr, nullptr, nullptr, ha, 8, HID_);
    gemm_kernel<0><<<gD, 256, GEMM_SMEM>>>(ha, w2, bf2, q_, nullptr, nullptr, nullptr, 32, D_);

    // 7. final expmap0 -> out
    final_kernel<<<NTOK, 256>>>(q_, out);
}

// round 9
// speedup vs baseline: 1.3270x; 1.0012x over previous
#include <cuda_runtime.h>
#include <cuda_bf16.h>
#include <math.h>
#include <stdint.h>

#define B_ 8
#define T_ 512
#define J_ 26
#define D_ 256
#define H_ 8
#define DH_ 32
#define HID_ 1024
#define NTOK 106496            // B*T*J  (= 832 * 128 exactly)
#define EPSF 1e-6f

// ================= PTX helpers (base ISA: sm_90 bulk-async, sm_80 mma) =================
__device__ __forceinline__ uint32_t smem_u32(const void* p) {
    uint32_t a;
    asm("{ .reg .u64 t; cvta.to.shared.u64 t, %1; cvt.u32.u64 %0, t; }" : "=r"(a) : "l"(p));
    return a;
}
#define MBAR_INIT(addr, cnt) \
    asm volatile("mbarrier.init.shared.b64 [%0], %1;" :: "r"(addr), "r"(cnt) : "memory")
#define MBAR_EXPECT_TX(addr, bytes) \
    asm volatile("mbarrier.arrive.expect_tx.shared.b64 _, [%0], %1;" :: "r"(addr), "r"(bytes) : "memory")
#define MBAR_WAIT(addr, phase) do { \
    uint32_t _m = (addr), _p = (phase); \
    asm volatile("{\n\t.reg .pred P;\n\tWL_%=:\n\t" \
        "mbarrier.try_wait.parity.acquire.cta.shared::cta.b64 P, [%0], %1, 0x989680;\n\t" \
        "@P bra.uni WD_%=;\n\tbra.uni WL_%=;\n\tWD_%=:\n\t}" :: "r"(_m), "r"(_p) : "memory"); \
} while (0)
#define CP_BULK(dst, src, bytes, mbar) \
    asm volatile("cp.async.bulk.shared::cluster.global.mbarrier::complete_tx::bytes [%0], [%1], %2, [%3];" \
        :: "r"(dst), "l"(src), "r"(bytes), "r"(mbar) : "memory")

#define LDSM4(r0, r1, r2, r3, addr) \
    asm volatile("ldmatrix.sync.aligned.m8n8.x4.shared.b16 {%0,%1,%2,%3}, [%4];" \
        : "=r"(r0), "=r"(r1), "=r"(r2), "=r"(r3) : "r"(addr))

__device__ __forceinline__ void mma16816(float* c, const uint32_t* a, const uint32_t* b) {
    asm volatile(
        "mma.sync.aligned.m16n8k16.row.col.f32.bf16.bf16.f32 "
        "{%0,%1,%2,%3}, {%4,%5,%6,%7}, {%8,%9}, {%0,%1,%2,%3};"
        : "+f"(c[0]), "+f"(c[1]), "+f"(c[2]), "+f"(c[3])
        : "r"(a[0]), "r"(a[1]), "r"(a[2]), "r"(a[3]), "r"(b[0]), "r"(b[1]));
}

// ============ tiled layout: [mtile][ktile][hi|lo][128x32 swizzled] ============
// tile = 128 rows x 32 cols bf16 = 4096 elems = 8192 B; hi+lo pair = 16384 B.
// within tile: elem(r, c) = r*32 + ((cc ^ ((r>>1)&3))<<3) + (c&7), cc = (c>>3)&3
// -> 64B rows; ldmatrix 8-row phases hit all 32 banks exactly once (conflict-free).
__device__ __forceinline__ size_t tiled_idx(int row, int col, int wKt) {
    int mt = row >> 7, r = row & 127, kt = col >> 5, c = col & 31;
    return ((size_t)(mt * wKt + kt) * 2) * 4096 + (size_t)(r * 32)
         + (size_t)(((((c >> 3) & 3) ^ ((r >> 1) & 3)) << 3) + (c & 7));
}

// ================= scratch (static device .bss) =================
__device__ __nv_bfloat16 g_ta [(size_t)NTOK * D_ * 2];    // t / y / u2, tiled hi|lo, wKt=8
__device__ __nv_bfloat16 g_ha [(size_t)NTOK * HID_ * 2];  // FFN hidden, tiled hi|lo, wKt=32
__device__ float         g_q  [(size_t)NTOK * D_];        // pq / o / f
__device__ float         g_k  [(size_t)NTOK * D_];        // pk
__device__ float         g_v  [(size_t)NTOK * D_];        // v
__device__ float g_kv [(size_t)B_ * J_ * H_ * DH_ * DH_];
__device__ float g_ks [(size_t)B_ * J_ * H_ * DH_];
// weights, tiled hi|lo (B operand: rows = output col n, cols = k)
__device__ __nv_bfloat16 g_wqkv[768 * D_ * 2];      // 6 ntiles, wKt=8
__device__ __nv_bfloat16 g_wo  [D_ * D_ * 2];       // 2 ntiles, wKt=8
__device__ __nv_bfloat16 g_w1  [HID_ * D_ * 2];     // 8 ntiles, wKt=8
__device__ __nv_bfloat16 g_w2  [D_ * HID_ * 2];     // 2 ntiles, wKt=32
__device__ float g_bqkv[768];

// ================= small helpers =================
__device__ __forceinline__ float block_reduce_sum(float v, float* sbuf) {
    int lane = threadIdx.x & 31, w = threadIdx.x >> 5;
    #pragma unroll
    for (int o = 16; o; o >>= 1) v += __shfl_down_sync(0xffffffffu, v, o);
    if (lane == 0) sbuf[w] = v;
    __syncthreads();
    float r = (threadIdx.x < 8) ? sbuf[threadIdx.x] : 0.f;
    if (w == 0) {
        r += __shfl_down_sync(0xffffffffu, r, 4);
        r += __shfl_down_sync(0xffffffffu, r, 2);
        r += __shfl_down_sync(0xffffffffu, r, 1);
        if (lane == 0) sbuf[0] = r;
    }
    __syncthreads();
    float res = sbuf[0];
    __syncthreads();
    return res;
}
// split fp32 -> bf16 hi/lo and store into tiled array (hi at idx, lo at idx+4096)
__device__ __forceinline__ void split_store_tiled(__nv_bfloat16* base, int row, int col,
                                                  int wKt, float v) {
    size_t idx = tiled_idx(row, col, wKt);
    __nv_bfloat16 h = __float2bfloat16(v);
    base[idx] = h;
    base[idx + 4096] = __float2bfloat16(v - __bfloat162float(h));
}

// ============ weight prep: transpose + split + tile, one launch ============
__global__ void wsplit_all_kernel(const float* __restrict__ Wq, const float* __restrict__ Wk,
                                  const float* __restrict__ Wv, const float* __restrict__ Wo,
                                  const float* __restrict__ W1, const float* __restrict__ W2,
                                  const float* __restrict__ bq, const float* __restrict__ bk,
                                  const float* __restrict__ bv) {
    int idx = blockIdx.x * 256 + threadIdx.x;
    if (idx < 196608) {                       // Wq, Wk, Wv [k,n] -> fused rows n' = wsel*256+n
        int wsel = idx >> 16;
        int local = idx & 65535;
        const float* W = (wsel == 0) ? Wq : (wsel == 1) ? Wk : Wv;
        int k = local >> 8, n = local & 255;
        split_store_tiled(g_wqkv, wsel * 256 + n, k, 8, W[local]);
    } else if (idx < 262144) {                // Wo [k,n]
        int local = idx - 196608;
        int k = local >> 8, n = local & 255;
        split_store_tiled(g_wo, n, k, 8, Wo[local]);
    } else if (idx < 524288) {                // W1 [k (256), n (1024)]
        int local = idx - 262144;
        int k = local >> 10, n = local & 1023;
        split_store_tiled(g_w1, n, k, 8, W1[local]);
    } else if (idx < 786432) {                // W2 [k (1024), n (256)]
        int local = idx - 524288;
        int k = local >> 8, n = local & 255;
        split_store_tiled(g_w2, n, k, 32, W2[local]);
    } else if (idx < 787200) {
        int bi = idx - 786432;
        g_bqkv[bi] = (bi < 256) ? bq[bi] : (bi < 512) ? bk[bi - 256] : bv[bi - 512];
    }
}

// ============ K1: t = layernorm(logmap0(x)) -> tiled bf16 hi/lo ============
// (expmap0 -> logmap0 round-trip in the reference is the identity; skipped)
__global__ void pre_kernel(const float* __restrict__ x,
                           const float* __restrict__ g1,
                           const float* __restrict__ b1,
                           __nv_bfloat16* __restrict__ ta) {
    __shared__ float sbuf[32];
    int row = blockIdx.x, i = threadIdx.x;
    const float* xr = x + (size_t)row * (D_ + 1);
    float xi = xr[1 + i];
    float ss = block_reduce_sum(xi * xi, sbuf);
    float n  = fmaxf(sqrtf(ss), EPSF);
    float x0 = fmaxf(xr[0], 1.0f + 1e-7f);
    float u  = acoshf(x0) * xi / n;
    float s1 = block_reduce_sum(u, sbuf);
    float s2 = block_reduce_sum(u * u, sbuf);
    float mean = s1 * (1.f / D_);
    float var  = s2 * (1.f / D_) - mean * mean;
    float tv = (u - mean) * rsqrtf(var + 1e-5f) * g1[i] + b1[i];
    split_store_tiled(ta, row, i, 8, tv);
}

// ============ HMMA split-bf16 GEMM, bulk-async staged =================
// MODE 0: fp32 out, no act.  MODE 2: tiled bf16 hi/lo out, gelu.
// MODE 3: fused QKV (route by nBase, elu for Q/K), fp32 out.
// Stage smem: A pair 16KB | B pair 16KB; double buffered. mbars at sb+0, sb+8.
#define STAGE_DATA 32768
#define GEMM_SMEM (64 + 2 * STAGE_DATA)   // 65600 B -> 2 CTAs/SM

template<int MODE>
__global__ __launch_bounds__(256) void gemm_kernel(
    const __nv_bfloat16* __restrict__ A,     // tiled, wKt = nkt
    const __nv_bfloat16* __restrict__ Bw,    // tiled, wKt = nkt
    const float* __restrict__ bias,
    float* __restrict__ Cf, float* __restrict__ Cf2, float* __restrict__ Cf3,
    __nv_bfloat16* __restrict__ Ct,          // tiled out (MODE 2)
    int nkt, int NC)
{
    extern __shared__ char smem[];
    const uint32_t sb = smem_u32(smem);
    const int tid  = threadIdx.x;
    const int lane = tid & 31;
    const int w    = tid >> 5;
    const int mTile = blockIdx.y;
    const int nTile = blockIdx.x;
    const int mBase = mTile * 128;
    const int nBase = nTile * 128;
    const int wm = (w & 3) * 32;
    const int wn = (w >> 2) * 64;

    if (tid == 0) { MBAR_INIT(sb, 1); MBAR_INIT(sb + 8, 1); }
    __syncthreads();

    const char* Ab = (const char*)A + (size_t)mTile * nkt * 16384;
    const char* Bb = (const char*)Bw + (size_t)nTile * nkt * 16384;

    if (tid == 0) {
        MBAR_EXPECT_TX(sb, 32768);
        CP_BULK(sb + 64,          Ab, 16384u, sb);
        CP_BULK(sb + 64 + 16384,  Bb, 16384u, sb);
    }

    float acc[2][8][4];
    #pragma unroll
    for (int mt = 0; mt < 2; mt++)
        #pragma unroll
        for (int nt = 0; nt < 8; nt++)
            #pragma unroll
            for (int i = 0; i < 4; i++) acc[mt][nt][i] = 0.f;

    const int aRow = lane & 15;
    const int aSel = lane >> 4;

    for (int kt = 0; kt < nkt; kt++) {
        int s = kt & 1;
        if (tid == 0 && kt + 1 < nkt) {        // prefetch next stage into other slot
            uint32_t mb2 = sb + (uint32_t)(s ^ 1) * 8;
            uint32_t d2  = sb + 64 + (uint32_t)(s ^ 1) * STAGE_DATA;
            MBAR_EXPECT_TX(mb2, 32768);
            CP_BULK(d2,         Ab + (size_t)(kt + 1) * 16384, 16384u, mb2);
            CP_BULK(d2 + 16384, Bb + (size_t)(kt + 1) * 16384, 16384u, mb2);
        }
        MBAR_WAIT(sb + (uint32_t)s * 8, (kt >> 1) & 1);

        uint32_t sbase = sb + 64 + (uint32_t)s * STAGE_DATA;
        uint32_t aHb = sbase;
        uint32_t aLb = sbase + 8192;
        uint32_t bHb = sbase + 16384;
        uint32_t bLb = sbase + 24576;

        #pragma unroll
        for (int kk = 0; kk < 2; kk++) {
            uint32_t bH[8][2], bL[8][2];
            #pragma unroll
            for (int p = 0; p < 4; p++) {
                int row = wn + p * 16 + (lane & 15);
                int cc  = 2 * kk + (lane >> 4);
                uint32_t off = (uint32_t)(row * 64 + ((cc ^ ((row >> 1) & 3)) << 4));
                uint32_t q0, q1, q2, q3;
                LDSM4(q0, q1, q2, q3, bHb + off);
                bH[2*p][0] = q0; bH[2*p+1][0] = q1; bH[2*p][1] = q2; bH[2*p+1][1] = q3;
                LDSM4(q0, q1, q2, q3, bLb + off);
                bL[2*p][0] = q0; bL[2*p+1][0] = q1; bL[2*p][1] = q2; bL[2*p+1][1] = q3;
            }
            #pragma unroll
            for (int mt = 0; mt < 2; mt++) {
                int row = wm + mt * 16 + aRow;
                int cc  = 2 * kk + aSel;
                uint32_t off = (uint32_t)(row * 64 + ((cc ^ ((row >> 1) & 3)) << 4));
                uint32_t aH[4], aL[4];
                LDSM4(aH[0], aH[1], aH[2], aH[3], aHb + off);
                LDSM4(aL[0], aL[1], aL[2], aL[3], aLb + off);
                #pragma unroll
                for (int nt = 0; nt < 8; nt++) {
                    mma16816(acc[mt][nt], aH, bH[nt]);   // Ah * Bh
                    mma16816(acc[mt][nt], aL, bH[nt]);   // Al * Bh
                    mma16816(acc[mt][nt], aH, bL[nt]);   // Ah * Bl
                }
            }
        }
        __syncthreads();   // all warps done with slot s -> safe to refill at iter kt+2
    }

    // ---------------- epilogue ----------------
    const int gid = lane >> 2;
    const int tig = lane & 3;
    int which = 0; float* dstQKV = Cf; bool eluAct = false; int nLoc = nBase;
    if (MODE == 3) {
        which = nBase >> 8;
        dstQKV = (which == 0) ? Cf : (which == 1) ? Cf2 : Cf3;
        eluAct = (which < 2);
        nLoc = nBase - which * 256;
    }
    #pragma unroll
    for (int mt = 0; mt < 2; mt++) {
        #pragma unroll
        for (int nt = 0; nt < 8; nt++) {
            int colT = wn + nt * 8 + tig * 2;
            float b0 = bias[nBase + colT], b1 = bias[nBase + colT + 1];
            #pragma unroll
            for (int half = 0; half < 2; half++) {
                int row = mBase + wm + mt * 16 + gid + half * 8;
                float v0 = acc[mt][nt][half * 2 + 0] + b0;
                float v1 = acc[mt][nt][half * 2 + 1] + b1;
                if (MODE == 3 && eluAct) {
                    v0 = (v0 > 0.f) ? (v0 + 1.f) : __expf(v0);
                    v1 = (v1 > 0.f) ? (v1 + 1.f) : __expf(v1);
                } else if (MODE == 2) {
                    float c0 = v0 * v0 * v0;
                    v0 = 0.5f * v0 * (1.f + tanhf(0.7978845608028654f * (v0 + 0.044715f * c0)));
                    float c1 = v1 * v1 * v1;
                    v1 = 0.5f * v1 * (1.f + tanhf(0.7978845608028654f * (v1 + 0.044715f * c1)));
                }
                if (MODE == 2) {
                    // tiled bf16 hi/lo out; col pair lies in one 16B chunk
                    size_t idx = tiled_idx(row, nBase + colT, NC >> 5);
                    __nv_bfloat16 h0 = __float2bfloat16(v0);
                    __nv_bfloat16 h1 = __float2bfloat16(v1);
                    __nv_bfloat16 l0 = __float2bfloat16(v0 - __bfloat162float(h0));
                    __nv_bfloat16 l1 = __float2bfloat16(v1 - __bfloat162float(h1));
                    uint32_t hp = ((uint32_t)__bfloat16_as_ushort(h1) << 16) | __bfloat16_as_ushort(h0);
                    uint32_t lp = ((uint32_t)__bfloat16_as_ushort(l1) << 16) | __bfloat16_as_ushort(l0);
                    *reinterpret_cast<uint32_t*>(Ct + idx) = hp;
                    *reinterpret_cast<uint32_t*>(Ct + idx + 4096) = lp;
                } else if (MODE == 3) {
                    size_t base = (size_t)row * 256 + nLoc + colT;
                    *reinterpret_cast<float2*>(dstQKV + base) = make_float2(v0, v1);
                } else {
                    size_t base = (size_t)row * NC + nBase + colT;
                    *reinterpret_cast<float2*>(Cf + base) = make_float2(v0, v1);
                }
            }
        }
    }
}

// ============ K3: kv / ksum reduction over T ============
__global__ void kv_reduce_kernel(const float* __restrict__ pk,
                                 const float* __restrict__ v,
                                 float* __restrict__ kv,
                                 float* __restrict__ ksum) {
    int bh = blockIdx.x;
    int h  = bh % H_;
    int bj = bh / H_;
    int j  = bj % J_;
    int b  = bj / J_;
    int tid = threadIdx.x;
    int lane = tid & 31, w = tid >> 5;
    __shared__ float sp[4][32];
    __shared__ float sv[4][32];
    float acc[4] = {0.f, 0.f, 0.f, 0.f};
    float ks = 0.f;
    int tl = tid >> 6;
    int e  = tid & 63;
    for (int t0 = 0; t0 < T_; t0 += 4) {
        int t = t0 + tl;
        size_t base = (((size_t)(b * T_ + t) * J_) + j) * D_ + h * DH_;
        float val = (e < 32) ? pk[base + e] : v[base + e - 32];
        __syncthreads();
        if (e < 32) sp[tl][e] = val; else sv[tl][e - 32] = val;
        __syncthreads();
        #pragma unroll
        for (int tt = 0; tt < 4; tt++) {
            float vv = sv[tt][lane];
            #pragma unroll
            for (int c = 0; c < 4; c++)
                acc[c] += sp[tt][w + c * 8] * vv;
            if (w == 0) ks += sp[tt][lane];
        }
    }
    size_t ob = (size_t)bh * (DH_ * DH_);
    #pragma unroll
    for (int c = 0; c < 4; c++)
        kv[ob + (size_t)(w + c * 8) * 32 + lane] = acc[c];
    if (w == 0) ksum[(size_t)bh * 32 + lane] = ks;
}

// ============ K4: y = (pq @ kv) / (pq . ksum + EPS) -> tiled bf16 hi/lo ============
__global__ void attn_apply_kernel(const float* __restrict__ pq,
                                  const float* __restrict__ kv,
                                  const float* __restrict__ ksum,
                                  __nv_bfloat16* __restrict__ ya) {
    int bh = blockIdx.x;
    int h  = bh % H_;
    int bj = bh / H_;
    int j  = bj % J_;
    int b  = bj / J_;
    __shared__ float skv[DH_ * DH_];
    __shared__ float sks[DH_];
    int tid = threadIdx.x;
    for (int i = tid; i < DH_ * DH_; i += 256) skv[i] = kv[(size_t)bh * (DH_ * DH_) + i];
    if (tid < DH_) sks[tid] = ksum[(size_t)bh * DH_ + tid];
    __syncthreads();
    int lane = tid & 31, w = tid >> 5;
    for (int t = w; t < T_; t += 8) {
        int token = (b * T_ + t) * J_ + j;
        size_t baseQ = (size_t)token * D_ + h * DH_;
        float q = pq[baseQ + lane];
        float den = q * sks[lane];
        #pragma unroll
        for (int o = 16; o; o >>= 1) den += __shfl_xor_sync(0xffffffffu, den, o);
        float num = 0.f;
        #pragma unroll
        for (int k = 0; k < 32; k++)
            num += __shfl_sync(0xffffffffu, q, k) * skv[k * 32 + lane];
        split_store_tiled(ya, token, h * DH_ + lane, 8, num / (den + EPSF));
    }
}

// ============ K5: residual + LN2 -> tiled bf16 hi/lo ============
__global__ void resid_kernel(const float* __restrict__ x,
                             const float* __restrict__ o_in,
                             const float* __restrict__ g2,
                             const float* __restrict__ b2,
                             __nv_bfloat16* __restrict__ ua) {
    __shared__ float sbuf[32];
    int row = blockIdx.x, i = threadIdx.x;
    const float* xr = x + (size_t)row * (D_ + 1);
    float o = o_in[(size_t)row * D_ + i];
    float so = block_reduce_sum(o * o, sbuf);
    float n  = fmaxf(sqrtf(so), EPSF);
    float z  = sinhf(n) * o / n;
    float m  = xr[1 + i] + z;
    float sm = block_reduce_sum(m * m, sbuf);
    float m0 = xr[0] + coshf(n);
    float mink = -m0 * m0 + sm;
    float inv  = rsqrtf(fmaxf(-mink, EPSF));
    float h0   = m0 * inv;
    float hs   = m * inv;
    float hn   = fmaxf(sqrtf(sm) * inv, EPSF);
    float u    = acoshf(fmaxf(h0, 1.0f + 1e-7f)) * hs / hn;
    float s1 = block_reduce_sum(u, sbuf);
    float s2 = block_reduce_sum(u * u, sbuf);
    float mean = s1 * (1.f / D_);
    float var  = s2 * (1.f / D_) - mean * mean;
    float uv = (u - mean) * rsqrtf(var + 1e-5f) * g2[i] + b2[i];
    split_store_tiled(ua, row, i, 8, uv);
}

// ============ K6: out = expmap0(f) ============
__global__ void final_kernel(const float* __restrict__ f_in,
                             float* __restrict__ out) {
    __shared__ float sbuf[32];
    int row = blockIdx.x, i = threadIdx.x;
    float f = f_in[(size_t)row * D_ + i];
    float ss = block_reduce_sum(f * f, sbuf);
    float n  = fmaxf(sqrtf(ss), EPSF);
    float* orow = out + (size_t)row * (D_ + 1);
    orow[1 + i] = sinhf(n) * f / n;
    if (i == 0) orow[0] = coshf(n);
}

// ================= launch =================
extern "C" void kernel_launch(void* const* d_in, const int* /*in_sizes*/, int /*n_in*/,
                              void* d_out, int /*out_size*/) {
    const float* x     = (const float*)d_in[0];
    const float* g1    = (const float*)d_in[1];
    const float* beta1 = (const float*)d_in[2];
    const float* Wq    = (const float*)d_in[3];
    const float* Wk    = (const float*)d_in[4];
    const float* Wv    = (const float*)d_in[5];
    const float* Wo    = (const float*)d_in[6];
    const float* bq    = (const float*)d_in[7];
    const float* bk    = (const float*)d_in[8];
    const float* bv    = (const float*)d_in[9];
    const float* bo    = (const float*)d_in[10];
    const float* g2    = (const float*)d_in[11];
    const float* beta2 = (const float*)d_in[12];
    const float* W1    = (const float*)d_in[13];
    const float* bf1   = (const float*)d_in[14];
    const float* W2    = (const float*)d_in[15];
    const float* bf2   = (const float*)d_in[16];
    float* out = (float*)d_out;

    static bool attr_done = false;
    if (!attr_done) {
        cudaFuncSetAttribute(gemm_kernel<0>, cudaFuncAttributeMaxDynamicSharedMemorySize, GEMM_SMEM);
        cudaFuncSetAttribute(gemm_kernel<2>, cudaFuncAttributeMaxDynamicSharedMemorySize, GEMM_SMEM);
        cudaFuncSetAttribute(gemm_kernel<3>, cudaFuncAttributeMaxDynamicSharedMemorySize, GEMM_SMEM);
        attr_done = true;
    }

    __nv_bfloat16 *ta, *ha, *wqkv, *wo, *w1, *w2;
    float *q_, *k_, *v_, *kv_, *ks_, *bqkv_;
    cudaGetSymbolAddress((void**)&ta, g_ta);     cudaGetSymbolAddress((void**)&ha, g_ha);
    cudaGetSymbolAddress((void**)&q_, g_q);      cudaGetSymbolAddress((void**)&k_, g_k);
    cudaGetSymbolAddress((void**)&v_, g_v);
    cudaGetSymbolAddress((void**)&kv_, g_kv);    cudaGetSymbolAddress((void**)&ks_, g_ks);
    cudaGetSymbolAddress((void**)&wqkv, g_wqkv); cudaGetSymbolAddress((void**)&wo, g_wo);
    cudaGetSymbolAddress((void**)&w1, g_w1);     cudaGetSymbolAddress((void**)&w2, g_w2);
    cudaGetSymbolAddress((void**)&bqkv_, g_bqkv);

    // 0. all weight prep in ONE launch
    wsplit_all_kernel<<<3075, 256>>>(Wq, Wk, Wv, Wo, W1, W2, bq, bk, bv);

    // 1. pre: x -> t (tiled bf16 split)
    pre_kernel<<<NTOK, 256>>>(x, g1, beta1, ta);

    // 2. fused QKV projection
    dim3 gQKV(6, NTOK / 128);
    gemm_kernel<3><<<gQKV, 256, GEMM_SMEM>>>(ta, wqkv, bqkv_, q_, k_, v_, nullptr, 8, 768);

    // 3. linear attention
    kv_reduce_kernel<<<B_ * J_ * H_, 256>>>(k_, v_, kv_, ks_);
    attn_apply_kernel<<<B_ * J_ * H_, 256>>>(q_, kv_, ks_, ta);   // y -> ta (tiled)

    // 4. output projection: o = y @ Wo + bo -> q_ (fp32)  [launch 5: ncu target]
    dim3 gD(2, NTOK / 128);
    gemm_kernel<0><<<gD, 256, GEMM_SMEM>>>(ta, wo, bo, q_, nullptr, nullptr, nullptr, 8, D_);

    // 5. Lorentz residual + LN2 -> ta (tiled u2)
    resid_kernel<<<NTOK, 256>>>(x, q_, g2, beta2, ta);

    // 6. FFN
    dim3 gH(8, NTOK / 128);
    gemm_kernel<2><<<gH, 256, GEMM_SMEM>>>(ta, w1, bf1, nullptr, nullptr, nullptr, ha, 8, HID_);
    gemm_kernel<0><<<gD, 256, GEMM_SMEM>>>(ha, w2, bf2, q_, nullptr, nullptr, nullptr, 32, D_);

    // 7. final expmap0 -> out
    final_kernel<<<NTOK, 256>>>(q_, out);
}

// round 10
// speedup vs baseline: 1.3702x; 1.0325x over previous
#include <cuda_runtime.h>
#include <cuda_bf16.h>
#include <math.h>
#include <stdint.h>

#define B_ 8
#define T_ 512
#define J_ 26
#define D_ 256
#define H_ 8
#define DH_ 32
#define HID_ 1024
#define NTOK 106496            // B*T*J  (= 832 * 128 exactly)
#define EPSF 1e-6f

// ================= PTX helpers (base ISA: sm_90 bulk-async, sm_80 mma) =================
__device__ __forceinline__ uint32_t smem_u32(const void* p) {
    uint32_t a;
    asm("{ .reg .u64 t; cvta.to.shared.u64 t, %1; cvt.u32.u64 %0, t; }" : "=r"(a) : "l"(p));
    return a;
}
#define MBAR_INIT(addr, cnt) \
    asm volatile("mbarrier.init.shared.b64 [%0], %1;" :: "r"(addr), "r"(cnt) : "memory")
#define MBAR_EXPECT_TX(addr, bytes) \
    asm volatile("mbarrier.arrive.expect_tx.shared.b64 _, [%0], %1;" :: "r"(addr), "r"(bytes) : "memory")
#define MBAR_WAIT(addr, phase) do { \
    uint32_t _m = (addr), _p = (phase); \
    asm volatile("{\n\t.reg .pred P;\n\tWL_%=:\n\t" \
        "mbarrier.try_wait.parity.acquire.cta.shared::cta.b64 P, [%0], %1, 0x989680;\n\t" \
        "@P bra.uni WD_%=;\n\tbra.uni WL_%=;\n\tWD_%=:\n\t}" :: "r"(_m), "r"(_p) : "memory"); \
} while (0)
#define CP_BULK(dst, src, bytes, mbar) \
    asm volatile("cp.async.bulk.shared::cluster.global.mbarrier::complete_tx::bytes [%0], [%1], %2, [%3];" \
        :: "r"(dst), "l"(src), "r"(bytes), "r"(mbar) : "memory")

#define LDSM4(r0, r1, r2, r3, addr) \
    asm volatile("ldmatrix.sync.aligned.m8n8.x4.shared.b16 {%0,%1,%2,%3}, [%4];" \
        : "=r"(r0), "=r"(r1), "=r"(r2), "=r"(r3) : "r"(addr))

__device__ __forceinline__ void mma16816(float* c, const uint32_t* a, const uint32_t* b) {
    asm volatile(
        "mma.sync.aligned.m16n8k16.row.col.f32.bf16.bf16.f32 "
        "{%0,%1,%2,%3}, {%4,%5,%6,%7}, {%8,%9}, {%0,%1,%2,%3};"
        : "+f"(c[0]), "+f"(c[1]), "+f"(c[2]), "+f"(c[3])
        : "r"(a[0]), "r"(a[1]), "r"(a[2]), "r"(a[3]), "r"(b[0]), "r"(b[1]));
}

// ============ tiled layout: [mtile][ktile][hi|lo][128x32 swizzled] ============
// tile = 128 rows x 32 cols bf16 = 8192 B; hi+lo pair = 16384 B.
// elem(r, c) -> r*32 + ((cc ^ ((r>>1)&3))<<3) + (c&7), cc = (c>>3)&3
__device__ __forceinline__ size_t tiled_idx(int row, int col, int wKt) {
    int mt = row >> 7, r = row & 127, kt = col >> 5, c = col & 31;
    return ((size_t)(mt * wKt + kt) * 2) * 4096 + (size_t)(r * 32)
         + (size_t)(((((c >> 3) & 3) ^ ((r >> 1) & 3)) << 3) + (c & 7));
}

// ================= scratch (static device .bss) =================
__device__ __nv_bfloat16 g_ta [(size_t)NTOK * D_ * 2];    // t / y / u2, tiled hi|lo, wKt=8
__device__ __nv_bfloat16 g_ha [(size_t)NTOK * HID_ * 2];  // FFN hidden, tiled hi|lo, wKt=32
__device__ float         g_q  [(size_t)NTOK * D_];        // pq / o / f
__device__ float         g_k  [(size_t)NTOK * D_];        // pk
__device__ float         g_v  [(size_t)NTOK * D_];        // v
__device__ float g_kv [(size_t)B_ * J_ * H_ * DH_ * DH_];
__device__ float g_ks [(size_t)B_ * J_ * H_ * DH_];
// weights, tiled hi|lo (B operand: rows = output col n, cols = k)
__device__ __nv_bfloat16 g_wqkv[768 * D_ * 2];      // 6 ntiles, wKt=8
__device__ __nv_bfloat16 g_wo  [D_ * D_ * 2];       // 2 ntiles, wKt=8
__device__ __nv_bfloat16 g_w1  [HID_ * D_ * 2];     // 8 ntiles, wKt=8
__device__ __nv_bfloat16 g_w2  [D_ * HID_ * 2];     // 2 ntiles, wKt=32
__device__ float g_bqkv[768];

// ================= small helpers =================
__device__ __forceinline__ float block_reduce_sum(float v, float* sbuf) {
    int lane = threadIdx.x & 31, w = threadIdx.x >> 5;
    #pragma unroll
    for (int o = 16; o; o >>= 1) v += __shfl_down_sync(0xffffffffu, v, o);
    if (lane == 0) sbuf[w] = v;
    __syncthreads();
    float r = (threadIdx.x < 8) ? sbuf[threadIdx.x] : 0.f;
    if (w == 0) {
        r += __shfl_down_sync(0xffffffffu, r, 4);
        r += __shfl_down_sync(0xffffffffu, r, 2);
        r += __shfl_down_sync(0xffffffffu, r, 1);
        if (lane == 0) sbuf[0] = r;
    }
    __syncthreads();
    float res = sbuf[0];
    __syncthreads();
    return res;
}
__device__ __forceinline__ void split_store_tiled(__nv_bfloat16* base, int row, int col,
                                                  int wKt, float v) {
    size_t idx = tiled_idx(row, col, wKt);
    __nv_bfloat16 h = __float2bfloat16(v);
    base[idx] = h;
    base[idx + 4096] = __float2bfloat16(v - __bfloat162float(h));
}

// ============ weight prep: transpose + split + tile, one launch ============
__global__ void wsplit_all_kernel(const float* __restrict__ Wq, const float* __restrict__ Wk,
                                  const float* __restrict__ Wv, const float* __restrict__ Wo,
                                  const float* __restrict__ W1, const float* __restrict__ W2,
                                  const float* __restrict__ bq, const float* __restrict__ bk,
                                  const float* __restrict__ bv) {
    int idx = blockIdx.x * 256 + threadIdx.x;
    if (idx < 196608) {
        int wsel = idx >> 16;
        int local = idx & 65535;
        const float* W = (wsel == 0) ? Wq : (wsel == 1) ? Wk : Wv;
        int k = local >> 8, n = local & 255;
        split_store_tiled(g_wqkv, wsel * 256 + n, k, 8, W[local]);
    } else if (idx < 262144) {
        int local = idx - 196608;
        int k = local >> 8, n = local & 255;
        split_store_tiled(g_wo, n, k, 8, Wo[local]);
    } else if (idx < 524288) {
        int local = idx - 262144;
        int k = local >> 10, n = local & 1023;
        split_store_tiled(g_w1, n, k, 8, W1[local]);
    } else if (idx < 786432) {
        int local = idx - 524288;
        int k = local >> 8, n = local & 255;
        split_store_tiled(g_w2, n, k, 32, W2[local]);
    } else if (idx < 787200) {
        int bi = idx - 786432;
        g_bqkv[bi] = (bi < 256) ? bq[bi] : (bi < 512) ? bk[bi - 256] : bv[bi - 512];
    }
}

// ============ K1: t = layernorm(logmap0(x)) -> tiled bf16 hi/lo ============
// (expmap0 -> logmap0 round-trip in the reference is the identity; skipped)
__global__ void pre_kernel(const float* __restrict__ x,
                           const float* __restrict__ g1,
                           const float* __restrict__ b1,
                           __nv_bfloat16* __restrict__ ta) {
    __shared__ float sbuf[32];
    int row = blockIdx.x, i = threadIdx.x;
    const float* xr = x + (size_t)row * (D_ + 1);
    float xi = xr[1 + i];
    float ss = block_reduce_sum(xi * xi, sbuf);
    float n  = fmaxf(sqrtf(ss), EPSF);
    float x0 = fmaxf(xr[0], 1.0f + 1e-7f);
    float u  = acoshf(x0) * xi / n;
    float s1 = block_reduce_sum(u, sbuf);
    float s2 = block_reduce_sum(u * u, sbuf);
    float mean = s1 * (1.f / D_);
    float var  = s2 * (1.f / D_) - mean * mean;
    float tv = (u - mean) * rsqrtf(var + 1e-5f) * g1[i] + b1[i];
    split_store_tiled(ta, row, i, 8, tv);
}

// ============ HMMA split-bf16 GEMM, 3-stage bulk-async pipeline =================
// MODE 0: fp32 out, no act.  MODE 2: tiled bf16 hi/lo out, gelu.
// MODE 3: fused QKV (route by nBase, elu for Q/K), fp32 out.
#define NSTG 3
#define STAGE_DATA 32768
#define GEMM_SMEM (64 + NSTG * STAGE_DATA)   // 98368 B -> 2 CTAs/SM

template<int MODE>
__global__ __launch_bounds__(256) void gemm_kernel(
    const __nv_bfloat16* __restrict__ A,     // tiled, wKt = nkt
    const __nv_bfloat16* __restrict__ Bw,    // tiled, wKt = nkt
    const float* __restrict__ bias,
    float* __restrict__ Cf, float* __restrict__ Cf2, float* __restrict__ Cf3,
    __nv_bfloat16* __restrict__ Ct,          // tiled out (MODE 2)
    int nkt, int NC)
{
    extern __shared__ char smem[];
    const uint32_t sb = smem_u32(smem);
    const int tid  = threadIdx.x;
    const int lane = tid & 31;
    const int w    = tid >> 5;
    const int mTile = blockIdx.y;
    const int nTile = blockIdx.x;
    const int mBase = mTile * 128;
    const int nBase = nTile * 128;
    const int wm = (w & 3) * 32;
    const int wn = (w >> 2) * 64;

    if (tid == 0) { MBAR_INIT(sb, 1); MBAR_INIT(sb + 8, 1); MBAR_INIT(sb + 16, 1); }
    __syncthreads();

    const char* Ab = (const char*)A + (size_t)mTile * nkt * 16384;
    const char* Bb = (const char*)Bw + (size_t)nTile * nkt * 16384;

    auto issue = [&](int kt, int s) {
        uint32_t mb = sb + (uint32_t)s * 8;
        uint32_t d  = sb + 64 + (uint32_t)s * STAGE_DATA;
        MBAR_EXPECT_TX(mb, 32768);
        CP_BULK(d,         Ab + (size_t)kt * 16384, 16384u, mb);
        CP_BULK(d + 16384, Bb + (size_t)kt * 16384, 16384u, mb);
    };
    if (tid == 0) {
        issue(0, 0);
        if (nkt > 1) issue(1, 1);
    }

    float acc[2][8][4];
    #pragma unroll
    for (int mt = 0; mt < 2; mt++)
        #pragma unroll
        for (int nt = 0; nt < 8; nt++)
            #pragma unroll
            for (int i = 0; i < 4; i++) acc[mt][nt][i] = 0.f;

    const int aRow = lane & 15;
    const int aSel = lane >> 4;

    for (int kt = 0; kt < nkt; kt++) {
        int s = kt % NSTG;
        // prefetch kt+2 into slot (kt+2)%NSTG: for kt=0 that slot (2) is virgin;
        // for kt>=1 it is slot (kt-1)%NSTG, freed by the syncthreads ending iter kt-1.
        if (tid == 0 && kt + 2 < nkt + (kt == 0 ? 1 : 0)) {
            // kt=0: prefetch kt=2 if exists; kt>=1: prefetch kt+2 if exists
        }
        if (tid == 0) {
            int pf = kt + 2;
            if (pf < nkt && (kt == 0 || true)) {
                if (kt == 0) { if (nkt > 2) issue(2, 2); }
                else issue(pf, pf % NSTG);
            }
        }
        MBAR_WAIT(sb + (uint32_t)s * 8, (kt / NSTG) & 1);

        uint32_t sbase = sb + 64 + (uint32_t)s * STAGE_DATA;
        uint32_t aHb = sbase;
        uint32_t aLb = sbase + 8192;
        uint32_t bHb = sbase + 16384;
        uint32_t bLb = sbase + 24576;

        #pragma unroll
        for (int kk = 0; kk < 2; kk++) {
            uint32_t bH[8][2], bL[8][2];
            #pragma unroll
            for (int p = 0; p < 4; p++) {
                int row = wn + p * 16 + (lane & 15);
                int cc  = 2 * kk + (lane >> 4);
                uint32_t off = (uint32_t)(row * 64 + ((cc ^ ((row >> 1) & 3)) << 4));
                uint32_t q0, q1, q2, q3;
                LDSM4(q0, q1, q2, q3, bHb + off);
                bH[2*p][0] = q0; bH[2*p+1][0] = q1; bH[2*p][1] = q2; bH[2*p+1][1] = q3;
                LDSM4(q0, q1, q2, q3, bLb + off);
                bL[2*p][0] = q0; bL[2*p+1][0] = q1; bL[2*p][1] = q2; bL[2*p+1][1] = q3;
            }
            #pragma unroll
            for (int mt = 0; mt < 2; mt++) {
                int row = wm + mt * 16 + aRow;
                int cc  = 2 * kk + aSel;
                uint32_t off = (uint32_t)(row * 64 + ((cc ^ ((row >> 1) & 3)) << 4));
                uint32_t aH[4], aL[4];
                LDSM4(aH[0], aH[1], aH[2], aH[3], aHb + off);
                LDSM4(aL[0], aL[1], aL[2], aL[3], aLb + off);
                #pragma unroll
                for (int nt = 0; nt < 8; nt++) {
                    mma16816(acc[mt][nt], aH, bH[nt]);   // Ah * Bh
                    mma16816(acc[mt][nt], aL, bH[nt]);   // Al * Bh
                    mma16816(acc[mt][nt], aH, bL[nt]);   // Ah * Bl
                }
            }
        }
        __syncthreads();   // all warps done with slot s -> legalizes refill
    }

    // ---------------- epilogue ----------------
    const int gid = lane >> 2;
    const int tig = lane & 3;
    int which = 0; float* dstQKV = Cf; bool eluAct = false; int nLoc = nBase;
    if (MODE == 3) {
        which = nBase >> 8;
        dstQKV = (which == 0) ? Cf : (which == 1) ? Cf2 : Cf3;
        eluAct = (which < 2);
        nLoc = nBase - which * 256;
    }
    #pragma unroll
    for (int mt = 0; mt < 2; mt++) {
        #pragma unroll
        for (int nt = 0; nt < 8; nt++) {
            int colT = wn + nt * 8 + tig * 2;
            float b0 = bias[nBase + colT], b1 = bias[nBase + colT + 1];
            #pragma unroll
            for (int half = 0; half < 2; half++) {
                int row = mBase + wm + mt * 16 + gid + half * 8;
                float v0 = acc[mt][nt][half * 2 + 0] + b0;
                float v1 = acc[mt][nt][half * 2 + 1] + b1;
                if (MODE == 3 && eluAct) {
                    v0 = (v0 > 0.f) ? (v0 + 1.f) : __expf(v0);
                    v1 = (v1 > 0.f) ? (v1 + 1.f) : __expf(v1);
                } else if (MODE == 2) {
                    float c0 = v0 * v0 * v0;
                    v0 = 0.5f * v0 * (1.f + tanhf(0.7978845608028654f * (v0 + 0.044715f * c0)));
                    float c1 = v1 * v1 * v1;
                    v1 = 0.5f * v1 * (1.f + tanhf(0.7978845608028654f * (v1 + 0.044715f * c1)));
                }
                if (MODE == 2) {
                    size_t idx = tiled_idx(row, nBase + colT, NC >> 5);
                    __nv_bfloat16 h0 = __float2bfloat16(v0);
                    __nv_bfloat16 h1 = __float2bfloat16(v1);
                    __nv_bfloat16 l0 = __float2bfloat16(v0 - __bfloat162float(h0));
                    __nv_bfloat16 l1 = __float2bfloat16(v1 - __bfloat162float(h1));
                    uint32_t hp = ((uint32_t)__bfloat16_as_ushort(h1) << 16) | __bfloat16_as_ushort(h0);
                    uint32_t lp = ((uint32_t)__bfloat16_as_ushort(l1) << 16) | __bfloat16_as_ushort(l0);
                    *reinterpret_cast<uint32_t*>(Ct + idx) = hp;
                    *reinterpret_cast<uint32_t*>(Ct + idx + 4096) = lp;
                } else if (MODE == 3) {
                    size_t base = (size_t)row * 256 + nLoc + colT;
                    *reinterpret_cast<float2*>(dstQKV + base) = make_float2(v0, v1);
                } else {
                    size_t base = (size_t)row * NC + nBase + colT;
                    *reinterpret_cast<float2*>(Cf + base) = make_float2(v0, v1);
                }
            }
        }
    }
}

// ============ K3: kv / ksum via per-warp shuffle outer-product ============
__global__ void kv_reduce_kernel(const float* __restrict__ pk,
                                 const float* __restrict__ v,
                                 float* __restrict__ kv,
                                 float* __restrict__ ksum) {
    int bh = blockIdx.x;
    int h  = bh % H_;
    int bj = bh / H_;
    int j  = bj % J_;
    int b  = bj / J_;
    int tid = threadIdx.x, lane = tid & 31, w = tid >> 5;

    float acc[32];
    #pragma unroll
    for (int k = 0; k < 32; k++) acc[k] = 0.f;
    float ks = 0.f;

    for (int t = w; t < T_; t += 8) {
        size_t base = (((size_t)(b * T_ + t) * J_) + j) * D_ + h * DH_ + lane;
        float pkv = pk[base];
        float vv  = v[base];
        ks += pkv;
        #pragma unroll
        for (int k = 0; k < 32; k++)
            acc[k] += __shfl_sync(0xffffffffu, pkv, k) * vv;
    }

    __shared__ float red[8][32][32];
    __shared__ float rks[8][32];
    #pragma unroll
    for (int k = 0; k < 32; k++) red[w][k][lane] = acc[k];
    rks[w][lane] = ks;
    __syncthreads();

    #pragma unroll
    for (int kk = 0; kk < 4; kk++) {
        int k = w * 4 + kk;
        float s = 0.f;
        #pragma unroll
        for (int ww = 0; ww < 8; ww++) s += red[ww][k][lane];
        kv[(size_t)bh * (DH_ * DH_) + k * 32 + lane] = s;
    }
    if (w == 0) {
        float s = 0.f;
        #pragma unroll
        for (int ww = 0; ww < 8; ww++) s += rks[ww][lane];
        ksum[(size_t)bh * DH_ + lane] = s;
    }
}

// ============ K4: y = (pq @ kv) / (pq . ksum + EPS) -> tiled bf16 hi/lo ============
__global__ void attn_apply_kernel(const float* __restrict__ pq,
                                  const float* __restrict__ kv,
                                  const float* __restrict__ ksum,
                                  __nv_bfloat16* __restrict__ ya) {
    int bh = blockIdx.x;
    int h  = bh % H_;
    int bj = bh / H_;
    int j  = bj % J_;
    int b  = bj / J_;
    __shared__ float skv[DH_ * DH_];
    __shared__ float sks[DH_];
    int tid = threadIdx.x;
    for (int i = tid; i < DH_ * DH_; i += 256) skv[i] = kv[(size_t)bh * (DH_ * DH_) + i];
    if (tid < DH_) sks[tid] = ksum[(size_t)bh * DH_ + tid];
    __syncthreads();
    int lane = tid & 31, w = tid >> 5;
    for (int t = w; t < T_; t += 8) {
        int token = (b * T_ + t) * J_ + j;
        size_t baseQ = (size_t)token * D_ + h * DH_;
        float q = pq[baseQ + lane];
        float den = q * sks[lane];
        #pragma unroll
        for (int o = 16; o; o >>= 1) den += __shfl_xor_sync(0xffffffffu, den, o);
        float num = 0.f;
        #pragma unroll
        for (int k = 0; k < 32; k++)
            num += __shfl_sync(0xffffffffu, q, k) * skv[k * 32 + lane];
        split_store_tiled(ya, token, h * DH_ + lane, 8, num / (den + EPSF));
    }
}

// ============ K5: residual + LN2 -> tiled bf16 hi/lo ============
__global__ void resid_kernel(const float* __restrict__ x,
                             const float* __restrict__ o_in,
                             const float* __restrict__ g2,
                             const float* __restrict__ b2,
                             __nv_bfloat16* __restrict__ ua) {
    __shared__ float sbuf[32];
    int row = blockIdx.x, i = threadIdx.x;
    const float* xr = x + (size_t)row * (D_ + 1);
    float o = o_in[(size_t)row * D_ + i];
    float so = block_reduce_sum(o * o, sbuf);
    float n  = fmaxf(sqrtf(so), EPSF);
    float z  = sinhf(n) * o / n;
    float m  = xr[1 + i] + z;
    float sm = block_reduce_sum(m * m, sbuf);
    float m0 = xr[0] + coshf(n);
    float mink = -m0 * m0 + sm;
    float inv  = rsqrtf(fmaxf(-mink, EPSF));
    float h0   = m0 * inv;
    float hs   = m * inv;
    float hn   = fmaxf(sqrtf(sm) * inv, EPSF);
    float u    = acoshf(fmaxf(h0, 1.0f + 1e-7f)) * hs / hn;
    float s1 = block_reduce_sum(u, sbuf);
    float s2 = block_reduce_sum(u * u, sbuf);
    float mean = s1 * (1.f / D_);
    float var  = s2 * (1.f / D_) - mean * mean;
    float uv = (u - mean) * rsqrtf(var + 1e-5f) * g2[i] + b2[i];
    split_store_tiled(ua, row, i, 8, uv);
}

// ============ K6: out = expmap0(f) ============
__global__ void final_kernel(const float* __restrict__ f_in,
                             float* __restrict__ out) {
    __shared__ float sbuf[32];
    int row = blockIdx.x, i = threadIdx.x;
    float f = f_in[(size_t)row * D_ + i];
    float ss = block_reduce_sum(f * f, sbuf);
    float n  = fmaxf(sqrtf(ss), EPSF);
    float* orow = out + (size_t)row * (D_ + 1);
    orow[1 + i] = sinhf(n) * f / n;
    if (i == 0) orow[0] = coshf(n);
}

// ================= launch =================
extern "C" void kernel_launch(void* const* d_in, const int* /*in_sizes*/, int /*n_in*/,
                              void* d_out, int /*out_size*/) {
    const float* x     = (const float*)d_in[0];
    const float* g1    = (const float*)d_in[1];
    const float* beta1 = (const float*)d_in[2];
    const float* Wq    = (const float*)d_in[3];
    const float* Wk    = (const float*)d_in[4];
    const float* Wv    = (const float*)d_in[5];
    const float* Wo    = (const float*)d_in[6];
    const float* bq    = (const float*)d_in[7];
    const float* bk    = (const float*)d_in[8];
    const float* bv    = (const float*)d_in[9];
    const float* bo    = (const float*)d_in[10];
    const float* g2    = (const float*)d_in[11];
    const float* beta2 = (const float*)d_in[12];
    const float* W1    = (const float*)d_in[13];
    const float* bf1   = (const float*)d_in[14];
    const float* W2    = (const float*)d_in[15];
    const float* bf2   = (const float*)d_in[16];
    float* out = (float*)d_out;

    static bool attr_done = false;
    if (!attr_done) {
        cudaFuncSetAttribute(gemm_kernel<0>, cudaFuncAttributeMaxDynamicSharedMemorySize, GEMM_SMEM);
        cudaFuncSetAttribute(gemm_kernel<2>, cudaFuncAttributeMaxDynamicSharedMemorySize, GEMM_SMEM);
        cudaFuncSetAttribute(gemm_kernel<3>, cudaFuncAttributeMaxDynamicSharedMemorySize, GEMM_SMEM);
        attr_done = true;
    }

    __nv_bfloat16 *ta, *ha, *wqkv, *wo, *w1, *w2;
    float *q_, *k_, *v_, *kv_, *ks_, *bqkv_;
    cudaGetSymbolAddress((void**)&ta, g_ta);     cudaGetSymbolAddress((void**)&ha, g_ha);
    cudaGetSymbolAddress((void**)&q_, g_q);      cudaGetSymbolAddress((void**)&k_, g_k);
    cudaGetSymbolAddress((void**)&v_, g_v);
    cudaGetSymbolAddress((void**)&kv_, g_kv);    cudaGetSymbolAddress((void**)&ks_, g_ks);
    cudaGetSymbolAddress((void**)&wqkv, g_wqkv); cudaGetSymbolAddress((void**)&wo, g_wo);
    cudaGetSymbolAddress((void**)&w1, g_w1);     cudaGetSymbolAddress((void**)&w2, g_w2);
    cudaGetSymbolAddress((void**)&bqkv_, g_bqkv);

    // 0. all weight prep in ONE launch
    wsplit_all_kernel<<<3075, 256>>>(Wq, Wk, Wv, Wo, W1, W2, bq, bk, bv);

    // 1. pre: x -> t (tiled bf16 split)
    pre_kernel<<<NTOK, 256>>>(x, g1, beta1, ta);

    // 2. fused QKV projection
    dim3 gQKV(6, NTOK / 128);
    gemm_kernel<3><<<gQKV, 256, GEMM_SMEM>>>(ta, wqkv, bqkv_, q_, k_, v_, nullptr, 8, 768);

    // 3. linear attention
    kv_reduce_kernel<<<B_ * J_ * H_, 256>>>(k_, v_, kv_, ks_);
    attn_apply_kernel<<<B_ * J_ * H_, 256>>>(q_, kv_, ks_, ta);   // y -> ta (tiled)

    // 4. output projection: o = y @ Wo + bo -> q_ (fp32)  [launch 5: ncu target]
    dim3 gD(2, NTOK / 128);
    gemm_kernel<0><<<gD, 256, GEMM_SMEM>>>(ta, wo, bo, q_, nullptr, nullptr, nullptr, 8, D_);

    // 5. Lorentz residual + LN2 -> ta (tiled u2)
    resid_kernel<<<NTOK, 256>>>(x, q_, g2, beta2, ta);

    // 6. FFN
    dim3 gH(8, NTOK / 128);
    gemm_kernel<2><<<gH, 256, GEMM_SMEM>>>(ta, w1, bf1, nullptr, nullptr, nullptr, ha, 8, HID_);
    gemm_kernel<0><<<gD, 256, GEMM_SMEM>>>(ha, w2, bf2, q_, nullptr, nullptr, nullptr, 32, D_);

    // 7. final expmap0 -> out
    final_kernel<<<NTOK, 256>>>(q_, out);
}

// round 11
// speedup vs baseline: 1.5805x; 1.1535x over previous
#include <cuda_runtime.h>
#include <cuda_fp16.h>
#include <math.h>
#include <stdint.h>

#define B_ 8
#define T_ 512
#define J_ 26
#define D_ 256
#define H_ 8
#define DH_ 32
#define HID_ 1024
#define NTOK 106496            // B*T*J  (= 832 * 128 exactly)
#define EPSF 1e-6f

// ================= PTX helpers (base ISA: sm_90 bulk-async, sm_80 mma) =================
__device__ __forceinline__ uint32_t smem_u32(const void* p) {
    uint32_t a;
    asm("{ .reg .u64 t; cvta.to.shared.u64 t, %1; cvt.u32.u64 %0, t; }" : "=r"(a) : "l"(p));
    return a;
}
#define MBAR_INIT(addr, cnt) \
    asm volatile("mbarrier.init.shared.b64 [%0], %1;" :: "r"(addr), "r"(cnt) : "memory")
#define MBAR_EXPECT_TX(addr, bytes) \
    asm volatile("mbarrier.arrive.expect_tx.shared.b64 _, [%0], %1;" :: "r"(addr), "r"(bytes) : "memory")
#define MBAR_WAIT(addr, phase) do { \
    uint32_t _m = (addr), _p = (phase); \
    asm volatile("{\n\t.reg .pred P;\n\tWL_%=:\n\t" \
        "mbarrier.try_wait.parity.acquire.cta.shared::cta.b64 P, [%0], %1, 0x989680;\n\t" \
        "@P bra.uni WD_%=;\n\tbra.uni WL_%=;\n\tWD_%=:\n\t}" :: "r"(_m), "r"(_p) : "memory"); \
} while (0)
#define CP_BULK(dst, src, bytes, mbar) \
    asm volatile("cp.async.bulk.shared::cluster.global.mbarrier::complete_tx::bytes [%0], [%1], %2, [%3];" \
        :: "r"(dst), "l"(src), "r"(bytes), "r"(mbar) : "memory")

#define LDSM4(r0, r1, r2, r3, addr) \
    asm volatile("ldmatrix.sync.aligned.m8n8.x4.shared.b16 {%0,%1,%2,%3}, [%4];" \
        : "=r"(r0), "=r"(r1), "=r"(r2), "=r"(r3) : "r"(addr))

__device__ __forceinline__ void mma16816(float* c, const uint32_t* a, const uint32_t* b) {
    asm volatile(
        "mma.sync.aligned.m16n8k16.row.col.f32.f16.f16.f32 "
        "{%0,%1,%2,%3}, {%4,%5,%6,%7}, {%8,%9}, {%0,%1,%2,%3};"
        : "+f"(c[0]), "+f"(c[1]), "+f"(c[2]), "+f"(c[3])
        : "r"(a[0]), "r"(a[1]), "r"(a[2]), "r"(a[3]), "r"(b[0]), "r"(b[1]));
}

// ============ tiled layout: [mtile][ktile][hi|lo][128x32 swizzled] ============
// tile = 128 rows x 32 cols fp16 = 8192 B; hi+lo pair = 16384 B.
// elem(r, c) -> r*32 + ((cc ^ ((r>>1)&3))<<3) + (c&7), cc = (c>>3)&3
__device__ __forceinline__ size_t tiled_idx(int row, int col, int wKt) {
    int mt = row >> 7, r = row & 127, kt = col >> 5, c = col & 31;
    return ((size_t)(mt * wKt + kt) * 2) * 4096 + (size_t)(r * 32)
         + (size_t)(((((c >> 3) & 3) ^ ((r >> 1) & 3)) << 3) + (c & 7));
}

// ================= scratch (static device .bss) =================
__device__ __half g_ta [(size_t)NTOK * D_ * 2];    // t / y / u2, tiled hi|lo, wKt=8
__device__ __half g_ha [(size_t)NTOK * HID_ * 2];  // FFN hidden, tiled hi|lo, wKt=32
__device__ float  g_q  [(size_t)NTOK * D_];        // pq / o / f
__device__ float  g_k  [(size_t)NTOK * D_];        // pk
__device__ float  g_v  [(size_t)NTOK * D_];        // v
__device__ float g_kv [(size_t)B_ * J_ * H_ * DH_ * DH_];
__device__ float g_ks [(size_t)B_ * J_ * H_ * DH_];
// weights, tiled hi|lo pairs (only hi consumed as B operand)
__device__ __half g_wqkv[768 * D_ * 2];      // 6 ntiles, wKt=8
__device__ __half g_wo  [D_ * D_ * 2];       // 2 ntiles, wKt=8
__device__ __half g_w1  [HID_ * D_ * 2];     // 8 ntiles, wKt=8
__device__ __half g_w2  [D_ * HID_ * 2];     // 2 ntiles, wKt=32
__device__ float g_bqkv[768];

// ================= small helpers =================
__device__ __forceinline__ float block_reduce_sum(float v, float* sbuf) {
    int lane = threadIdx.x & 31, w = threadIdx.x >> 5;
    #pragma unroll
    for (int o = 16; o; o >>= 1) v += __shfl_down_sync(0xffffffffu, v, o);
    if (lane == 0) sbuf[w] = v;
    __syncthreads();
    float r = (threadIdx.x < 8) ? sbuf[threadIdx.x] : 0.f;
    if (w == 0) {
        r += __shfl_down_sync(0xffffffffu, r, 4);
        r += __shfl_down_sync(0xffffffffu, r, 2);
        r += __shfl_down_sync(0xffffffffu, r, 1);
        if (lane == 0) sbuf[0] = r;
    }
    __syncthreads();
    float res = sbuf[0];
    __syncthreads();
    return res;
}
__device__ __forceinline__ void split_store_tiled(__half* base, int row, int col,
                                                  int wKt, float v) {
    size_t idx = tiled_idx(row, col, wKt);
    __half h = __float2half(v);
    base[idx] = h;
    base[idx + 4096] = __float2half(v - __half2float(h));
}

// ============ weight prep: transpose + split + tile, one launch ============
__global__ void wsplit_all_kernel(const float* __restrict__ Wq, const float* __restrict__ Wk,
                                  const float* __restrict__ Wv, const float* __restrict__ Wo,
                                  const float* __restrict__ W1, const float* __restrict__ W2,
                                  const float* __restrict__ bq, const float* __restrict__ bk,
                                  const float* __restrict__ bv) {
    int idx = blockIdx.x * 256 + threadIdx.x;
    if (idx < 196608) {
        int wsel = idx >> 16;
        int local = idx & 65535;
        const float* W = (wsel == 0) ? Wq : (wsel == 1) ? Wk : Wv;
        int k = local >> 8, n = local & 255;
        split_store_tiled(g_wqkv, wsel * 256 + n, k, 8, W[local]);
    } else if (idx < 262144) {
        int local = idx - 196608;
        int k = local >> 8, n = local & 255;
        split_store_tiled(g_wo, n, k, 8, Wo[local]);
    } else if (idx < 524288) {
        int local = idx - 262144;
        int k = local >> 10, n = local & 1023;
        split_store_tiled(g_w1, n, k, 8, W1[local]);
    } else if (idx < 786432) {
        int local = idx - 524288;
        int k = local >> 8, n = local & 255;
        split_store_tiled(g_w2, n, k, 32, W2[local]);
    } else if (idx < 787200) {
        int bi = idx - 786432;
        g_bqkv[bi] = (bi < 256) ? bq[bi] : (bi < 512) ? bk[bi - 256] : bv[bi - 512];
    }
}

// ============ K1: t = layernorm(logmap0(x)) -> tiled fp16 hi/lo ============
// (expmap0 -> logmap0 round-trip in the reference is the identity; skipped)
__global__ void pre_kernel(const float* __restrict__ x,
                           const float* __restrict__ g1,
                           const float* __restrict__ b1,
                           __half* __restrict__ ta) {
    __shared__ float sbuf[32];
    int row = blockIdx.x, i = threadIdx.x;
    const float* xr = x + (size_t)row * (D_ + 1);
    float xi = xr[1 + i];
    float ss = block_reduce_sum(xi * xi, sbuf);
    float n  = fmaxf(sqrtf(ss), EPSF);
    float x0 = fmaxf(xr[0], 1.0f + 1e-7f);
    float u  = acoshf(x0) * xi / n;
    float s1 = block_reduce_sum(u, sbuf);
    float s2 = block_reduce_sum(u * u, sbuf);
    float mean = s1 * (1.f / D_);
    float var  = s2 * (1.f / D_) - mean * mean;
    float tv = (u - mean) * rsqrtf(var + 1e-5f) * g1[i] + b1[i];
    split_store_tiled(ta, row, i, 8, tv);
}

// ============ HMMA split-fp16 2-pass GEMM, 3-stage bulk-async pipeline ============
// C = (Ah + Al) @ Bh^T + bias (fp32 accum).  Dropped A@Bl: rel ~2^-11.
// MODE 0: fp32 out, no act.  MODE 2: tiled fp16 hi/lo out, gelu.
// MODE 3: fused QKV (route by nBase, elu for Q/K), fp32 out.
#define NSTG 3
#define STAGE_DATA 24576                     // Ah 8K | Al 8K | Bh 8K
#define GEMM_SMEM (64 + NSTG * STAGE_DATA)   // 73792 B -> 2 CTAs/SM

template<int MODE>
__global__ __launch_bounds__(256) void gemm_kernel(
    const __half* __restrict__ A,     // tiled pairs, wKt = nkt
    const __half* __restrict__ Bw,    // tiled pairs (hi used), wKt = nkt
    const float* __restrict__ bias,
    float* __restrict__ Cf, float* __restrict__ Cf2, float* __restrict__ Cf3,
    __half* __restrict__ Ct,          // tiled out (MODE 2)
    int nkt, int NC)
{
    extern __shared__ char smem[];
    const uint32_t sb = smem_u32(smem);
    const int tid  = threadIdx.x;
    const int lane = tid & 31;
    const int w    = tid >> 5;
    const int mTile = blockIdx.y;
    const int nTile = blockIdx.x;
    const int mBase = mTile * 128;
    const int nBase = nTile * 128;
    const int wm = (w & 3) * 32;
    const int wn = (w >> 2) * 64;

    if (tid == 0) { MBAR_INIT(sb, 1); MBAR_INIT(sb + 8, 1); MBAR_INIT(sb + 16, 1); }
    __syncthreads();

    const char* Ab = (const char*)A + (size_t)mTile * nkt * 16384;
    const char* Bb = (const char*)Bw + (size_t)nTile * nkt * 16384;

    auto issue = [&](int kt, int s) {
        uint32_t mb = sb + (uint32_t)s * 8;
        uint32_t d  = sb + 64 + (uint32_t)s * STAGE_DATA;
        MBAR_EXPECT_TX(mb, 24576);
        CP_BULK(d,         Ab + (size_t)kt * 16384, 16384u, mb);   // Ah+Al pair
        CP_BULK(d + 16384, Bb + (size_t)kt * 16384, 8192u,  mb);   // Bh only
    };
    if (tid == 0) {
        issue(0, 0);
        if (nkt > 1) issue(1, 1);
    }

    float acc[2][8][4];
    #pragma unroll
    for (int mt = 0; mt < 2; mt++)
        #pragma unroll
        for (int nt = 0; nt < 8; nt++)
            #pragma unroll
            for (int i = 0; i < 4; i++) acc[mt][nt][i] = 0.f;

    const int aRow = lane & 15;
    const int aSel = lane >> 4;

    for (int kt = 0; kt < nkt; kt++) {
        int s = kt % NSTG;
        if (tid == 0) {
            int pf = kt + 2;
            if (pf < nkt) issue(pf, pf % NSTG);
        }
        MBAR_WAIT(sb + (uint32_t)s * 8, (kt / NSTG) & 1);

        uint32_t sbase = sb + 64 + (uint32_t)s * STAGE_DATA;
        uint32_t aHb = sbase;
        uint32_t aLb = sbase + 8192;
        uint32_t bHb = sbase + 16384;

        #pragma unroll
        for (int kk = 0; kk < 2; kk++) {
            uint32_t bH[8][2];
            #pragma unroll
            for (int p = 0; p < 4; p++) {
                int row = wn + p * 16 + (lane & 15);
                int cc  = 2 * kk + (lane >> 4);
                uint32_t off = (uint32_t)(row * 64 + ((cc ^ ((row >> 1) & 3)) << 4));
                uint32_t q0, q1, q2, q3;
                LDSM4(q0, q1, q2, q3, bHb + off);
                bH[2*p][0] = q0; bH[2*p+1][0] = q1; bH[2*p][1] = q2; bH[2*p+1][1] = q3;
            }
            #pragma unroll
            for (int mt = 0; mt < 2; mt++) {
                int row = wm + mt * 16 + aRow;
                int cc  = 2 * kk + aSel;
                uint32_t off = (uint32_t)(row * 64 + ((cc ^ ((row >> 1) & 3)) << 4));
                uint32_t aH[4], aL[4];
                LDSM4(aH[0], aH[1], aH[2], aH[3], aHb + off);
                LDSM4(aL[0], aL[1], aL[2], aL[3], aLb + off);
                #pragma unroll
                for (int nt = 0; nt < 8; nt++) mma16816(acc[mt][nt], aH, bH[nt]);
                #pragma unroll
                for (int nt = 0; nt < 8; nt++) mma16816(acc[mt][nt], aL, bH[nt]);
            }
        }
        __syncthreads();   // all warps done with slot s -> legalizes refill at kt+2
    }

    // ---------------- epilogue ----------------
    const int gid = lane >> 2;
    const int tig = lane & 3;
    int which = 0; float* dstQKV = Cf; bool eluAct = false; int nLoc = nBase;
    if (MODE == 3) {
        which = nBase >> 8;
        dstQKV = (which == 0) ? Cf : (which == 1) ? Cf2 : Cf3;
        eluAct = (which < 2);
        nLoc = nBase - which * 256;
    }
    #pragma unroll
    for (int mt = 0; mt < 2; mt++) {
        #pragma unroll
        for (int nt = 0; nt < 8; nt++) {
            int colT = wn + nt * 8 + tig * 2;
            float b0 = bias[nBase + colT], b1 = bias[nBase + colT + 1];
            #pragma unroll
            for (int half = 0; half < 2; half++) {
                int row = mBase + wm + mt * 16 + gid + half * 8;
                float v0 = acc[mt][nt][half * 2 + 0] + b0;
                float v1 = acc[mt][nt][half * 2 + 1] + b1;
                if (MODE == 3 && eluAct) {
                    v0 = (v0 > 0.f) ? (v0 + 1.f) : __expf(v0);
                    v1 = (v1 > 0.f) ? (v1 + 1.f) : __expf(v1);
                } else if (MODE == 2) {
                    float c0 = v0 * v0 * v0;
                    v0 = 0.5f * v0 * (1.f + tanhf(0.7978845608028654f * (v0 + 0.044715f * c0)));
                    float c1 = v1 * v1 * v1;
                    v1 = 0.5f * v1 * (1.f + tanhf(0.7978845608028654f * (v1 + 0.044715f * c1)));
                }
                if (MODE == 2) {
                    size_t idx = tiled_idx(row, nBase + colT, NC >> 5);
                    __half h0 = __float2half(v0);
                    __half h1 = __float2half(v1);
                    __half l0 = __float2half(v0 - __half2float(h0));
                    __half l1 = __float2half(v1 - __half2float(h1));
                    uint32_t hp = ((uint32_t)__half_as_ushort(h1) << 16) | __half_as_ushort(h0);
                    uint32_t lp = ((uint32_t)__half_as_ushort(l1) << 16) | __half_as_ushort(l0);
                    *reinterpret_cast<uint32_t*>(Ct + idx) = hp;
                    *reinterpret_cast<uint32_t*>(Ct + idx + 4096) = lp;
                } else if (MODE == 3) {
                    size_t base = (size_t)row * 256 + nLoc + colT;
                    *reinterpret_cast<float2*>(dstQKV + base) = make_float2(v0, v1);
                } else {
                    size_t base = (size_t)row * NC + nBase + colT;
                    *reinterpret_cast<float2*>(Cf + base) = make_float2(v0, v1);
                }
            }
        }
    }
}

// ============ K3: kv / ksum via per-warp shuffle outer-product ============
__global__ void kv_reduce_kernel(const float* __restrict__ pk,
                                 const float* __restrict__ v,
                                 float* __restrict__ kv,
                                 float* __restrict__ ksum) {
    int bh = blockIdx.x;
    int h  = bh % H_;
    int bj = bh / H_;
    int j  = bj % J_;
    int b  = bj / J_;
    int tid = threadIdx.x, lane = tid & 31, w = tid >> 5;

    float acc[32];
    #pragma unroll
    for (int k = 0; k < 32; k++) acc[k] = 0.f;
    float ks = 0.f;

    for (int t = w; t < T_; t += 8) {
        size_t base = (((size_t)(b * T_ + t) * J_) + j) * D_ + h * DH_ + lane;
        float pkv = pk[base];
        float vv  = v[base];
        ks += pkv;
        #pragma unroll
        for (int k = 0; k < 32; k++)
            acc[k] += __shfl_sync(0xffffffffu, pkv, k) * vv;
    }

    __shared__ float red[8][32][32];
    __shared__ float rks[8][32];
    #pragma unroll
    for (int k = 0; k < 32; k++) red[w][k][lane] = acc[k];
    rks[w][lane] = ks;
    __syncthreads();

    #pragma unroll
    for (int kk = 0; kk < 4; kk++) {
        int k = w * 4 + kk;
        float s = 0.f;
        #pragma unroll
        for (int ww = 0; ww < 8; ww++) s += red[ww][k][lane];
        kv[(size_t)bh * (DH_ * DH_) + k * 32 + lane] = s;
    }
    if (w == 0) {
        float s = 0.f;
        #pragma unroll
        for (int ww = 0; ww < 8; ww++) s += rks[ww][lane];
        ksum[(size_t)bh * DH_ + lane] = s;
    }
}

// ============ K4: y = (pq @ kv) / (pq . ksum + EPS) -> tiled fp16 hi/lo ============
__global__ void attn_apply_kernel(const float* __restrict__ pq,
                                  const float* __restrict__ kv,
                                  const float* __restrict__ ksum,
                                  __half* __restrict__ ya) {
    int bh = blockIdx.x;
    int h  = bh % H_;
    int bj = bh / H_;
    int j  = bj % J_;
    int b  = bj / J_;
    __shared__ float skv[DH_ * DH_];
    __shared__ float sks[DH_];
    int tid = threadIdx.x;
    for (int i = tid; i < DH_ * DH_; i += 256) skv[i] = kv[(size_t)bh * (DH_ * DH_) + i];
    if (tid < DH_) sks[tid] = ksum[(size_t)bh * DH_ + tid];
    __syncthreads();
    int lane = tid & 31, w = tid >> 5;
    for (int t = w; t < T_; t += 8) {
        int token = (b * T_ + t) * J_ + j;
        size_t baseQ = (size_t)token * D_ + h * DH_;
        float q = pq[baseQ + lane];
        float den = q * sks[lane];
        #pragma unroll
        for (int o = 16; o; o >>= 1) den += __shfl_xor_sync(0xffffffffu, den, o);
        float num = 0.f;
        #pragma unroll
        for (int k = 0; k < 32; k++)
            num += __shfl_sync(0xffffffffu, q, k) * skv[k * 32 + lane];
        split_store_tiled(ya, token, h * DH_ + lane, 8, num / (den + EPSF));
    }
}

// ============ K5: residual + LN2 -> tiled fp16 hi/lo ============
__global__ void resid_kernel(const float* __restrict__ x,
                             const float* __restrict__ o_in,
                             const float* __restrict__ g2,
                             const float* __restrict__ b2,
                             __half* __restrict__ ua) {
    __shared__ float sbuf[32];
    int row = blockIdx.x, i = threadIdx.x;
    const float* xr = x + (size_t)row * (D_ + 1);
    float o = o_in[(size_t)row * D_ + i];
    float so = block_reduce_sum(o * o, sbuf);
    float n  = fmaxf(sqrtf(so), EPSF);
    float z  = sinhf(n) * o / n;
    float m  = xr[1 + i] + z;
    float sm = block_reduce_sum(m * m, sbuf);
    float m0 = xr[0] + coshf(n);
    float mink = -m0 * m0 + sm;
    float inv  = rsqrtf(fmaxf(-mink, EPSF));
    float h0   = m0 * inv;
    float hs   = m * inv;
    float hn   = fmaxf(sqrtf(sm) * inv, EPSF);
    float u    = acoshf(fmaxf(h0, 1.0f + 1e-7f)) * hs / hn;
    float s1 = block_reduce_sum(u, sbuf);
    float s2 = block_reduce_sum(u * u, sbuf);
    float mean = s1 * (1.f / D_);
    float var  = s2 * (1.f / D_) - mean * mean;
    float uv = (u - mean) * rsqrtf(var + 1e-5f) * g2[i] + b2[i];
    split_store_tiled(ua, row, i, 8, uv);
}

// ============ K6: out = expmap0(f) ============
__global__ void final_kernel(const float* __restrict__ f_in,
                             float* __restrict__ out) {
    __shared__ float sbuf[32];
    int row = blockIdx.x, i = threadIdx.x;
    float f = f_in[(size_t)row * D_ + i];
    float ss = block_reduce_sum(f * f, sbuf);
    float n  = fmaxf(sqrtf(ss), EPSF);
    float* orow = out + (size_t)row * (D_ + 1);
    orow[1 + i] = sinhf(n) * f / n;
    if (i == 0) orow[0] = coshf(n);
}

// ================= launch =================
extern "C" void kernel_launch(void* const* d_in, const int* /*in_sizes*/, int /*n_in*/,
                              void* d_out, int /*out_size*/) {
    const float* x     = (const float*)d_in[0];
    const float* g1    = (const float*)d_in[1];
    const float* beta1 = (const float*)d_in[2];
    const float* Wq    = (const float*)d_in[3];
    const float* Wk    = (const float*)d_in[4];
    const float* Wv    = (const float*)d_in[5];
    const float* Wo    = (const float*)d_in[6];
    const float* bq    = (const float*)d_in[7];
    const float* bk    = (const float*)d_in[8];
    const float* bv    = (const float*)d_in[9];
    const float* bo    = (const float*)d_in[10];
    const float* g2    = (const float*)d_in[11];
    const float* beta2 = (const float*)d_in[12];
    const float* W1    = (const float*)d_in[13];
    const float* bf1   = (const float*)d_in[14];
    const float* W2    = (const float*)d_in[15];
    const float* bf2   = (const float*)d_in[16];
    float* out = (float*)d_out;

    static bool attr_done = false;
    if (!attr_done) {
        cudaFuncSetAttribute(gemm_kernel<0>, cudaFuncAttributeMaxDynamicSharedMemorySize, GEMM_SMEM);
        cudaFuncSetAttribute(gemm_kernel<2>, cudaFuncAttributeMaxDynamicSharedMemorySize, GEMM_SMEM);
        cudaFuncSetAttribute(gemm_kernel<3>, cudaFuncAttributeMaxDynamicSharedMemorySize, GEMM_SMEM);
        attr_done = true;
    }

    __half *ta, *ha, *wqkv, *wo, *w1, *w2;
    float *q_, *k_, *v_, *kv_, *ks_, *bqkv_;
    cudaGetSymbolAddress((void**)&ta, g_ta);     cudaGetSymbolAddress((void**)&ha, g_ha);
    cudaGetSymbolAddress((void**)&q_, g_q);      cudaGetSymbolAddress((void**)&k_, g_k);
    cudaGetSymbolAddress((void**)&v_, g_v);
    cudaGetSymbolAddress((void**)&kv_, g_kv);    cudaGetSymbolAddress((void**)&ks_, g_ks);
    cudaGetSymbolAddress((void**)&wqkv, g_wqkv); cudaGetSymbolAddress((void**)&wo, g_wo);
    cudaGetSymbolAddress((void**)&w1, g_w1);     cudaGetSymbolAddress((void**)&w2, g_w2);
    cudaGetSymbolAddress((void**)&bqkv_, g_bqkv);

    // 0. all weight prep in ONE launch
    wsplit_all_kernel<<<3075, 256>>>(Wq, Wk, Wv, Wo, W1, W2, bq, bk, bv);

    // 1. pre: x -> t (tiled fp16 split)
    pre_kernel<<<NTOK, 256>>>(x, g1, beta1, ta);

    // 2. fused QKV projection
    dim3 gQKV(6, NTOK / 128);
    gemm_kernel<3><<<gQKV, 256, GEMM_SMEM>>>(ta, wqkv, bqkv_, q_, k_, v_, nullptr, 8, 768);

    // 3. linear attention
    kv_reduce_kernel<<<B_ * J_ * H_, 256>>>(k_, v_, kv_, ks_);
    attn_apply_kernel<<<B_ * J_ * H_, 256>>>(q_, kv_, ks_, ta);   // y -> ta (tiled)

    // 4. output projection: o = y @ Wo + bo -> q_ (fp32)
    dim3 gD(2, NTOK / 128);
    gemm_kernel<0><<<gD, 256, GEMM_SMEM>>>(ta, wo, bo, q_, nullptr, nullptr, nullptr, 8, D_);

    // 5. Lorentz residual + LN2 -> ta (tiled u2)
    resid_kernel<<<NTOK, 256>>>(x, q_, g2, beta2, ta);

    // 6. FFN
    dim3 gH(8, NTOK / 128);
    gemm_kernel<2><<<gH, 256, GEMM_SMEM>>>(ta, w1, bf1, nullptr, nullptr, nullptr, ha, 8, HID_);
    gemm_kernel<0><<<gD, 256, GEMM_SMEM>>>(ha, w2, bf2, q_, nullptr, nullptr, nullptr, 32, D_);

    // 7. final expmap0 -> out
    final_kernel<<<NTOK, 256>>>(q_, out);
}

// round 12
// speedup vs baseline: 1.5817x; 1.0008x over previous
#include <cuda_runtime.h>
#include <cuda_fp16.h>
#include <math.h>
#include <stdint.h>

#define B_ 8
#define T_ 512
#define J_ 26
#define D_ 256
#define H_ 8
#define DH_ 32
#define HID_ 1024
#define NTOK 106496            // B*T*J  (= 832 * 128 exactly)
#define EPSF 1e-6f

// ================= PTX helpers (base ISA: sm_90 bulk-async, sm_80 mma) =================
__device__ __forceinline__ uint32_t smem_u32(const void* p) {
    uint32_t a;
    asm("{ .reg .u64 t; cvta.to.shared.u64 t, %1; cvt.u32.u64 %0, t; }" : "=r"(a) : "l"(p));
    return a;
}
#define MBAR_INIT(addr, cnt) \
    asm volatile("mbarrier.init.shared.b64 [%0], %1;" :: "r"(addr), "r"(cnt) : "memory")
#define MBAR_EXPECT_TX(addr, bytes) \
    asm volatile("mbarrier.arrive.expect_tx.shared.b64 _, [%0], %1;" :: "r"(addr), "r"(bytes) : "memory")
#define MBAR_WAIT(addr, phase) do { \
    uint32_t _m = (addr), _p = (phase); \
    asm volatile("{\n\t.reg .pred P;\n\tWL_%=:\n\t" \
        "mbarrier.try_wait.parity.acquire.cta.shared::cta.b64 P, [%0], %1, 0x989680;\n\t" \
        "@P bra.uni WD_%=;\n\tbra.uni WL_%=;\n\tWD_%=:\n\t}" :: "r"(_m), "r"(_p) : "memory"); \
} while (0)
#define CP_BULK(dst, src, bytes, mbar) \
    asm volatile("cp.async.bulk.shared::cluster.global.mbarrier::complete_tx::bytes [%0], [%1], %2, [%3];" \
        :: "r"(dst), "l"(src), "r"(bytes), "r"(mbar) : "memory")

#define LDSM4(r0, r1, r2, r3, addr) \
    asm volatile("ldmatrix.sync.aligned.m8n8.x4.shared.b16 {%0,%1,%2,%3}, [%4];" \
        : "=r"(r0), "=r"(r1), "=r"(r2), "=r"(r3) : "r"(addr))

__device__ __forceinline__ void mma16816(float* c, const uint32_t* a, const uint32_t* b) {
    asm volatile(
        "mma.sync.aligned.m16n8k16.row.col.f32.f16.f16.f32 "
        "{%0,%1,%2,%3}, {%4,%5,%6,%7}, {%8,%9}, {%0,%1,%2,%3};"
        : "+f"(c[0]), "+f"(c[1]), "+f"(c[2]), "+f"(c[3])
        : "r"(a[0]), "r"(a[1]), "r"(a[2]), "r"(a[3]), "r"(b[0]), "r"(b[1]));
}

// ============ tiled layout: [mtile][ktile][hi|lo][128x32 swizzled] ============
// tile = 128 rows x 32 cols fp16 = 8192 B; hi+lo pair = 16384 B.
// elem(r, c) -> r*32 + ((cc ^ ((r>>1)&3))<<3) + (c&7), cc = (c>>3)&3
__device__ __forceinline__ size_t tiled_idx(int row, int col, int wKt) {
    int mt = row >> 7, r = row & 127, kt = col >> 5, c = col & 31;
    return ((size_t)(mt * wKt + kt) * 2) * 4096 + (size_t)(r * 32)
         + (size_t)(((((c >> 3) & 3) ^ ((r >> 1) & 3)) << 3) + (c & 7));
}

// ================= scratch (static device .bss) =================
__device__ __half g_ta [(size_t)NTOK * D_ * 2];    // t / y / u2, tiled hi|lo, wKt=8
__device__ __half g_ha [(size_t)NTOK * HID_ * 2];  // FFN hidden, tiled hi|lo, wKt=32
__device__ float  g_q  [(size_t)NTOK * D_];        // pq / o / f
__device__ float  g_k  [(size_t)NTOK * D_];        // pk
__device__ float  g_v  [(size_t)NTOK * D_];        // v
__device__ float g_kv [(size_t)B_ * J_ * H_ * DH_ * DH_];
__device__ float g_ks [(size_t)B_ * J_ * H_ * DH_];
// weights, tiled hi|lo pairs (only hi consumed as B operand)
__device__ __half g_wqkv[768 * D_ * 2];      // 6 ntiles, wKt=8
__device__ __half g_wo  [D_ * D_ * 2];       // 2 ntiles, wKt=8
__device__ __half g_w1  [HID_ * D_ * 2];     // 8 ntiles, wKt=8
__device__ __half g_w2  [D_ * HID_ * 2];     // 2 ntiles, wKt=32
__device__ float g_bqkv[768];

// ================= small helpers =================
__device__ __forceinline__ float block_reduce_sum(float v, float* sbuf) {
    int lane = threadIdx.x & 31, w = threadIdx.x >> 5;
    #pragma unroll
    for (int o = 16; o; o >>= 1) v += __shfl_down_sync(0xffffffffu, v, o);
    if (lane == 0) sbuf[w] = v;
    __syncthreads();
    float r = (threadIdx.x < 8) ? sbuf[threadIdx.x] : 0.f;
    if (w == 0) {
        r += __shfl_down_sync(0xffffffffu, r, 4);
        r += __shfl_down_sync(0xffffffffu, r, 2);
        r += __shfl_down_sync(0xffffffffu, r, 1);
        if (lane == 0) sbuf[0] = r;
    }
    __syncthreads();
    float res = sbuf[0];
    __syncthreads();
    return res;
}
__device__ __forceinline__ void split_store_tiled(__half* base, int row, int col,
                                                  int wKt, float v) {
    size_t idx = tiled_idx(row, col, wKt);
    __half h = __float2half(v);
    base[idx] = h;
    base[idx + 4096] = __float2half(v - __half2float(h));
}

// ============ weight prep: transpose + split + tile, one launch ============
__global__ void wsplit_all_kernel(const float* __restrict__ Wq, const float* __restrict__ Wk,
                                  const float* __restrict__ Wv, const float* __restrict__ Wo,
                                  const float* __restrict__ W1, const float* __restrict__ W2,
                                  const float* __restrict__ bq, const float* __restrict__ bk,
                                  const float* __restrict__ bv) {
    int idx = blockIdx.x * 256 + threadIdx.x;
    if (idx < 196608) {
        int wsel = idx >> 16;
        int local = idx & 65535;
        const float* W = (wsel == 0) ? Wq : (wsel == 1) ? Wk : Wv;
        int k = local >> 8, n = local & 255;
        split_store_tiled(g_wqkv, wsel * 256 + n, k, 8, W[local]);
    } else if (idx < 262144) {
        int local = idx - 196608;
        int k = local >> 8, n = local & 255;
        split_store_tiled(g_wo, n, k, 8, Wo[local]);
    } else if (idx < 524288) {
        int local = idx - 262144;
        int k = local >> 10, n = local & 1023;
        split_store_tiled(g_w1, n, k, 8, W1[local]);
    } else if (idx < 786432) {
        int local = idx - 524288;
        int k = local >> 8, n = local & 255;
        split_store_tiled(g_w2, n, k, 32, W2[local]);
    } else if (idx < 787200) {
        int bi = idx - 786432;
        g_bqkv[bi] = (bi < 256) ? bq[bi] : (bi < 512) ? bk[bi - 256] : bv[bi - 512];
    }
}

// ============ K1: t = layernorm(logmap0(x)) -> tiled fp16 hi/lo ============
// (expmap0 -> logmap0 round-trip in the reference is the identity; skipped)
__global__ void pre_kernel(const float* __restrict__ x,
                           const float* __restrict__ g1,
                           const float* __restrict__ b1,
                           __half* __restrict__ ta) {
    __shared__ float sbuf[32];
    int row = blockIdx.x, i = threadIdx.x;
    const float* xr = x + (size_t)row * (D_ + 1);
    float xi = xr[1 + i];
    float ss = block_reduce_sum(xi * xi, sbuf);
    float n  = fmaxf(sqrtf(ss), EPSF);
    float x0 = fmaxf(xr[0], 1.0f + 1e-7f);
    float u  = acoshf(x0) * xi / n;
    float s1 = block_reduce_sum(u, sbuf);
    float s2 = block_reduce_sum(u * u, sbuf);
    float mean = s1 * (1.f / D_);
    float var  = s2 * (1.f / D_) - mean * mean;
    float tv = (u - mean) * rsqrtf(var + 1e-5f) * g1[i] + b1[i];
    split_store_tiled(ta, row, i, 8, tv);
}

// ============ HMMA split-fp16 2-pass GEMM, 3-stage bulk-async pipeline ============
// C = (Ah + Al) @ Bh^T + bias (fp32 accum).  Dropped A@Bl: rel ~2^-11.
// MODE 0: fp32 out, no act.  MODE 2: tiled fp16 hi/lo out, gelu.
// MODE 3: fused QKV (route by nBase, elu for Q/K), fp32 out.
#define NSTG 3
#define STAGE_DATA 24576                     // Ah 8K | Al 8K | Bh 8K
#define GEMM_SMEM (64 + NSTG * STAGE_DATA)   // 73792 B -> 2 CTAs/SM

template<int MODE>
__global__ __launch_bounds__(256) void gemm_kernel(
    const __half* __restrict__ A,     // tiled pairs, wKt = nkt
    const __half* __restrict__ Bw,    // tiled pairs (hi used), wKt = nkt
    const float* __restrict__ bias,
    float* __restrict__ Cf, float* __restrict__ Cf2, float* __restrict__ Cf3,
    __half* __restrict__ Ct,          // tiled out (MODE 2)
    int nkt, int NC)
{
    extern __shared__ char smem[];
    const uint32_t sb = smem_u32(smem);
    const int tid  = threadIdx.x;
    const int lane = tid & 31;
    const int w    = tid >> 5;
    const int mTile = blockIdx.y;
    const int nTile = blockIdx.x;
    const int mBase = mTile * 128;
    const int nBase = nTile * 128;
    const int wm = (w & 3) * 32;
    const int wn = (w >> 2) * 64;

    if (tid == 0) { MBAR_INIT(sb, 1); MBAR_INIT(sb + 8, 1); MBAR_INIT(sb + 16, 1); }
    __syncthreads();

    const char* Ab = (const char*)A + (size_t)mTile * nkt * 16384;
    const char* Bb = (const char*)Bw + (size_t)nTile * nkt * 16384;

    auto issue = [&](int kt, int s) {
        uint32_t mb = sb + (uint32_t)s * 8;
        uint32_t d  = sb + 64 + (uint32_t)s * STAGE_DATA;
        MBAR_EXPECT_TX(mb, 24576);
        CP_BULK(d,         Ab + (size_t)kt * 16384, 16384u, mb);   // Ah+Al pair
        CP_BULK(d + 16384, Bb + (size_t)kt * 16384, 8192u,  mb);   // Bh only
    };
    if (tid == 0) {
        issue(0, 0);
        if (nkt > 1) issue(1, 1);
    }

    float acc[2][8][4];
    #pragma unroll
    for (int mt = 0; mt < 2; mt++)
        #pragma unroll
        for (int nt = 0; nt < 8; nt++)
            #pragma unroll
            for (int i = 0; i < 4; i++) acc[mt][nt][i] = 0.f;

    const int aRow = lane & 15;
    const int aSel = lane >> 4;

    for (int kt = 0; kt < nkt; kt++) {
        int s = kt % NSTG;
        if (tid == 0) {
            int pf = kt + 2;
            if (pf < nkt) issue(pf, pf % NSTG);
        }
        MBAR_WAIT(sb + (uint32_t)s * 8, (kt / NSTG) & 1);

        uint32_t sbase = sb + 64 + (uint32_t)s * STAGE_DATA;
        uint32_t aHb = sbase;
        uint32_t aLb = sbase + 8192;
        uint32_t bHb = sbase + 16384;

        #pragma unroll
        for (int kk = 0; kk < 2; kk++) {
            uint32_t bH[8][2];
            #pragma unroll
            for (int p = 0; p < 4; p++) {
                int row = wn + p * 16 + (lane & 15);
                int cc  = 2 * kk + (lane >> 4);
                uint32_t off = (uint32_t)(row * 64 + ((cc ^ ((row >> 1) & 3)) << 4));
                uint32_t q0, q1, q2, q3;
                LDSM4(q0, q1, q2, q3, bHb + off);
                bH[2*p][0] = q0; bH[2*p+1][0] = q1; bH[2*p][1] = q2; bH[2*p+1][1] = q3;
            }
            #pragma unroll
            for (int mt = 0; mt < 2; mt++) {
                int row = wm + mt * 16 + aRow;
                int cc  = 2 * kk + aSel;
                uint32_t off = (uint32_t)(row * 64 + ((cc ^ ((row >> 1) & 3)) << 4));
                uint32_t aH[4], aL[4];
                LDSM4(aH[0], aH[1], aH[2], aH[3], aHb + off);
                LDSM4(aL[0], aL[1], aL[2], aL[3], aLb + off);
                #pragma unroll
                for (int nt = 0; nt < 8; nt++) mma16816(acc[mt][nt], aH, bH[nt]);
                #pragma unroll
                for (int nt = 0; nt < 8; nt++) mma16816(acc[mt][nt], aL, bH[nt]);
            }
        }
        __syncthreads();   // all warps done with slot s -> legalizes refill at kt+2
    }

    // ---------------- epilogue ----------------
    const int gid = lane >> 2;
    const int tig = lane & 3;
    int which = 0; float* dstQKV = Cf; bool eluAct = false; int nLoc = nBase;
    if (MODE == 3) {
        which = nBase >> 8;
        dstQKV = (which == 0) ? Cf : (which == 1) ? Cf2 : Cf3;
        eluAct = (which < 2);
        nLoc = nBase - which * 256;
    }
    #pragma unroll
    for (int mt = 0; mt < 2; mt++) {
        #pragma unroll
        for (int nt = 0; nt < 8; nt++) {
            int colT = wn + nt * 8 + tig * 2;
            float b0 = bias[nBase + colT], b1 = bias[nBase + colT + 1];
            #pragma unroll
            for (int half = 0; half < 2; half++) {
                int row = mBase + wm + mt * 16 + gid + half * 8;
                float v0 = acc[mt][nt][half * 2 + 0] + b0;
                float v1 = acc[mt][nt][half * 2 + 1] + b1;
                if (MODE == 3 && eluAct) {
                    v0 = (v0 > 0.f) ? (v0 + 1.f) : __expf(v0);
                    v1 = (v1 > 0.f) ? (v1 + 1.f) : __expf(v1);
                } else if (MODE == 2) {
                    float c0 = v0 * v0 * v0;
                    v0 = 0.5f * v0 * (1.f + tanhf(0.7978845608028654f * (v0 + 0.044715f * c0)));
                    float c1 = v1 * v1 * v1;
                    v1 = 0.5f * v1 * (1.f + tanhf(0.7978845608028654f * (v1 + 0.044715f * c1)));
                }
                if (MODE == 2) {
                    size_t idx = tiled_idx(row, nBase + colT, NC >> 5);
                    __half h0 = __float2half(v0);
                    __half h1 = __float2half(v1);
                    __half l0 = __float2half(v0 - __half2float(h0));
                    __half l1 = __float2half(v1 - __half2float(h1));
                    uint32_t hp = ((uint32_t)__half_as_ushort(h1) << 16) | __half_as_ushort(h0);
                    uint32_t lp = ((uint32_t)__half_as_ushort(l1) << 16) | __half_as_ushort(l0);
                    *reinterpret_cast<uint32_t*>(Ct + idx) = hp;
                    *reinterpret_cast<uint32_t*>(Ct + idx + 4096) = lp;
                } else if (MODE == 3) {
                    size_t base = (size_t)row * 256 + nLoc + colT;
                    *reinterpret_cast<float2*>(dstQKV + base) = make_float2(v0, v1);
                } else {
                    size_t base = (size_t)row * NC + nBase + colT;
                    *reinterpret_cast<float2*>(Cf + base) = make_float2(v0, v1);
                }
            }
        }
    }
}

// ============ K3: kv / ksum via per-warp shuffle outer-product ============
__global__ void kv_reduce_kernel(const float* __restrict__ pk,
                                 const float* __restrict__ v,
                                 float* __restrict__ kv,
                                 float* __restrict__ ksum) {
    int bh = blockIdx.x;
    int h  = bh % H_;
    int bj = bh / H_;
    int j  = bj % J_;
    int b  = bj / J_;
    int tid = threadIdx.x, lane = tid & 31, w = tid >> 5;

    float acc[32];
    #pragma unroll
    for (int k = 0; k < 32; k++) acc[k] = 0.f;
    float ks = 0.f;

    for (int t = w; t < T_; t += 8) {
        size_t base = (((size_t)(b * T_ + t) * J_) + j) * D_ + h * DH_ + lane;
        float pkv = pk[base];
        float vv  = v[base];
        ks += pkv;
        #pragma unroll
        for (int k = 0; k < 32; k++)
            acc[k] += __shfl_sync(0xffffffffu, pkv, k) * vv;
    }

    __shared__ float red[8][32][32];
    __shared__ float rks[8][32];
    #pragma unroll
    for (int k = 0; k < 32; k++) red[w][k][lane] = acc[k];
    rks[w][lane] = ks;
    __syncthreads();

    #pragma unroll
    for (int kk = 0; kk < 4; kk++) {
        int k = w * 4 + kk;
        float s = 0.f;
        #pragma unroll
        for (int ww = 0; ww < 8; ww++) s += red[ww][k][lane];
        kv[(size_t)bh * (DH_ * DH_) + k * 32 + lane] = s;
    }
    if (w == 0) {
        float s = 0.f;
        #pragma unroll
        for (int ww = 0; ww < 8; ww++) s += rks[ww][lane];
        ksum[(size_t)bh * DH_ + lane] = s;
    }
}

// ============ K4: y = (pq @ kv) / (pq . ksum + EPS) -> tiled fp16 hi/lo ============
__global__ void attn_apply_kernel(const float* __restrict__ pq,
                                  const float* __restrict__ kv,
                                  const float* __restrict__ ksum,
                                  __half* __restrict__ ya) {
    int bh = blockIdx.x;
    int h  = bh % H_;
    int bj = bh / H_;
    int j  = bj % J_;
    int b  = bj / J_;
    __shared__ float skv[DH_ * DH_];
    __shared__ float sks[DH_];
    int tid = threadIdx.x;
    for (int i = tid; i < DH_ * DH_; i += 256) skv[i] = kv[(size_t)bh * (DH_ * DH_) + i];
    if (tid < DH_) sks[tid] = ksum[(size_t)bh * DH_ + tid];
    __syncthreads();
    int lane = tid & 31, w = tid >> 5;
    for (int t = w; t < T_; t += 8) {
        int token = (b * T_ + t) * J_ + j;
        size_t baseQ = (size_t)token * D_ + h * DH_;
        float q = pq[baseQ + lane];
        float den = q * sks[lane];
        #pragma unroll
        for (int o = 16; o; o >>= 1) den += __shfl_xor_sync(0xffffffffu, den, o);
        float num = 0.f;
        #pragma unroll
        for (int k = 0; k < 32; k++)
            num += __shfl_sync(0xffffffffu, q, k) * skv[k * 32 + lane];
        split_store_tiled(ya, token, h * DH_ + lane, 8, num / (den + EPSF));
    }
}

// ============ K5: residual + LN2 -> tiled fp16 hi/lo ============
__global__ void resid_kernel(const float* __restrict__ x,
                             const float* __restrict__ o_in,
                             const float* __restrict__ g2,
                             const float* __restrict__ b2,
                             __half* __restrict__ ua) {
    __shared__ float sbuf[32];
    int row = blockIdx.x, i = threadIdx.x;
    const float* xr = x + (size_t)row * (D_ + 1);
    float o = o_in[(size_t)row * D_ + i];
    float so = block_reduce_sum(o * o, sbuf);
    float n  = fmaxf(sqrtf(so), EPSF);
    float z  = sinhf(n) * o / n;
    float m  = xr[1 + i] + z;
    float sm = block_reduce_sum(m * m, sbuf);
    float m0 = xr[0] + coshf(n);
    float mink = -m0 * m0 + sm;
    float inv  = rsqrtf(fmaxf(-mink, EPSF));
    float h0   = m0 * inv;
    float hs   = m * inv;
    float hn   = fmaxf(sqrtf(sm) * inv, EPSF);
    float u    = acoshf(fmaxf(h0, 1.0f + 1e-7f)) * hs / hn;
    float s1 = block_reduce_sum(u, sbuf);
    float s2 = block_reduce_sum(u * u, sbuf);
    float mean = s1 * (1.f / D_);
    float var  = s2 * (1.f / D_) - mean * mean;
    float uv = (u - mean) * rsqrtf(var + 1e-5f) * g2[i] + b2[i];
    split_store_tiled(ua, row, i, 8, uv);
}

// ============ K6: out = expmap0(f) ============
__global__ void final_kernel(const float* __restrict__ f_in,
                             float* __restrict__ out) {
    __shared__ float sbuf[32];
    int row = blockIdx.x, i = threadIdx.x;
    float f = f_in[(size_t)row * D_ + i];
    float ss = block_reduce_sum(f * f, sbuf);
    float n  = fmaxf(sqrtf(ss), EPSF);
    float* orow = out + (size_t)row * (D_ + 1);
    orow[1 + i] = sinhf(n) * f / n;
    if (i == 0) orow[0] = coshf(n);
}

// ================= launch =================
extern "C" void kernel_launch(void* const* d_in, const int* /*in_sizes*/, int /*n_in*/,
                              void* d_out, int /*out_size*/) {
    const float* x     = (const float*)d_in[0];
    const float* g1    = (const float*)d_in[1];
    const float* beta1 = (const float*)d_in[2];
    const float* Wq    = (const float*)d_in[3];
    const float* Wk    = (const float*)d_in[4];
    const float* Wv    = (const float*)d_in[5];
    const float* Wo    = (const float*)d_in[6];
    const float* bq    = (const float*)d_in[7];
    const float* bk    = (const float*)d_in[8];
    const float* bv    = (const float*)d_in[9];
    const float* bo    = (const float*)d_in[10];
    const float* g2    = (const float*)d_in[11];
    const float* beta2 = (const float*)d_in[12];
    const float* W1    = (const float*)d_in[13];
    const float* bf1   = (const float*)d_in[14];
    const float* W2    = (const float*)d_in[15];
    const float* bf2   = (const float*)d_in[16];
    float* out = (float*)d_out;

    static bool attr_done = false;
    if (!attr_done) {
        cudaFuncSetAttribute(gemm_kernel<0>, cudaFuncAttributeMaxDynamicSharedMemorySize, GEMM_SMEM);
        cudaFuncSetAttribute(gemm_kernel<2>, cudaFuncAttributeMaxDynamicSharedMemorySize, GEMM_SMEM);
        cudaFuncSetAttribute(gemm_kernel<3>, cudaFuncAttributeMaxDynamicSharedMemorySize, GEMM_SMEM);
        attr_done = true;
    }

    __half *ta, *ha, *wqkv, *wo, *w1, *w2;
    float *q_, *k_, *v_, *kv_, *ks_, *bqkv_;
    cudaGetSymbolAddress((void**)&ta, g_ta);     cudaGetSymbolAddress((void**)&ha, g_ha);
    cudaGetSymbolAddress((void**)&q_, g_q);      cudaGetSymbolAddress((void**)&k_, g_k);
    cudaGetSymbolAddress((void**)&v_, g_v);
    cudaGetSymbolAddress((void**)&kv_, g_kv);    cudaGetSymbolAddress((void**)&ks_, g_ks);
    cudaGetSymbolAddress((void**)&wqkv, g_wqkv); cudaGetSymbolAddress((void**)&wo, g_wo);
    cudaGetSymbolAddress((void**)&w1, g_w1);     cudaGetSymbolAddress((void**)&w2, g_w2);
    cudaGetSymbolAddress((void**)&bqkv_, g_bqkv);

    // 0. all weight prep in ONE launch
    wsplit_all_kernel<<<3075, 256>>>(Wq, Wk, Wv, Wo, W1, W2, bq, bk, bv);

    // 1. pre: x -> t (tiled fp16 split)
    pre_kernel<<<NTOK, 256>>>(x, g1, beta1, ta);

    // 2. fused QKV projection
    dim3 gQKV(6, NTOK / 128);
    gemm_kernel<3><<<gQKV, 256, GEMM_SMEM>>>(ta, wqkv, bqkv_, q_, k_, v_, nullptr, 8, 768);

    // 3. linear attention
    kv_reduce_kernel<<<B_ * J_ * H_, 256>>>(k_, v_, kv_, ks_);
    attn_apply_kernel<<<B_ * J_ * H_, 256>>>(q_, kv_, ks_, ta);   // y -> ta (tiled)

    // 4. output projection: o = y @ Wo + bo -> q_ (fp32)
    dim3 gD(2, NTOK / 128);
    gemm_kernel<0><<<gD, 256, GEMM_SMEM>>>(ta, wo, bo, q_, nullptr, nullptr, nullptr, 8, D_);

    // 5. Lorentz residual + LN2 -> ta (tiled u2)
    resid_kernel<<<NTOK, 256>>>(x, q_, g2, beta2, ta);

    // 6. FFN
    dim3 gH(8, NTOK / 128);
    gemm_kernel<2><<<gH, 256, GEMM_SMEM>>>(ta, w1, bf1, nullptr, nullptr, nullptr, ha, 8, HID_);
    gemm_kernel<0><<<gD, 256, GEMM_SMEM>>>(ha, w2, bf2, q_, nullptr, nullptr, nullptr, 32, D_);

    // 7. final expmap0 -> out
    final_kernel<<<NTOK, 256>>>(q_, out);
}

// round 13
// speedup vs baseline: 1.5822x; 1.0003x over previous
#include <cuda_runtime.h>
#include <cuda_fp16.h>
#include <math.h>
#include <stdint.h>

#define B_ 8
#define T_ 512
#define J_ 26
#define D_ 256
#define H_ 8
#define DH_ 32
#define HID_ 1024
#define NTOK 106496            // B*T*J  (= 832 * 128 exactly)
#define EPSF 1e-6f

// ================= PTX helpers (base ISA: sm_90 bulk-async, sm_80 mma) =================
__device__ __forceinline__ uint32_t smem_u32(const void* p) {
    uint32_t a;
    asm("{ .reg .u64 t; cvta.to.shared.u64 t, %1; cvt.u32.u64 %0, t; }" : "=r"(a) : "l"(p));
    return a;
}
#define MBAR_INIT(addr, cnt) \
    asm volatile("mbarrier.init.shared.b64 [%0], %1;" :: "r"(addr), "r"(cnt) : "memory")
#define MBAR_EXPECT_TX(addr, bytes) \
    asm volatile("mbarrier.arrive.expect_tx.shared.b64 _, [%0], %1;" :: "r"(addr), "r"(bytes) : "memory")
#define MBAR_WAIT(addr, phase) do { \
    uint32_t _m = (addr), _p = (phase); \
    asm volatile("{\n\t.reg .pred P;\n\tWL_%=:\n\t" \
        "mbarrier.try_wait.parity.acquire.cta.shared::cta.b64 P, [%0], %1, 0x989680;\n\t" \
        "@P bra.uni WD_%=;\n\tbra.uni WL_%=;\n\tWD_%=:\n\t}" :: "r"(_m), "r"(_p) : "memory"); \
} while (0)
#define CP_BULK(dst, src, bytes, mbar) \
    asm volatile("cp.async.bulk.shared::cluster.global.mbarrier::complete_tx::bytes [%0], [%1], %2, [%3];" \
        :: "r"(dst), "l"(src), "r"(bytes), "r"(mbar) : "memory")

#define LDSM4(r0, r1, r2, r3, addr) \
    asm volatile("ldmatrix.sync.aligned.m8n8.x4.shared.b16 {%0,%1,%2,%3}, [%4];" \
        : "=r"(r0), "=r"(r1), "=r"(r2), "=r"(r3) : "r"(addr))

__device__ __forceinline__ void mma16816(float* c, const uint32_t* a, const uint32_t* b) {
    asm volatile(
        "mma.sync.aligned.m16n8k16.row.col.f32.f16.f16.f32 "
        "{%0,%1,%2,%3}, {%4,%5,%6,%7}, {%8,%9}, {%0,%1,%2,%3};"
        : "+f"(c[0]), "+f"(c[1]), "+f"(c[2]), "+f"(c[3])
        : "r"(a[0]), "r"(a[1]), "r"(a[2]), "r"(a[3]), "r"(b[0]), "r"(b[1]));
}

// ============ tiled layout: [mtile][ktile][hi|lo][128x32 swizzled] ============
// tile = 128 rows x 32 cols fp16 = 8192 B; hi+lo pair = 16384 B.
// elem(r, c) -> r*32 + ((cc ^ ((r>>1)&3))<<3) + (c&7), cc = (c>>3)&3
__device__ __forceinline__ size_t tiled_idx(int row, int col, int wKt) {
    int mt = row >> 7, r = row & 127, kt = col >> 5, c = col & 31;
    return ((size_t)(mt * wKt + kt) * 2) * 4096 + (size_t)(r * 32)
         + (size_t)(((((c >> 3) & 3) ^ ((r >> 1) & 3)) << 3) + (c & 7));
}

// ================= scratch (static device .bss) =================
__device__ __half g_ta [(size_t)NTOK * D_ * 2];    // t / y / u2, tiled hi|lo, wKt=8
__device__ __half g_ha [(size_t)NTOK * HID_ * 2];  // FFN hidden, tiled hi|lo, wKt=32
__device__ float  g_q  [(size_t)NTOK * D_];        // pq / o / f
__device__ float  g_k  [(size_t)NTOK * D_];        // pk
__device__ float  g_v  [(size_t)NTOK * D_];        // v
__device__ float g_kv [(size_t)B_ * J_ * H_ * DH_ * DH_];
__device__ float g_ks [(size_t)B_ * J_ * H_ * DH_];
// weights, tiled hi|lo pairs (only hi consumed as B operand)
__device__ __half g_wqkv[768 * D_ * 2];      // 6 ntiles, wKt=8
__device__ __half g_wo  [D_ * D_ * 2];       // 2 ntiles, wKt=8
__device__ __half g_w1  [HID_ * D_ * 2];     // 8 ntiles, wKt=8
__device__ __half g_w2  [D_ * HID_ * 2];     // 2 ntiles, wKt=32
__device__ float g_bqkv[768];

// ================= small helpers =================
__device__ __forceinline__ float block_reduce_sum(float v, float* sbuf) {
    int lane = threadIdx.x & 31, w = threadIdx.x >> 5;
    #pragma unroll
    for (int o = 16; o; o >>= 1) v += __shfl_down_sync(0xffffffffu, v, o);
    if (lane == 0) sbuf[w] = v;
    __syncthreads();
    float r = (threadIdx.x < 8) ? sbuf[threadIdx.x] : 0.f;
    if (w == 0) {
        r += __shfl_down_sync(0xffffffffu, r, 4);
        r += __shfl_down_sync(0xffffffffu, r, 2);
        r += __shfl_down_sync(0xffffffffu, r, 1);
        if (lane == 0) sbuf[0] = r;
    }
    __syncthreads();
    float res = sbuf[0];
    __syncthreads();
    return res;
}
__device__ __forceinline__ void split_store_tiled(__half* base, int row, int col,
                                                  int wKt, float v) {
    size_t idx = tiled_idx(row, col, wKt);
    __half h = __float2half(v);
    base[idx] = h;
    base[idx + 4096] = __float2half(v - __half2float(h));
}

// ============ weight prep: transpose + split + tile, one launch ============
__global__ void wsplit_all_kernel(const float* __restrict__ Wq, const float* __restrict__ Wk,
                                  const float* __restrict__ Wv, const float* __restrict__ Wo,
                                  const float* __restrict__ W1, const float* __restrict__ W2,
                                  const float* __restrict__ bq, const float* __restrict__ bk,
                                  const float* __restrict__ bv) {
    int idx = blockIdx.x * 256 + threadIdx.x;
    if (idx < 196608) {
        int wsel = idx >> 16;
        int local = idx & 65535;
        const float* W = (wsel == 0) ? Wq : (wsel == 1) ? Wk : Wv;
        int k = local >> 8, n = local & 255;
        split_store_tiled(g_wqkv, wsel * 256 + n, k, 8, W[local]);
    } else if (idx < 262144) {
        int local = idx - 196608;
        int k = local >> 8, n = local & 255;
        split_store_tiled(g_wo, n, k, 8, Wo[local]);
    } else if (idx < 524288) {
        int local = idx - 262144;
        int k = local >> 10, n = local & 1023;
        split_store_tiled(g_w1, n, k, 8, W1[local]);
    } else if (idx < 786432) {
        int local = idx - 524288;
        int k = local >> 8, n = local & 255;
        split_store_tiled(g_w2, n, k, 32, W2[local]);
    } else if (idx < 787200) {
        int bi = idx - 786432;
        g_bqkv[bi] = (bi < 256) ? bq[bi] : (bi < 512) ? bk[bi - 256] : bv[bi - 512];
    }
}

// ============ K1: t = layernorm(logmap0(x)) -> tiled fp16 hi/lo ============
// (expmap0 -> logmap0 round-trip in the reference is the identity; skipped)
__global__ void pre_kernel(const float* __restrict__ x,
                           const float* __restrict__ g1,
                           const float* __restrict__ b1,
                           __half* __restrict__ ta) {
    __shared__ float sbuf[32];
    int row = blockIdx.x, i = threadIdx.x;
    const float* xr = x + (size_t)row * (D_ + 1);
    float xi = xr[1 + i];
    float ss = block_reduce_sum(xi * xi, sbuf);
    float n  = fmaxf(sqrtf(ss), EPSF);
    float x0 = fmaxf(xr[0], 1.0f + 1e-7f);
    float u  = acoshf(x0) * xi / n;
    float s1 = block_reduce_sum(u, sbuf);
    float s2 = block_reduce_sum(u * u, sbuf);
    float mean = s1 * (1.f / D_);
    float var  = s2 * (1.f / D_) - mean * mean;
    float tv = (u - mean) * rsqrtf(var + 1e-5f) * g1[i] + b1[i];
    split_store_tiled(ta, row, i, 8, tv);
}

// ============ HMMA split-fp16 2-pass GEMM, 3-stage bulk-async pipeline ============
// C = (Ah + Al) @ Bh^T + bias (fp32 accum).  Dropped A@Bl: rel ~2^-11.
// MODE 0: fp32 out, no act.  MODE 2: tiled fp16 hi/lo out, gelu.
// MODE 3: fused QKV (route by nBase, elu for Q/K), fp32 out.
#define NSTG 3
#define STAGE_DATA 24576                     // Ah 8K | Al 8K | Bh 8K
#define GEMM_SMEM (64 + NSTG * STAGE_DATA)   // 73792 B -> 2 CTAs/SM

template<int MODE>
__global__ __launch_bounds__(256) void gemm_kernel(
    const __half* __restrict__ A,     // tiled pairs, wKt = nkt
    const __half* __restrict__ Bw,    // tiled pairs (hi used), wKt = nkt
    const float* __restrict__ bias,
    float* __restrict__ Cf, float* __restrict__ Cf2, float* __restrict__ Cf3,
    __half* __restrict__ Ct,          // tiled out (MODE 2)
    int nkt, int NC)
{
    extern __shared__ char smem[];
    const uint32_t sb = smem_u32(smem);
    const int tid  = threadIdx.x;
    const int lane = tid & 31;
    const int w    = tid >> 5;
    const int mTile = blockIdx.y;
    const int nTile = blockIdx.x;
    const int mBase = mTile * 128;
    const int nBase = nTile * 128;
    const int wm = (w & 3) * 32;
    const int wn = (w >> 2) * 64;

    if (tid == 0) { MBAR_INIT(sb, 1); MBAR_INIT(sb + 8, 1); MBAR_INIT(sb + 16, 1); }
    __syncthreads();

    const char* Ab = (const char*)A + (size_t)mTile * nkt * 16384;
    const char* Bb = (const char*)Bw + (size_t)nTile * nkt * 16384;

    auto issue = [&](int kt, int s) {
        uint32_t mb = sb + (uint32_t)s * 8;
        uint32_t d  = sb + 64 + (uint32_t)s * STAGE_DATA;
        MBAR_EXPECT_TX(mb, 24576);
        CP_BULK(d,         Ab + (size_t)kt * 16384, 16384u, mb);   // Ah+Al pair
        CP_BULK(d + 16384, Bb + (size_t)kt * 16384, 8192u,  mb);   // Bh only
    };
    if (tid == 0) {
        issue(0, 0);
        if (nkt > 1) issue(1, 1);
    }

    float acc[2][8][4];
    #pragma unroll
    for (int mt = 0; mt < 2; mt++)
        #pragma unroll
        for (int nt = 0; nt < 8; nt++)
            #pragma unroll
            for (int i = 0; i < 4; i++) acc[mt][nt][i] = 0.f;

    const int aRow = lane & 15;
    const int aSel = lane >> 4;

    for (int kt = 0; kt < nkt; kt++) {
        int s = kt % NSTG;
        if (tid == 0) {
            int pf = kt + 2;
            if (pf < nkt) issue(pf, pf % NSTG);
        }
        MBAR_WAIT(sb + (uint32_t)s * 8, (kt / NSTG) & 1);

        uint32_t sbase = sb + 64 + (uint32_t)s * STAGE_DATA;
        uint32_t aHb = sbase;
        uint32_t aLb = sbase + 8192;
        uint32_t bHb = sbase + 16384;

        #pragma unroll
        for (int kk = 0; kk < 2; kk++) {
            uint32_t bH[8][2];
            #pragma unroll
            for (int p = 0; p < 4; p++) {
                int row = wn + p * 16 + (lane & 15);
                int cc  = 2 * kk + (lane >> 4);
                uint32_t off = (uint32_t)(row * 64 + ((cc ^ ((row >> 1) & 3)) << 4));
                uint32_t q0, q1, q2, q3;
                LDSM4(q0, q1, q2, q3, bHb + off);
                bH[2*p][0] = q0; bH[2*p+1][0] = q1; bH[2*p][1] = q2; bH[2*p+1][1] = q3;
            }
            #pragma unroll
            for (int mt = 0; mt < 2; mt++) {
                int row = wm + mt * 16 + aRow;
                int cc  = 2 * kk + aSel;
                uint32_t off = (uint32_t)(row * 64 + ((cc ^ ((row >> 1) & 3)) << 4));
                uint32_t aH[4], aL[4];
                LDSM4(aH[0], aH[1], aH[2], aH[3], aHb + off);
                LDSM4(aL[0], aL[1], aL[2], aL[3], aLb + off);
                #pragma unroll
                for (int nt = 0; nt < 8; nt++) mma16816(acc[mt][nt], aH, bH[nt]);
                #pragma unroll
                for (int nt = 0; nt < 8; nt++) mma16816(acc[mt][nt], aL, bH[nt]);
            }
        }
        __syncthreads();   // all warps done with slot s -> legalizes refill at kt+2
    }

    // ---------------- epilogue ----------------
    const int gid = lane >> 2;
    const int tig = lane & 3;
    int which = 0; float* dstQKV = Cf; bool eluAct = false; int nLoc = nBase;
    if (MODE == 3) {
        which = nBase >> 8;
        dstQKV = (which == 0) ? Cf : (which == 1) ? Cf2 : Cf3;
        eluAct = (which < 2);
        nLoc = nBase - which * 256;
    }
    #pragma unroll
    for (int mt = 0; mt < 2; mt++) {
        #pragma unroll
        for (int nt = 0; nt < 8; nt++) {
            int colT = wn + nt * 8 + tig * 2;
            float b0 = bias[nBase + colT], b1 = bias[nBase + colT + 1];
            #pragma unroll
            for (int half = 0; half < 2; half++) {
                int row = mBase + wm + mt * 16 + gid + half * 8;
                float v0 = acc[mt][nt][half * 2 + 0] + b0;
                float v1 = acc[mt][nt][half * 2 + 1] + b1;
                if (MODE == 3 && eluAct) {
                    v0 = (v0 > 0.f) ? (v0 + 1.f) : __expf(v0);
                    v1 = (v1 > 0.f) ? (v1 + 1.f) : __expf(v1);
                } else if (MODE == 2) {
                    float c0 = v0 * v0 * v0;
                    v0 = 0.5f * v0 * (1.f + tanhf(0.7978845608028654f * (v0 + 0.044715f * c0)));
                    float c1 = v1 * v1 * v1;
                    v1 = 0.5f * v1 * (1.f + tanhf(0.7978845608028654f * (v1 + 0.044715f * c1)));
                }
                if (MODE == 2) {
                    size_t idx = tiled_idx(row, nBase + colT, NC >> 5);
                    __half h0 = __float2half(v0);
                    __half h1 = __float2half(v1);
                    __half l0 = __float2half(v0 - __half2float(h0));
                    __half l1 = __float2half(v1 - __half2float(h1));
                    uint32_t hp = ((uint32_t)__half_as_ushort(h1) << 16) | __half_as_ushort(h0);
                    uint32_t lp = ((uint32_t)__half_as_ushort(l1) << 16) | __half_as_ushort(l0);
                    *reinterpret_cast<uint32_t*>(Ct + idx) = hp;
                    *reinterpret_cast<uint32_t*>(Ct + idx + 4096) = lp;
                } else if (MODE == 3) {
                    size_t base = (size_t)row * 256 + nLoc + colT;
                    *reinterpret_cast<float2*>(dstQKV + base) = make_float2(v0, v1);
                } else {
                    size_t base = (size_t)row * NC + nBase + colT;
                    *reinterpret_cast<float2*>(Cf + base) = make_float2(v0, v1);
                }
            }
        }
    }
}

// ============ K3: kv / ksum via per-warp shuffle outer-product ============
__global__ void kv_reduce_kernel(const float* __restrict__ pk,
                                 const float* __restrict__ v,
                                 float* __restrict__ kv,
                                 float* __restrict__ ksum) {
    int bh = blockIdx.x;
    int h  = bh % H_;
    int bj = bh / H_;
    int j  = bj % J_;
    int b  = bj / J_;
    int tid = threadIdx.x, lane = tid & 31, w = tid >> 5;

    float acc[32];
    #pragma unroll
    for (int k = 0; k < 32; k++) acc[k] = 0.f;
    float ks = 0.f;

    for (int t = w; t < T_; t += 8) {
        size_t base = (((size_t)(b * T_ + t) * J_) + j) * D_ + h * DH_ + lane;
        float pkv = pk[base];
        float vv  = v[base];
        ks += pkv;
        #pragma unroll
        for (int k = 0; k < 32; k++)
            acc[k] += __shfl_sync(0xffffffffu, pkv, k) * vv;
    }

    __shared__ float red[8][32][32];
    __shared__ float rks[8][32];
    #pragma unroll
    for (int k = 0; k < 32; k++) red[w][k][lane] = acc[k];
    rks[w][lane] = ks;
    __syncthreads();

    #pragma unroll
    for (int kk = 0; kk < 4; kk++) {
        int k = w * 4 + kk;
        float s = 0.f;
        #pragma unroll
        for (int ww = 0; ww < 8; ww++) s += red[ww][k][lane];
        kv[(size_t)bh * (DH_ * DH_) + k * 32 + lane] = s;
    }
    if (w == 0) {
        float s = 0.f;
        #pragma unroll
        for (int ww = 0; ww < 8; ww++) s += rks[ww][lane];
        ksum[(size_t)bh * DH_ + lane] = s;
    }
}

// ============ K4: y = (pq @ kv) / (pq . ksum + EPS) -> tiled fp16 hi/lo ============
__global__ void attn_apply_kernel(const float* __restrict__ pq,
                                  const float* __restrict__ kv,
                                  const float* __restrict__ ksum,
                                  __half* __restrict__ ya) {
    int bh = blockIdx.x;
    int h  = bh % H_;
    int bj = bh / H_;
    int j  = bj % J_;
    int b  = bj / J_;
    __shared__ float skv[DH_ * DH_];
    __shared__ float sks[DH_];
    int tid = threadIdx.x;
    for (int i = tid; i < DH_ * DH_; i += 256) skv[i] = kv[(size_t)bh * (DH_ * DH_) + i];
    if (tid < DH_) sks[tid] = ksum[(size_t)bh * DH_ + tid];
    __syncthreads();
    int lane = tid & 31, w = tid >> 5;
    for (int t = w; t < T_; t += 8) {
        int token = (b * T_ + t) * J_ + j;
        size_t baseQ = (size_t)token * D_ + h * DH_;
        float q = pq[baseQ + lane];
        float den = q * sks[lane];
        #pragma unroll
        for (int o = 16; o; o >>= 1) den += __shfl_xor_sync(0xffffffffu, den, o);
        float num = 0.f;
        #pragma unroll
        for (int k = 0; k < 32; k++)
            num += __shfl_sync(0xffffffffu, q, k) * skv[k * 32 + lane];
        split_store_tiled(ya, token, h * DH_ + lane, 8, num / (den + EPSF));
    }
}

// ============ K5: residual + LN2 -> tiled fp16 hi/lo ============
__global__ void resid_kernel(const float* __restrict__ x,
                             const float* __restrict__ o_in,
                             const float* __restrict__ g2,
                             const float* __restrict__ b2,
                             __half* __restrict__ ua) {
    __shared__ float sbuf[32];
    int row = blockIdx.x, i = threadIdx.x;
    const float* xr = x + (size_t)row * (D_ + 1);
    float o = o_in[(size_t)row * D_ + i];
    float so = block_reduce_sum(o * o, sbuf);
    float n  = fmaxf(sqrtf(so), EPSF);
    float z  = sinhf(n) * o / n;
    float m  = xr[1 + i] + z;
    float sm = block_reduce_sum(m * m, sbuf);
    float m0 = xr[0] + coshf(n);
    float mink = -m0 * m0 + sm;
    float inv  = rsqrtf(fmaxf(-mink, EPSF));
    float h0   = m0 * inv;
    float hs   = m * inv;
    float hn   = fmaxf(sqrtf(sm) * inv, EPSF);
    float u    = acoshf(fmaxf(h0, 1.0f + 1e-7f)) * hs / hn;
    float s1 = block_reduce_sum(u, sbuf);
    float s2 = block_reduce_sum(u * u, sbuf);
    float mean = s1 * (1.f / D_);
    float var  = s2 * (1.f / D_) - mean * mean;
    float uv = (u - mean) * rsqrtf(var + 1e-5f) * g2[i] + b2[i];
    split_store_tiled(ua, row, i, 8, uv);
}

// ============ K6: out = expmap0(f) ============
__global__ void final_kernel(const float* __restrict__ f_in,
                             float* __restrict__ out) {
    __shared__ float sbuf[32];
    int row = blockIdx.x, i = threadIdx.x;
    float f = f_in[(size_t)row * D_ + i];
    float ss = block_reduce_sum(f * f, sbuf);
    float n  = fmaxf(sqrtf(ss), EPSF);
    float* orow = out + (size_t)row * (D_ + 1);
    orow[1 + i] = sinhf(n) * f / n;
    if (i == 0) orow[0] = coshf(n);
}

// ================= launch =================
extern "C" void kernel_launch(void* const* d_in, const int* /*in_sizes*/, int /*n_in*/,
                              void* d_out, int /*out_size*/) {
    const float* x     = (const float*)d_in[0];
    const float* g1    = (const float*)d_in[1];
    const float* beta1 = (const float*)d_in[2];
    const float* Wq    = (const float*)d_in[3];
    const float* Wk    = (const float*)d_in[4];
    const float* Wv    = (const float*)d_in[5];
    const float* Wo    = (const float*)d_in[6];
    const float* bq    = (const float*)d_in[7];
    const float* bk    = (const float*)d_in[8];
    const float* bv    = (const float*)d_in[9];
    const float* bo    = (const float*)d_in[10];
    const float* g2    = (const float*)d_in[11];
    const float* beta2 = (const float*)d_in[12];
    const float* W1    = (const float*)d_in[13];
    const float* bf1   = (const float*)d_in[14];
    const float* W2    = (const float*)d_in[15];
    const float* bf2   = (const float*)d_in[16];
    float* out = (float*)d_out;

    static bool attr_done = false;
    if (!attr_done) {
        cudaFuncSetAttribute(gemm_kernel<0>, cudaFuncAttributeMaxDynamicSharedMemorySize, GEMM_SMEM);
        cudaFuncSetAttribute(gemm_kernel<2>, cudaFuncAttributeMaxDynamicSharedMemorySize, GEMM_SMEM);
        cudaFuncSetAttribute(gemm_kernel<3>, cudaFuncAttributeMaxDynamicSharedMemorySize, GEMM_SMEM);
        attr_done = true;
    }

    __half *ta, *ha, *wqkv, *wo, *w1, *w2;
    float *q_, *k_, *v_, *kv_, *ks_, *bqkv_;
    cudaGetSymbolAddress((void**)&ta, g_ta);     cudaGetSymbolAddress((void**)&ha, g_ha);
    cudaGetSymbolAddress((void**)&q_, g_q);      cudaGetSymbolAddress((void**)&k_, g_k);
    cudaGetSymbolAddress((void**)&v_, g_v);
    cudaGetSymbolAddress((void**)&kv_, g_kv);    cudaGetSymbolAddress((void**)&ks_, g_ks);
    cudaGetSymbolAddress((void**)&wqkv, g_wqkv); cudaGetSymbolAddress((void**)&wo, g_wo);
    cudaGetSymbolAddress((void**)&w1, g_w1);     cudaGetSymbolAddress((void**)&w2, g_w2);
    cudaGetSymbolAddress((void**)&bqkv_, g_bqkv);

    // 0. all weight prep in ONE launch
    wsplit_all_kernel<<<3075, 256>>>(Wq, Wk, Wv, Wo, W1, W2, bq, bk, bv);

    // 1. pre: x -> t (tiled fp16 split)
    pre_kernel<<<NTOK, 256>>>(x, g1, beta1, ta);

    // 2. fused QKV projection
    dim3 gQKV(6, NTOK / 128);
    gemm_kernel<3><<<gQKV, 256, GEMM_SMEM>>>(ta, wqkv, bqkv_, q_, k_, v_, nullptr, 8, 768);

    // 3. linear attention
    kv_reduce_kernel<<<B_ * J_ * H_, 256>>>(k_, v_, kv_, ks_);
    attn_apply_kernel<<<B_ * J_ * H_, 256>>>(q_, kv_, ks_, ta);   // y -> ta (tiled)

    // 4. output projection: o = y @ Wo + bo -> q_ (fp32)
    dim3 gD(2, NTOK / 128);
    gemm_kernel<0><<<gD, 256, GEMM_SMEM>>>(ta, wo, bo, q_, nullptr, nullptr, nullptr, 8, D_);

    // 5. Lorentz residual + LN2 -> ta (tiled u2)
    resid_kernel<<<NTOK, 256>>>(x, q_, g2, beta2, ta);

    // 6. FFN
    dim3 gH(8, NTOK / 128);
    gemm_kernel<2><<<gH, 256, GEMM_SMEM>>>(ta, w1, bf1, nullptr, nullptr, nullptr, ha, 8, HID_);
    gemm_kernel<0><<<gD, 256, GEMM_SMEM>>>(ha, w2, bf2, q_, nullptr, nullptr, nullptr, 32, D_);

    // 7. final expmap0 -> out
    final_kernel<<<NTOK, 256>>>(q_, out);
}

// round 14
// speedup vs baseline: 1.5834x; 1.0007x over previous
#include <cuda_runtime.h>
#include <cuda_fp16.h>
#include <math.h>
#include <stdint.h>

#define B_ 8
#define T_ 512
#define J_ 26
#define D_ 256
#define H_ 8
#define DH_ 32
#define HID_ 1024
#define NTOK 106496            // B*T*J  (= 832 * 128 exactly)
#define EPSF 1e-6f

// ================= PTX helpers (base ISA: sm_90 bulk-async, sm_80 mma) =================
__device__ __forceinline__ uint32_t smem_u32(const void* p) {
    uint32_t a;
    asm("{ .reg .u64 t; cvta.to.shared.u64 t, %1; cvt.u32.u64 %0, t; }" : "=r"(a) : "l"(p));
    return a;
}
#define MBAR_INIT(addr, cnt) \
    asm volatile("mbarrier.init.shared.b64 [%0], %1;" :: "r"(addr), "r"(cnt) : "memory")
#define MBAR_EXPECT_TX(addr, bytes) \
    asm volatile("mbarrier.arrive.expect_tx.shared.b64 _, [%0], %1;" :: "r"(addr), "r"(bytes) : "memory")
#define MBAR_WAIT(addr, phase) do { \
    uint32_t _m = (addr), _p = (phase); \
    asm volatile("{\n\t.reg .pred P;\n\tWL_%=:\n\t" \
        "mbarrier.try_wait.parity.acquire.cta.shared::cta.b64 P, [%0], %1, 0x989680;\n\t" \
        "@P bra.uni WD_%=;\n\tbra.uni WL_%=;\n\tWD_%=:\n\t}" :: "r"(_m), "r"(_p) : "memory"); \
} while (0)
#define CP_BULK(dst, src, bytes, mbar) \
    asm volatile("cp.async.bulk.shared::cluster.global.mbarrier::complete_tx::bytes [%0], [%1], %2, [%3];" \
        :: "r"(dst), "l"(src), "r"(bytes), "r"(mbar) : "memory")

#define LDSM4(r0, r1, r2, r3, addr) \
    asm volatile("ldmatrix.sync.aligned.m8n8.x4.shared.b16 {%0,%1,%2,%3}, [%4];" \
        : "=r"(r0), "=r"(r1), "=r"(r2), "=r"(r3) : "r"(addr))

__device__ __forceinline__ void mma16816(float* c, const uint32_t* a, const uint32_t* b) {
    asm volatile(
        "mma.sync.aligned.m16n8k16.row.col.f32.f16.f16.f32 "
        "{%0,%1,%2,%3}, {%4,%5,%6,%7}, {%8,%9}, {%0,%1,%2,%3};"
        : "+f"(c[0]), "+f"(c[1]), "+f"(c[2]), "+f"(c[3])
        : "r"(a[0]), "r"(a[1]), "r"(a[2]), "r"(a[3]), "r"(b[0]), "r"(b[1]));
}

// ============ tiled layout: [mtile][ktile][hi|lo][128x32 swizzled] ============
// tile = 128 rows x 32 cols fp16 = 8192 B; hi+lo pair = 16384 B.
// elem(r, c) -> r*32 + ((cc ^ ((r>>1)&3))<<3) + (c&7), cc = (c>>3)&3
__device__ __forceinline__ size_t tiled_idx(int row, int col, int wKt) {
    int mt = row >> 7, r = row & 127, kt = col >> 5, c = col & 31;
    return ((size_t)(mt * wKt + kt) * 2) * 4096 + (size_t)(r * 32)
         + (size_t)(((((c >> 3) & 3) ^ ((r >> 1) & 3)) << 3) + (c & 7));
}

// ================= scratch (static device .bss) =================
__device__ __half g_ta [(size_t)NTOK * D_ * 2];    // t / y / u2, tiled hi|lo, wKt=8
__device__ __half g_ha [(size_t)NTOK * HID_ * 2];  // FFN hidden, tiled hi|lo, wKt=32
__device__ float  g_q  [(size_t)NTOK * D_];        // pq / o / f
__device__ float  g_k  [(size_t)NTOK * D_];        // pk
__device__ float  g_v  [(size_t)NTOK * D_];        // v
__device__ float g_kv [(size_t)B_ * J_ * H_ * DH_ * DH_];
__device__ float g_ks [(size_t)B_ * J_ * H_ * DH_];
// weights, tiled hi|lo pairs (only hi consumed as B operand)
__device__ __half g_wqkv[768 * D_ * 2];      // 6 ntiles, wKt=8
__device__ __half g_wo  [D_ * D_ * 2];       // 2 ntiles, wKt=8
__device__ __half g_w1  [HID_ * D_ * 2];     // 8 ntiles, wKt=8
__device__ __half g_w2  [D_ * HID_ * 2];     // 2 ntiles, wKt=32
__device__ float g_bqkv[768];

// ================= small helpers =================
__device__ __forceinline__ float block_reduce_sum(float v, float* sbuf) {
    int lane = threadIdx.x & 31, w = threadIdx.x >> 5;
    #pragma unroll
    for (int o = 16; o; o >>= 1) v += __shfl_down_sync(0xffffffffu, v, o);
    if (lane == 0) sbuf[w] = v;
    __syncthreads();
    float r = (threadIdx.x < 8) ? sbuf[threadIdx.x] : 0.f;
    if (w == 0) {
        r += __shfl_down_sync(0xffffffffu, r, 4);
        r += __shfl_down_sync(0xffffffffu, r, 2);
        r += __shfl_down_sync(0xffffffffu, r, 1);
        if (lane == 0) sbuf[0] = r;
    }
    __syncthreads();
    float res = sbuf[0];
    __syncthreads();
    return res;
}
__device__ __forceinline__ void split_store_tiled(__half* base, int row, int col,
                                                  int wKt, float v) {
    size_t idx = tiled_idx(row, col, wKt);
    __half h = __float2half(v);
    base[idx] = h;
    base[idx + 4096] = __float2half(v - __half2float(h));
}

// ============ weight prep: transpose + split + tile, one launch ============
__global__ void wsplit_all_kernel(const float* __restrict__ Wq, const float* __restrict__ Wk,
                                  const float* __restrict__ Wv, const float* __restrict__ Wo,
                                  const float* __restrict__ W1, const float* __restrict__ W2,
                                  const float* __restrict__ bq, const float* __restrict__ bk,
                                  const float* __restrict__ bv) {
    int idx = blockIdx.x * 256 + threadIdx.x;
    if (idx < 196608) {
        int wsel = idx >> 16;
        int local = idx & 65535;
        const float* W = (wsel == 0) ? Wq : (wsel == 1) ? Wk : Wv;
        int k = local >> 8, n = local & 255;
        split_store_tiled(g_wqkv, wsel * 256 + n, k, 8, W[local]);
    } else if (idx < 262144) {
        int local = idx - 196608;
        int k = local >> 8, n = local & 255;
        split_store_tiled(g_wo, n, k, 8, Wo[local]);
    } else if (idx < 524288) {
        int local = idx - 262144;
        int k = local >> 10, n = local & 1023;
        split_store_tiled(g_w1, n, k, 8, W1[local]);
    } else if (idx < 786432) {
        int local = idx - 524288;
        int k = local >> 8, n = local & 255;
        split_store_tiled(g_w2, n, k, 32, W2[local]);
    } else if (idx < 787200) {
        int bi = idx - 786432;
        g_bqkv[bi] = (bi < 256) ? bq[bi] : (bi < 512) ? bk[bi - 256] : bv[bi - 512];
    }
}

// ============ K1: t = layernorm(logmap0(x)) -> tiled fp16 hi/lo ============
// (expmap0 -> logmap0 round-trip in the reference is the identity; skipped)
__global__ void pre_kernel(const float* __restrict__ x,
                           const float* __restrict__ g1,
                           const float* __restrict__ b1,
                           __half* __restrict__ ta) {
    __shared__ float sbuf[32];
    int row = blockIdx.x, i = threadIdx.x;
    const float* xr = x + (size_t)row * (D_ + 1);
    float xi = xr[1 + i];
    float ss = block_reduce_sum(xi * xi, sbuf);
    float n  = fmaxf(sqrtf(ss), EPSF);
    float x0 = fmaxf(xr[0], 1.0f + 1e-7f);
    float u  = acoshf(x0) * xi / n;
    float s1 = block_reduce_sum(u, sbuf);
    float s2 = block_reduce_sum(u * u, sbuf);
    float mean = s1 * (1.f / D_);
    float var  = s2 * (1.f / D_) - mean * mean;
    float tv = (u - mean) * rsqrtf(var + 1e-5f) * g1[i] + b1[i];
    split_store_tiled(ta, row, i, 8, tv);
}

// ============ HMMA split-fp16 2-pass GEMM, 3-stage bulk-async pipeline ============
// C = (Ah + Al) @ Bh^T + bias (fp32 accum).  Dropped A@Bl: rel ~2^-11.
// MODE 0: fp32 out, no act.  MODE 2: tiled fp16 hi/lo out, gelu.
// MODE 3: fused QKV (route by nBase, elu for Q/K), fp32 out.
#define NSTG 3
#define STAGE_DATA 24576                     // Ah 8K | Al 8K | Bh 8K
#define GEMM_SMEM (64 + NSTG * STAGE_DATA)   // 73792 B -> 2 CTAs/SM

template<int MODE>
__global__ __launch_bounds__(256) void gemm_kernel(
    const __half* __restrict__ A,     // tiled pairs, wKt = nkt
    const __half* __restrict__ Bw,    // tiled pairs (hi used), wKt = nkt
    const float* __restrict__ bias,
    float* __restrict__ Cf, float* __restrict__ Cf2, float* __restrict__ Cf3,
    __half* __restrict__ Ct,          // tiled out (MODE 2)
    int nkt, int NC)
{
    extern __shared__ char smem[];
    const uint32_t sb = smem_u32(smem);
    const int tid  = threadIdx.x;
    const int lane = tid & 31;
    const int w    = tid >> 5;
    const int mTile = blockIdx.y;
    const int nTile = blockIdx.x;
    const int mBase = mTile * 128;
    const int nBase = nTile * 128;
    const int wm = (w & 3) * 32;
    const int wn = (w >> 2) * 64;

    if (tid == 0) { MBAR_INIT(sb, 1); MBAR_INIT(sb + 8, 1); MBAR_INIT(sb + 16, 1); }
    __syncthreads();

    const char* Ab = (const char*)A + (size_t)mTile * nkt * 16384;
    const char* Bb = (const char*)Bw + (size_t)nTile * nkt * 16384;

    auto issue = [&](int kt, int s) {
        uint32_t mb = sb + (uint32_t)s * 8;
        uint32_t d  = sb + 64 + (uint32_t)s * STAGE_DATA;
        MBAR_EXPECT_TX(mb, 24576);
        CP_BULK(d,         Ab + (size_t)kt * 16384, 16384u, mb);   // Ah+Al pair
        CP_BULK(d + 16384, Bb + (size_t)kt * 16384, 8192u,  mb);   // Bh only
    };
    if (tid == 0) {
        issue(0, 0);
        if (nkt > 1) issue(1, 1);
    }

    float acc[2][8][4];
    #pragma unroll
    for (int mt = 0; mt < 2; mt++)
        #pragma unroll
        for (int nt = 0; nt < 8; nt++)
            #pragma unroll
            for (int i = 0; i < 4; i++) acc[mt][nt][i] = 0.f;

    const int aRow = lane & 15;
    const int aSel = lane >> 4;

    for (int kt = 0; kt < nkt; kt++) {
        int s = kt % NSTG;
        if (tid == 0) {
            int pf = kt + 2;
            if (pf < nkt) issue(pf, pf % NSTG);
        }
        MBAR_WAIT(sb + (uint32_t)s * 8, (kt / NSTG) & 1);

        uint32_t sbase = sb + 64 + (uint32_t)s * STAGE_DATA;
        uint32_t aHb = sbase;
        uint32_t aLb = sbase + 8192;
        uint32_t bHb = sbase + 16384;

        #pragma unroll
        for (int kk = 0; kk < 2; kk++) {
            uint32_t bH[8][2];
            #pragma unroll
            for (int p = 0; p < 4; p++) {
                int row = wn + p * 16 + (lane & 15);
                int cc  = 2 * kk + (lane >> 4);
                uint32_t off = (uint32_t)(row * 64 + ((cc ^ ((row >> 1) & 3)) << 4));
                uint32_t q0, q1, q2, q3;
                LDSM4(q0, q1, q2, q3, bHb + off);
                bH[2*p][0] = q0; bH[2*p+1][0] = q1; bH[2*p][1] = q2; bH[2*p+1][1] = q3;
            }
            #pragma unroll
            for (int mt = 0; mt < 2; mt++) {
                int row = wm + mt * 16 + aRow;
                int cc  = 2 * kk + aSel;
                uint32_t off = (uint32_t)(row * 64 + ((cc ^ ((row >> 1) & 3)) << 4));
                uint32_t aH[4], aL[4];
                LDSM4(aH[0], aH[1], aH[2], aH[3], aHb + off);
                LDSM4(aL[0], aL[1], aL[2], aL[3], aLb + off);
                #pragma unroll
                for (int nt = 0; nt < 8; nt++) mma16816(acc[mt][nt], aH, bH[nt]);
                #pragma unroll
                for (int nt = 0; nt < 8; nt++) mma16816(acc[mt][nt], aL, bH[nt]);
            }
        }
        __syncthreads();   // all warps done with slot s -> legalizes refill at kt+2
    }

    // ---------------- epilogue ----------------
    const int gid = lane >> 2;
    const int tig = lane & 3;
    int which = 0; float* dstQKV = Cf; bool eluAct = false; int nLoc = nBase;
    if (MODE == 3) {
        which = nBase >> 8;
        dstQKV = (which == 0) ? Cf : (which == 1) ? Cf2 : Cf3;
        eluAct = (which < 2);
        nLoc = nBase - which * 256;
    }
    #pragma unroll
    for (int mt = 0; mt < 2; mt++) {
        #pragma unroll
        for (int nt = 0; nt < 8; nt++) {
            int colT = wn + nt * 8 + tig * 2;
            float b0 = bias[nBase + colT], b1 = bias[nBase + colT + 1];
            #pragma unroll
            for (int half = 0; half < 2; half++) {
                int row = mBase + wm + mt * 16 + gid + half * 8;
                float v0 = acc[mt][nt][half * 2 + 0] + b0;
                float v1 = acc[mt][nt][half * 2 + 1] + b1;
                if (MODE == 3 && eluAct) {
                    v0 = (v0 > 0.f) ? (v0 + 1.f) : __expf(v0);
                    v1 = (v1 > 0.f) ? (v1 + 1.f) : __expf(v1);
                } else if (MODE == 2) {
                    float c0 = v0 * v0 * v0;
                    v0 = 0.5f * v0 * (1.f + tanhf(0.7978845608028654f * (v0 + 0.044715f * c0)));
                    float c1 = v1 * v1 * v1;
                    v1 = 0.5f * v1 * (1.f + tanhf(0.7978845608028654f * (v1 + 0.044715f * c1)));
                }
                if (MODE == 2) {
                    size_t idx = tiled_idx(row, nBase + colT, NC >> 5);
                    __half h0 = __float2half(v0);
                    __half h1 = __float2half(v1);
                    __half l0 = __float2half(v0 - __half2float(h0));
                    __half l1 = __float2half(v1 - __half2float(h1));
                    uint32_t hp = ((uint32_t)__half_as_ushort(h1) << 16) | __half_as_ushort(h0);
                    uint32_t lp = ((uint32_t)__half_as_ushort(l1) << 16) | __half_as_ushort(l0);
                    *reinterpret_cast<uint32_t*>(Ct + idx) = hp;
                    *reinterpret_cast<uint32_t*>(Ct + idx + 4096) = lp;
                } else if (MODE == 3) {
                    size_t base = (size_t)row * 256 + nLoc + colT;
                    *reinterpret_cast<float2*>(dstQKV + base) = make_float2(v0, v1);
                } else {
                    size_t base = (size_t)row * NC + nBase + colT;
                    *reinterpret_cast<float2*>(Cf + base) = make_float2(v0, v1);
                }
            }
        }
    }
}

// ============ K3: kv / ksum via per-warp shuffle outer-product ============
__global__ void kv_reduce_kernel(const float* __restrict__ pk,
                                 const float* __restrict__ v,
                                 float* __restrict__ kv,
                                 float* __restrict__ ksum) {
    int bh = blockIdx.x;
    int h  = bh % H_;
    int bj = bh / H_;
    int j  = bj % J_;
    int b  = bj / J_;
    int tid = threadIdx.x, lane = tid & 31, w = tid >> 5;

    float acc[32];
    #pragma unroll
    for (int k = 0; k < 32; k++) acc[k] = 0.f;
    float ks = 0.f;

    for (int t = w; t < T_; t += 8) {
        size_t base = (((size_t)(b * T_ + t) * J_) + j) * D_ + h * DH_ + lane;
        float pkv = pk[base];
        float vv  = v[base];
        ks += pkv;
        #pragma unroll
        for (int k = 0; k < 32; k++)
            acc[k] += __shfl_sync(0xffffffffu, pkv, k) * vv;
    }

    __shared__ float red[8][32][32];
    __shared__ float rks[8][32];
    #pragma unroll
    for (int k = 0; k < 32; k++) red[w][k][lane] = acc[k];
    rks[w][lane] = ks;
    __syncthreads();

    #pragma unroll
    for (int kk = 0; kk < 4; kk++) {
        int k = w * 4 + kk;
        float s = 0.f;
        #pragma unroll
        for (int ww = 0; ww < 8; ww++) s += red[ww][k][lane];
        kv[(size_t)bh * (DH_ * DH_) + k * 32 + lane] = s;
    }
    if (w == 0) {
        float s = 0.f;
        #pragma unroll
        for (int ww = 0; ww < 8; ww++) s += rks[ww][lane];
        ksum[(size_t)bh * DH_ + lane] = s;
    }
}

// ============ K4: y = (pq @ kv) / (pq . ksum + EPS) -> tiled fp16 hi/lo ============
__global__ void attn_apply_kernel(const float* __restrict__ pq,
                                  const float* __restrict__ kv,
                                  const float* __restrict__ ksum,
                                  __half* __restrict__ ya) {
    int bh = blockIdx.x;
    int h  = bh % H_;
    int bj = bh / H_;
    int j  = bj % J_;
    int b  = bj / J_;
    __shared__ float skv[DH_ * DH_];
    __shared__ float sks[DH_];
    int tid = threadIdx.x;
    for (int i = tid; i < DH_ * DH_; i += 256) skv[i] = kv[(size_t)bh * (DH_ * DH_) + i];
    if (tid < DH_) sks[tid] = ksum[(size_t)bh * DH_ + tid];
    __syncthreads();
    int lane = tid & 31, w = tid >> 5;
    for (int t = w; t < T_; t += 8) {
        int token = (b * T_ + t) * J_ + j;
        size_t baseQ = (size_t)token * D_ + h * DH_;
        float q = pq[baseQ + lane];
        float den = q * sks[lane];
        #pragma unroll
        for (int o = 16; o; o >>= 1) den += __shfl_xor_sync(0xffffffffu, den, o);
        float num = 0.f;
        #pragma unroll
        for (int k = 0; k < 32; k++)
            num += __shfl_sync(0xffffffffu, q, k) * skv[k * 32 + lane];
        split_store_tiled(ya, token, h * DH_ + lane, 8, num / (den + EPSF));
    }
}

// ============ K5: residual + LN2 -> tiled fp16 hi/lo ============
__global__ void resid_kernel(const float* __restrict__ x,
                             const float* __restrict__ o_in,
                             const float* __restrict__ g2,
                             const float* __restrict__ b2,
                             __half* __restrict__ ua) {
    __shared__ float sbuf[32];
    int row = blockIdx.x, i = threadIdx.x;
    const float* xr = x + (size_t)row * (D_ + 1);
    float o = o_in[(size_t)row * D_ + i];
    float so = block_reduce_sum(o * o, sbuf);
    float n  = fmaxf(sqrtf(so), EPSF);
    float z  = sinhf(n) * o / n;
    float m  = xr[1 + i] + z;
    float sm = block_reduce_sum(m * m, sbuf);
    float m0 = xr[0] + coshf(n);
    float mink = -m0 * m0 + sm;
    float inv  = rsqrtf(fmaxf(-mink, EPSF));
    float h0   = m0 * inv;
    float hs   = m * inv;
    float hn   = fmaxf(sqrtf(sm) * inv, EPSF);
    float u    = acoshf(fmaxf(h0, 1.0f + 1e-7f)) * hs / hn;
    float s1 = block_reduce_sum(u, sbuf);
    float s2 = block_reduce_sum(u * u, sbuf);
    float mean = s1 * (1.f / D_);
    float var  = s2 * (1.f / D_) - mean * mean;
    float uv = (u - mean) * rsqrtf(var + 1e-5f) * g2[i] + b2[i];
    split_store_tiled(ua, row, i, 8, uv);
}

// ============ K6: out = expmap0(f) ============
__global__ void final_kernel(const float* __restrict__ f_in,
                             float* __restrict__ out) {
    __shared__ float sbuf[32];
    int row = blockIdx.x, i = threadIdx.x;
    float f = f_in[(size_t)row * D_ + i];
    float ss = block_reduce_sum(f * f, sbuf);
    float n  = fmaxf(sqrtf(ss), EPSF);
    float* orow = out + (size_t)row * (D_ + 1);
    orow[1 + i] = sinhf(n) * f / n;
    if (i == 0) orow[0] = coshf(n);
}

// ================= launch =================
extern "C" void kernel_launch(void* const* d_in, const int* /*in_sizes*/, int /*n_in*/,
                              void* d_out, int /*out_size*/) {
    const float* x     = (const float*)d_in[0];
    const float* g1    = (const float*)d_in[1];
    const float* beta1 = (const float*)d_in[2];
    const float* Wq    = (const float*)d_in[3];
    const float* Wk    = (const float*)d_in[4];
    const float* Wv    = (const float*)d_in[5];
    const float* Wo    = (const float*)d_in[6];
    const float* bq    = (const float*)d_in[7];
    const float* bk    = (const float*)d_in[8];
    const float* bv    = (const float*)d_in[9];
    const float* bo    = (const float*)d_in[10];
    const float* g2    = (const float*)d_in[11];
    const float* beta2 = (const float*)d_in[12];
    const float* W1    = (const float*)d_in[13];
    const float* bf1   = (const float*)d_in[14];
    const float* W2    = (const float*)d_in[15];
    const float* bf2   = (const float*)d_in[16];
    float* out = (float*)d_out;

    static bool attr_done = false;
    if (!attr_done) {
        cudaFuncSetAttribute(gemm_kernel<0>, cudaFuncAttributeMaxDynamicSharedMemorySize, GEMM_SMEM);
        cudaFuncSetAttribute(gemm_kernel<2>, cudaFuncAttributeMaxDynamicSharedMemorySize, GEMM_SMEM);
        cudaFuncSetAttribute(gemm_kernel<3>, cudaFuncAttributeMaxDynamicSharedMemorySize, GEMM_SMEM);
        attr_done = true;
    }

    __half *ta, *ha, *wqkv, *wo, *w1, *w2;
    float *q_, *k_, *v_, *kv_, *ks_, *bqkv_;
    cudaGetSymbolAddress((void**)&ta, g_ta);     cudaGetSymbolAddress((void**)&ha, g_ha);
    cudaGetSymbolAddress((void**)&q_, g_q);      cudaGetSymbolAddress((void**)&k_, g_k);
    cudaGetSymbolAddress((void**)&v_, g_v);
    cudaGetSymbolAddress((void**)&kv_, g_kv);    cudaGetSymbolAddress((void**)&ks_, g_ks);
    cudaGetSymbolAddress((void**)&wqkv, g_wqkv); cudaGetSymbolAddress((void**)&wo, g_wo);
    cudaGetSymbolAddress((void**)&w1, g_w1);     cudaGetSymbolAddress((void**)&w2, g_w2);
    cudaGetSymbolAddress((void**)&bqkv_, g_bqkv);

    // 0. all weight prep in ONE launch
    wsplit_all_kernel<<<3075, 256>>>(Wq, Wk, Wv, Wo, W1, W2, bq, bk, bv);

    // 1. pre: x -> t (tiled fp16 split)
    pre_kernel<<<NTOK, 256>>>(x, g1, beta1, ta);

    // 2. fused QKV projection
    dim3 gQKV(6, NTOK / 128);
    gemm_kernel<3><<<gQKV, 256, GEMM_SMEM>>>(ta, wqkv, bqkv_, q_, k_, v_, nullptr, 8, 768);

    // 3. linear attention
    kv_reduce_kernel<<<B_ * J_ * H_, 256>>>(k_, v_, kv_, ks_);
    attn_apply_kernel<<<B_ * J_ * H_, 256>>>(q_, kv_, ks_, ta);   // y -> ta (tiled)

    // 4. output projection: o = y @ Wo + bo -> q_ (fp32)
    dim3 gD(2, NTOK / 128);
    gemm_kernel<0><<<gD, 256, GEMM_SMEM>>>(ta, wo, bo, q_, nullptr, nullptr, nullptr, 8, D_);

    // 5. Lorentz residual + LN2 -> ta (tiled u2)
    resid_kernel<<<NTOK, 256>>>(x, q_, g2, beta2, ta);

    // 6. FFN
    dim3 gH(8, NTOK / 128);
    gemm_kernel<2><<<gH, 256, GEMM_SMEM>>>(ta, w1, bf1, nullptr, nullptr, nullptr, ha, 8, HID_);
    gemm_kernel<0><<<gD, 256, GEMM_SMEM>>>(ha, w2, bf2, q_, nullptr, nullptr, nullptr, 32, D_);

    // 7. final expmap0 -> out
    final_kernel<<<NTOK, 256>>>(q_, out);
}

// round 15
// speedup vs baseline: 1.5840x; 1.0004x over previous
#include <cuda_runtime.h>
#include <cuda_fp16.h>
#include <math.h>
#include <stdint.h>

#define B_ 8
#define T_ 512
#define J_ 26
#define D_ 256
#define H_ 8
#define DH_ 32
#define HID_ 1024
#define NTOK 106496            // B*T*J  (= 832 * 128 exactly)
#define EPSF 1e-6f

// ================= PTX helpers (base ISA: sm_90 bulk-async, sm_80 mma) =================
__device__ __forceinline__ uint32_t smem_u32(const void* p) {
    uint32_t a;
    asm("{ .reg .u64 t; cvta.to.shared.u64 t, %1; cvt.u32.u64 %0, t; }" : "=r"(a) : "l"(p));
    return a;
}
#define MBAR_INIT(addr, cnt) \
    asm volatile("mbarrier.init.shared.b64 [%0], %1;" :: "r"(addr), "r"(cnt) : "memory")
#define MBAR_EXPECT_TX(addr, bytes) \
    asm volatile("mbarrier.arrive.expect_tx.shared.b64 _, [%0], %1;" :: "r"(addr), "r"(bytes) : "memory")
#define MBAR_WAIT(addr, phase) do { \
    uint32_t _m = (addr), _p = (phase); \
    asm volatile("{\n\t.reg .pred P;\n\tWL_%=:\n\t" \
        "mbarrier.try_wait.parity.acquire.cta.shared::cta.b64 P, [%0], %1, 0x989680;\n\t" \
        "@P bra.uni WD_%=;\n\tbra.uni WL_%=;\n\tWD_%=:\n\t}" :: "r"(_m), "r"(_p) : "memory"); \
} while (0)
#define CP_BULK(dst, src, bytes, mbar) \
    asm volatile("cp.async.bulk.shared::cluster.global.mbarrier::complete_tx::bytes [%0], [%1], %2, [%3];" \
        :: "r"(dst), "l"(src), "r"(bytes), "r"(mbar) : "memory")

#define LDSM4(r0, r1, r2, r3, addr) \
    asm volatile("ldmatrix.sync.aligned.m8n8.x4.shared.b16 {%0,%1,%2,%3}, [%4];" \
        : "=r"(r0), "=r"(r1), "=r"(r2), "=r"(r3) : "r"(addr))

__device__ __forceinline__ void mma16816(float* c, const uint32_t* a, const uint32_t* b) {
    asm volatile(
        "mma.sync.aligned.m16n8k16.row.col.f32.f16.f16.f32 "
        "{%0,%1,%2,%3}, {%4,%5,%6,%7}, {%8,%9}, {%0,%1,%2,%3};"
        : "+f"(c[0]), "+f"(c[1]), "+f"(c[2]), "+f"(c[3])
        : "r"(a[0]), "r"(a[1]), "r"(a[2]), "r"(a[3]), "r"(b[0]), "r"(b[1]));
}

// ============ tiled layout: [mtile][ktile][hi|lo][128x32 swizzled] ============
// tile = 128 rows x 32 cols fp16 = 8192 B; hi+lo pair = 16384 B.
// elem(r, c) -> r*32 + ((cc ^ ((r>>1)&3))<<3) + (c&7), cc = (c>>3)&3
__device__ __forceinline__ size_t tiled_idx(int row, int col, int wKt) {
    int mt = row >> 7, r = row & 127, kt = col >> 5, c = col & 31;
    return ((size_t)(mt * wKt + kt) * 2) * 4096 + (size_t)(r * 32)
         + (size_t)(((((c >> 3) & 3) ^ ((r >> 1) & 3)) << 3) + (c & 7));
}

// ================= scratch (static device .bss) =================
__device__ __half g_ta [(size_t)NTOK * D_ * 2];    // t / y / u2, tiled hi|lo, wKt=8
__device__ __half g_ha [(size_t)NTOK * HID_ * 2];  // FFN hidden, tiled hi|lo, wKt=32
__device__ float  g_q  [(size_t)NTOK * D_];        // pq / o / f
__device__ float  g_k  [(size_t)NTOK * D_];        // pk
__device__ float  g_v  [(size_t)NTOK * D_];        // v
__device__ float g_kv [(size_t)B_ * J_ * H_ * DH_ * DH_];
__device__ float g_ks [(size_t)B_ * J_ * H_ * DH_];
// weights, tiled hi|lo pairs (only hi consumed as B operand)
__device__ __half g_wqkv[768 * D_ * 2];      // 6 ntiles, wKt=8
__device__ __half g_wo  [D_ * D_ * 2];       // 2 ntiles, wKt=8
__device__ __half g_w1  [HID_ * D_ * 2];     // 8 ntiles, wKt=8
__device__ __half g_w2  [D_ * HID_ * 2];     // 2 ntiles, wKt=32
__device__ float g_bqkv[768];

// ================= small helpers =================
__device__ __forceinline__ float block_reduce_sum(float v, float* sbuf) {
    int lane = threadIdx.x & 31, w = threadIdx.x >> 5;
    #pragma unroll
    for (int o = 16; o; o >>= 1) v += __shfl_down_sync(0xffffffffu, v, o);
    if (lane == 0) sbuf[w] = v;
    __syncthreads();
    float r = (threadIdx.x < 8) ? sbuf[threadIdx.x] : 0.f;
    if (w == 0) {
        r += __shfl_down_sync(0xffffffffu, r, 4);
        r += __shfl_down_sync(0xffffffffu, r, 2);
        r += __shfl_down_sync(0xffffffffu, r, 1);
        if (lane == 0) sbuf[0] = r;
    }
    __syncthreads();
    float res = sbuf[0];
    __syncthreads();
    return res;
}
__device__ __forceinline__ void split_store_tiled(__half* base, int row, int col,
                                                  int wKt, float v) {
    size_t idx = tiled_idx(row, col, wKt);
    __half h = __float2half(v);
    base[idx] = h;
    base[idx + 4096] = __float2half(v - __half2float(h));
}

// ============ weight prep: transpose + split + tile, one launch ============
__global__ void wsplit_all_kernel(const float* __restrict__ Wq, const float* __restrict__ Wk,
                                  const float* __restrict__ Wv, const float* __restrict__ Wo,
                                  const float* __restrict__ W1, const float* __restrict__ W2,
                                  const float* __restrict__ bq, const float* __restrict__ bk,
                                  const float* __restrict__ bv) {
    int idx = blockIdx.x * 256 + threadIdx.x;
    if (idx < 196608) {
        int wsel = idx >> 16;
        int local = idx & 65535;
        const float* W = (wsel == 0) ? Wq : (wsel == 1) ? Wk : Wv;
        int k = local >> 8, n = local & 255;
        split_store_tiled(g_wqkv, wsel * 256 + n, k, 8, W[local]);
    } else if (idx < 262144) {
        int local = idx - 196608;
        int k = local >> 8, n = local & 255;
        split_store_tiled(g_wo, n, k, 8, Wo[local]);
    } else if (idx < 524288) {
        int local = idx - 262144;
        int k = local >> 10, n = local & 1023;
        split_store_tiled(g_w1, n, k, 8, W1[local]);
    } else if (idx < 786432) {
        int local = idx - 524288;
        int k = local >> 8, n = local & 255;
        split_store_tiled(g_w2, n, k, 32, W2[local]);
    } else if (idx < 787200) {
        int bi = idx - 786432;
        g_bqkv[bi] = (bi < 256) ? bq[bi] : (bi < 512) ? bk[bi - 256] : bv[bi - 512];
    }
}

// ============ K1: t = layernorm(logmap0(x)) -> tiled fp16 hi/lo ============
// (expmap0 -> logmap0 round-trip in the reference is the identity; skipped)
__global__ void pre_kernel(const float* __restrict__ x,
                           const float* __restrict__ g1,
                           const float* __restrict__ b1,
                           __half* __restrict__ ta) {
    __shared__ float sbuf[32];
    int row = blockIdx.x, i = threadIdx.x;
    const float* xr = x + (size_t)row * (D_ + 1);
    float xi = xr[1 + i];
    float ss = block_reduce_sum(xi * xi, sbuf);
    float n  = fmaxf(sqrtf(ss), EPSF);
    float x0 = fmaxf(xr[0], 1.0f + 1e-7f);
    float u  = acoshf(x0) * xi / n;
    float s1 = block_reduce_sum(u, sbuf);
    float s2 = block_reduce_sum(u * u, sbuf);
    float mean = s1 * (1.f / D_);
    float var  = s2 * (1.f / D_) - mean * mean;
    float tv = (u - mean) * rsqrtf(var + 1e-5f) * g1[i] + b1[i];
    split_store_tiled(ta, row, i, 8, tv);
}

// ============ HMMA split-fp16 2-pass GEMM, 3-stage bulk-async pipeline ============
// C = (Ah + Al) @ Bh^T + bias (fp32 accum).  Dropped A@Bl: rel ~2^-11.
// MODE 0: fp32 out, no act.  MODE 2: tiled fp16 hi/lo out, gelu.
// MODE 3: fused QKV (route by nBase, elu for Q/K), fp32 out.
#define NSTG 3
#define STAGE_DATA 24576                     // Ah 8K | Al 8K | Bh 8K
#define GEMM_SMEM (64 + NSTG * STAGE_DATA)   // 73792 B -> 2 CTAs/SM

template<int MODE>
__global__ __launch_bounds__(256) void gemm_kernel(
    const __half* __restrict__ A,     // tiled pairs, wKt = nkt
    const __half* __restrict__ Bw,    // tiled pairs (hi used), wKt = nkt
    const float* __restrict__ bias,
    float* __restrict__ Cf, float* __restrict__ Cf2, float* __restrict__ Cf3,
    __half* __restrict__ Ct,          // tiled out (MODE 2)
    int nkt, int NC)
{
    extern __shared__ char smem[];
    const uint32_t sb = smem_u32(smem);
    const int tid  = threadIdx.x;
    const int lane = tid & 31;
    const int w    = tid >> 5;
    const int mTile = blockIdx.y;
    const int nTile = blockIdx.x;
    const int mBase = mTile * 128;
    const int nBase = nTile * 128;
    const int wm = (w & 3) * 32;
    const int wn = (w >> 2) * 64;

    if (tid == 0) { MBAR_INIT(sb, 1); MBAR_INIT(sb + 8, 1); MBAR_INIT(sb + 16, 1); }
    __syncthreads();

    const char* Ab = (const char*)A + (size_t)mTile * nkt * 16384;
    const char* Bb = (const char*)Bw + (size_t)nTile * nkt * 16384;

    auto issue = [&](int kt, int s) {
        uint32_t mb = sb + (uint32_t)s * 8;
        uint32_t d  = sb + 64 + (uint32_t)s * STAGE_DATA;
        MBAR_EXPECT_TX(mb, 24576);
        CP_BULK(d,         Ab + (size_t)kt * 16384, 16384u, mb);   // Ah+Al pair
        CP_BULK(d + 16384, Bb + (size_t)kt * 16384, 8192u,  mb);   // Bh only
    };
    if (tid == 0) {
        issue(0, 0);
        if (nkt > 1) issue(1, 1);
    }

    float acc[2][8][4];
    #pragma unroll
    for (int mt = 0; mt < 2; mt++)
        #pragma unroll
        for (int nt = 0; nt < 8; nt++)
            #pragma unroll
            for (int i = 0; i < 4; i++) acc[mt][nt][i] = 0.f;

    const int aRow = lane & 15;
    const int aSel = lane >> 4;

    for (int kt = 0; kt < nkt; kt++) {
        int s = kt % NSTG;
        if (tid == 0) {
            int pf = kt + 2;
            if (pf < nkt) issue(pf, pf % NSTG);
        }
        MBAR_WAIT(sb + (uint32_t)s * 8, (kt / NSTG) & 1);

        uint32_t sbase = sb + 64 + (uint32_t)s * STAGE_DATA;
        uint32_t aHb = sbase;
        uint32_t aLb = sbase + 8192;
        uint32_t bHb = sbase + 16384;

        #pragma unroll
        for (int kk = 0; kk < 2; kk++) {
            uint32_t bH[8][2];
            #pragma unroll
            for (int p = 0; p < 4; p++) {
                int row = wn + p * 16 + (lane & 15);
                int cc  = 2 * kk + (lane >> 4);
                uint32_t off = (uint32_t)(row * 64 + ((cc ^ ((row >> 1) & 3)) << 4));
                uint32_t q0, q1, q2, q3;
                LDSM4(q0, q1, q2, q3, bHb + off);
                bH[2*p][0] = q0; bH[2*p+1][0] = q1; bH[2*p][1] = q2; bH[2*p+1][1] = q3;
            }
            #pragma unroll
            for (int mt = 0; mt < 2; mt++) {
                int row = wm + mt * 16 + aRow;
                int cc  = 2 * kk + aSel;
                uint32_t off = (uint32_t)(row * 64 + ((cc ^ ((row >> 1) & 3)) << 4));
                uint32_t aH[4], aL[4];
                LDSM4(aH[0], aH[1], aH[2], aH[3], aHb + off);
                LDSM4(aL[0], aL[1], aL[2], aL[3], aLb + off);
                #pragma unroll
                for (int nt = 0; nt < 8; nt++) mma16816(acc[mt][nt], aH, bH[nt]);
                #pragma unroll
                for (int nt = 0; nt < 8; nt++) mma16816(acc[mt][nt], aL, bH[nt]);
            }
        }
        __syncthreads();   // all warps done with slot s -> legalizes refill at kt+2
    }

    // ---------------- epilogue ----------------
    const int gid = lane >> 2;
    const int tig = lane & 3;
    int which = 0; float* dstQKV = Cf; bool eluAct = false; int nLoc = nBase;
    if (MODE == 3) {
        which = nBase >> 8;
        dstQKV = (which == 0) ? Cf : (which == 1) ? Cf2 : Cf3;
        eluAct = (which < 2);
        nLoc = nBase - which * 256;
    }
    #pragma unroll
    for (int mt = 0; mt < 2; mt++) {
        #pragma unroll
        for (int nt = 0; nt < 8; nt++) {
            int colT = wn + nt * 8 + tig * 2;
            float b0 = bias[nBase + colT], b1 = bias[nBase + colT + 1];
            #pragma unroll
            for (int half = 0; half < 2; half++) {
                int row = mBase + wm + mt * 16 + gid + half * 8;
                float v0 = acc[mt][nt][half * 2 + 0] + b0;
                float v1 = acc[mt][nt][half * 2 + 1] + b1;
                if (MODE == 3 && eluAct) {
                    v0 = (v0 > 0.f) ? (v0 + 1.f) : __expf(v0);
                    v1 = (v1 > 0.f) ? (v1 + 1.f) : __expf(v1);
                } else if (MODE == 2) {
                    float c0 = v0 * v0 * v0;
                    v0 = 0.5f * v0 * (1.f + tanhf(0.7978845608028654f * (v0 + 0.044715f * c0)));
                    float c1 = v1 * v1 * v1;
                    v1 = 0.5f * v1 * (1.f + tanhf(0.7978845608028654f * (v1 + 0.044715f * c1)));
                }
                if (MODE == 2) {
                    size_t idx = tiled_idx(row, nBase + colT, NC >> 5);
                    __half h0 = __float2half(v0);
                    __half h1 = __float2half(v1);
                    __half l0 = __float2half(v0 - __half2float(h0));
                    __half l1 = __float2half(v1 - __half2float(h1));
                    uint32_t hp = ((uint32_t)__half_as_ushort(h1) << 16) | __half_as_ushort(h0);
                    uint32_t lp = ((uint32_t)__half_as_ushort(l1) << 16) | __half_as_ushort(l0);
                    *reinterpret_cast<uint32_t*>(Ct + idx) = hp;
                    *reinterpret_cast<uint32_t*>(Ct + idx + 4096) = lp;
                } else if (MODE == 3) {
                    size_t base = (size_t)row * 256 + nLoc + colT;
                    *reinterpret_cast<float2*>(dstQKV + base) = make_float2(v0, v1);
                } else {
                    size_t base = (size_t)row * NC + nBase + colT;
                    *reinterpret_cast<float2*>(Cf + base) = make_float2(v0, v1);
                }
            }
        }
    }
}

// ============ K3: kv / ksum via per-warp shuffle outer-product ============
__global__ void kv_reduce_kernel(const float* __restrict__ pk,
                                 const float* __restrict__ v,
                                 float* __restrict__ kv,
                                 float* __restrict__ ksum) {
    int bh = blockIdx.x;
    int h  = bh % H_;
    int bj = bh / H_;
    int j  = bj % J_;
    int b  = bj / J_;
    int tid = threadIdx.x, lane = tid & 31, w = tid >> 5;

    float acc[32];
    #pragma unroll
    for (int k = 0; k < 32; k++) acc[k] = 0.f;
    float ks = 0.f;

    for (int t = w; t < T_; t += 8) {
        size_t base = (((size_t)(b * T_ + t) * J_) + j) * D_ + h * DH_ + lane;
        float pkv = pk[base];
        float vv  = v[base];
        ks += pkv;
        #pragma unroll
        for (int k = 0; k < 32; k++)
            acc[k] += __shfl_sync(0xffffffffu, pkv, k) * vv;
    }

    __shared__ float red[8][32][32];
    __shared__ float rks[8][32];
    #pragma unroll
    for (int k = 0; k < 32; k++) red[w][k][lane] = acc[k];
    rks[w][lane] = ks;
    __syncthreads();

    #pragma unroll
    for (int kk = 0; kk < 4; kk++) {
        int k = w * 4 + kk;
        float s = 0.f;
        #pragma unroll
        for (int ww = 0; ww < 8; ww++) s += red[ww][k][lane];
        kv[(size_t)bh * (DH_ * DH_) + k * 32 + lane] = s;
    }
    if (w == 0) {
        float s = 0.f;
        #pragma unroll
        for (int ww = 0; ww < 8; ww++) s += rks[ww][lane];
        ksum[(size_t)bh * DH_ + lane] = s;
    }
}

// ============ K4: y = (pq @ kv) / (pq . ksum + EPS) -> tiled fp16 hi/lo ============
__global__ void attn_apply_kernel(const float* __restrict__ pq,
                                  const float* __restrict__ kv,
                                  const float* __restrict__ ksum,
                                  __half* __restrict__ ya) {
    int bh = blockIdx.x;
    int h  = bh % H_;
    int bj = bh / H_;
    int j  = bj % J_;
    int b  = bj / J_;
    __shared__ float skv[DH_ * DH_];
    __shared__ float sks[DH_];
    int tid = threadIdx.x;
    for (int i = tid; i < DH_ * DH_; i += 256) skv[i] = kv[(size_t)bh * (DH_ * DH_) + i];
    if (tid < DH_) sks[tid] = ksum[(size_t)bh * DH_ + tid];
    __syncthreads();
    int lane = tid & 31, w = tid >> 5;
    for (int t = w; t < T_; t += 8) {
        int token = (b * T_ + t) * J_ + j;
        size_t baseQ = (size_t)token * D_ + h * DH_;
        float q = pq[baseQ + lane];
        float den = q * sks[lane];
        #pragma unroll
        for (int o = 16; o; o >>= 1) den += __shfl_xor_sync(0xffffffffu, den, o);
        float num = 0.f;
        #pragma unroll
        for (int k = 0; k < 32; k++)
            num += __shfl_sync(0xffffffffu, q, k) * skv[k * 32 + lane];
        split_store_tiled(ya, token, h * DH_ + lane, 8, num / (den + EPSF));
    }
}

// ============ K5: residual + LN2 -> tiled fp16 hi/lo ============
__global__ void resid_kernel(const float* __restrict__ x,
                             const float* __restrict__ o_in,
                             const float* __restrict__ g2,
                             const float* __restrict__ b2,
                             __half* __restrict__ ua) {
    __shared__ float sbuf[32];
    int row = blockIdx.x, i = threadIdx.x;
    const float* xr = x + (size_t)row * (D_ + 1);
    float o = o_in[(size_t)row * D_ + i];
    float so = block_reduce_sum(o * o, sbuf);
    float n  = fmaxf(sqrtf(so), EPSF);
    float z  = sinhf(n) * o / n;
    float m  = xr[1 + i] + z;
    float sm = block_reduce_sum(m * m, sbuf);
    float m0 = xr[0] + coshf(n);
    float mink = -m0 * m0 + sm;
    float inv  = rsqrtf(fmaxf(-mink, EPSF));
    float h0   = m0 * inv;
    float hs   = m * inv;
    float hn   = fmaxf(sqrtf(sm) * inv, EPSF);
    float u    = acoshf(fmaxf(h0, 1.0f + 1e-7f)) * hs / hn;
    float s1 = block_reduce_sum(u, sbuf);
    float s2 = block_reduce_sum(u * u, sbuf);
    float mean = s1 * (1.f / D_);
    float var  = s2 * (1.f / D_) - mean * mean;
    float uv = (u - mean) * rsqrtf(var + 1e-5f) * g2[i] + b2[i];
    split_store_tiled(ua, row, i, 8, uv);
}

// ============ K6: out = expmap0(f) ============
__global__ void final_kernel(const float* __restrict__ f_in,
                             float* __restrict__ out) {
    __shared__ float sbuf[32];
    int row = blockIdx.x, i = threadIdx.x;
    float f = f_in[(size_t)row * D_ + i];
    float ss = block_reduce_sum(f * f, sbuf);
    float n  = fmaxf(sqrtf(ss), EPSF);
    float* orow = out + (size_t)row * (D_ + 1);
    orow[1 + i] = sinhf(n) * f / n;
    if (i == 0) orow[0] = coshf(n);
}

// ================= launch =================
extern "C" void kernel_launch(void* const* d_in, const int* /*in_sizes*/, int /*n_in*/,
                              void* d_out, int /*out_size*/) {
    const float* x     = (const float*)d_in[0];
    const float* g1    = (const float*)d_in[1];
    const float* beta1 = (const float*)d_in[2];
    const float* Wq    = (const float*)d_in[3];
    const float* Wk    = (const float*)d_in[4];
    const float* Wv    = (const float*)d_in[5];
    const float* Wo    = (const float*)d_in[6];
    const float* bq    = (const float*)d_in[7];
    const float* bk    = (const float*)d_in[8];
    const float* bv    = (const float*)d_in[9];
    const float* bo    = (const float*)d_in[10];
    const float* g2    = (const float*)d_in[11];
    const float* beta2 = (const float*)d_in[12];
    const float* W1    = (const float*)d_in[13];
    const float* bf1   = (const float*)d_in[14];
    const float* W2    = (const float*)d_in[15];
    const float* bf2   = (const float*)d_in[16];
    float* out = (float*)d_out;

    static bool attr_done = false;
    if (!attr_done) {
        cudaFuncSetAttribute(gemm_kernel<0>, cudaFuncAttributeMaxDynamicSharedMemorySize, GEMM_SMEM);
        cudaFuncSetAttribute(gemm_kernel<2>, cudaFuncAttributeMaxDynamicSharedMemorySize, GEMM_SMEM);
        cudaFuncSetAttribute(gemm_kernel<3>, cudaFuncAttributeMaxDynamicSharedMemorySize, GEMM_SMEM);
        attr_done = true;
    }

    __half *ta, *ha, *wqkv, *wo, *w1, *w2;
    float *q_, *k_, *v_, *kv_, *ks_, *bqkv_;
    cudaGetSymbolAddress((void**)&ta, g_ta);     cudaGetSymbolAddress((void**)&ha, g_ha);
    cudaGetSymbolAddress((void**)&q_, g_q);      cudaGetSymbolAddress((void**)&k_, g_k);
    cudaGetSymbolAddress((void**)&v_, g_v);
    cudaGetSymbolAddress((void**)&kv_, g_kv);    cudaGetSymbolAddress((void**)&ks_, g_ks);
    cudaGetSymbolAddress((void**)&wqkv, g_wqkv); cudaGetSymbolAddress((void**)&wo, g_wo);
    cudaGetSymbolAddress((void**)&w1, g_w1);     cudaGetSymbolAddress((void**)&w2, g_w2);
    cudaGetSymbolAddress((void**)&bqkv_, g_bqkv);

    // 0. all weight prep in ONE launch
    wsplit_all_kernel<<<3075, 256>>>(Wq, Wk, Wv, Wo, W1, W2, bq, bk, bv);

    // 1. pre: x -> t (tiled fp16 split)
    pre_kernel<<<NTOK, 256>>>(x, g1, beta1, ta);

    // 2. fused QKV projection
    dim3 gQKV(6, NTOK / 128);
    gemm_kernel<3><<<gQKV, 256, GEMM_SMEM>>>(ta, wqkv, bqkv_, q_, k_, v_, nullptr, 8, 768);

    // 3. linear attention
    kv_reduce_kernel<<<B_ * J_ * H_, 256>>>(k_, v_, kv_, ks_);
    attn_apply_kernel<<<B_ * J_ * H_, 256>>>(q_, kv_, ks_, ta);   // y -> ta (tiled)

    // 4. output projection: o = y @ Wo + bo -> q_ (fp32)
    dim3 gD(2, NTOK / 128);
    gemm_kernel<0><<<gD, 256, GEMM_SMEM>>>(ta, wo, bo, q_, nullptr, nullptr, nullptr, 8, D_);

    // 5. Lorentz residual + LN2 -> ta (tiled u2)
    resid_kernel<<<NTOK, 256>>>(x, q_, g2, beta2, ta);

    // 6. FFN
    dim3 gH(8, NTOK / 128);
    gemm_kernel<2><<<gH, 256, GEMM_SMEM>>>(ta, w1, bf1, nullptr, nullptr, nullptr, ha, 8, HID_);
    gemm_kernel<0><<<gD, 256, GEMM_SMEM>>>(ha, w2, bf2, q_, nullptr, nullptr, nullptr, 32, D_);

    // 7. final expmap0 -> out
    final_kernel<<<NTOK, 256>>>(q_, out);
}